// round 1
// baseline (speedup 1.0000x reference)
#include <cuda_runtime.h>
#include <cuda_bf16.h>

// Problem constants
#define B_   2
#define S_   2048
#define D_   2048
#define H_   32
#define DH_  64
#define M_   (B_*S_)    // 4096 tokens
#define BH_  (B_*H_)    // 64 (batch*heads)

// Scratch (static __device__ arrays: allocation-guard safe)
__device__ float g_q[(size_t)M_*D_];     // [B,H,S,d] packed
__device__ float g_k[(size_t)M_*D_];
__device__ float g_v[(size_t)M_*D_];
__device__ float g_ctx[(size_t)M_*D_];   // [B,S,H*d]
__device__ float g_sc[(size_t)BH_*S_*S_]; // scores [BH,S,S]  (~1 GB)

// ---------------------------------------------------------------------------
// Generic 128x128x16 fp32 GEMM:  C = A[MxK] @ W[KxN] + bias
// split=1: scatter output into [B,H,S,d] layout (for Q/K/V)
// split=0: row-major [M,N] (for output projection)
// Shapes hardwired: K=N=2048, M=4096. 256 threads, 8x8 micro-tile.
// ---------------------------------------------------------------------------
__global__ void __launch_bounds__(256, 1) gemm128(
    const float* __restrict__ A, const float* __restrict__ Wm,
    const float* __restrict__ bias, float* __restrict__ C, int split)
{
    __shared__ float As[16][128];   // transposed A tile
    __shared__ float Bs[16][128];
    const int tid  = threadIdx.x;
    const int row0 = blockIdx.y * 128;
    const int col0 = blockIdx.x * 128;
    const int ar = tid >> 2, ac = (tid & 3) << 2;   // A loader: 64 rows x 16 cols / pass
    const int br = tid >> 5, bc = (tid & 31) << 2;  // B loader: 8 rows x 128 cols / pass
    const int ty = tid >> 4, tx = tid & 15;

    float acc[8][8] = {};

    for (int k0 = 0; k0 < D_; k0 += 16) {
        #pragma unroll
        for (int p = 0; p < 2; ++p) {
            int r = ar + p * 64;
            float4 v = *(const float4*)(A + (size_t)(row0 + r) * D_ + k0 + ac);
            As[ac + 0][r] = v.x; As[ac + 1][r] = v.y;
            As[ac + 2][r] = v.z; As[ac + 3][r] = v.w;
        }
        #pragma unroll
        for (int p = 0; p < 2; ++p) {
            int r = br + p * 8;
            *(float4*)&Bs[r][bc] =
                *(const float4*)(Wm + (size_t)(k0 + r) * D_ + col0 + bc);
        }
        __syncthreads();
        #pragma unroll
        for (int k = 0; k < 16; ++k) {
            float a[8], b[8];
            *(float4*)(a)     = *(const float4*)&As[k][ty * 8];
            *(float4*)(a + 4) = *(const float4*)&As[k][ty * 8 + 4];
            *(float4*)(b)     = *(const float4*)&Bs[k][tx * 8];
            *(float4*)(b + 4) = *(const float4*)&Bs[k][tx * 8 + 4];
            #pragma unroll
            for (int i = 0; i < 8; ++i)
                #pragma unroll
                for (int j = 0; j < 8; ++j)
                    acc[i][j] += a[i] * b[j];
        }
        __syncthreads();
    }

    #pragma unroll
    for (int i = 0; i < 8; ++i) {
        int m = row0 + ty * 8 + i;
        #pragma unroll
        for (int j = 0; j < 8; ++j) {
            int n = col0 + tx * 8 + j;
            float v = acc[i][j] + bias[n];
            if (split) {
                int bb = m >> 11, s = m & (S_ - 1);
                int hh = n >> 6,  jj = n & 63;
                g_q[0]; // no-op to keep symbol referenced pattern harmless
                ((float*)C)[(((size_t)(bb * H_ + hh) * S_) + s) * DH_ + jj] = v;
            } else {
                C[(size_t)m * D_ + n] = v;
            }
        }
    }
}

// ---------------------------------------------------------------------------
// Scores:  Sc[bh][m][n] = scale * sum_k Q[bh][m][k] * K[bh][n][k]   (K dim=64)
// 128x128 output tile per block, 4 k-iterations of 16.
// ---------------------------------------------------------------------------
__global__ void __launch_bounds__(256, 1) qk_gemm(
    const float* __restrict__ Q, const float* __restrict__ Km,
    float* __restrict__ Sc)
{
    const int bh = blockIdx.z;
    const float* Aq = Q  + (size_t)bh * S_ * DH_;
    const float* Bk = Km + (size_t)bh * S_ * DH_;
    float* out      = Sc + (size_t)bh * S_ * S_;

    __shared__ float As[16][128];
    __shared__ float Bs[16][128];
    const int tid  = threadIdx.x;
    const int row0 = blockIdx.y * 128;
    const int col0 = blockIdx.x * 128;
    const int ar = tid >> 2, ac = (tid & 3) << 2;
    const int ty = tid >> 4, tx = tid & 15;

    float acc[8][8] = {};

    for (int k0 = 0; k0 < DH_; k0 += 16) {
        #pragma unroll
        for (int p = 0; p < 2; ++p) {
            int r = ar + p * 64;
            float4 v = *(const float4*)(Aq + (size_t)(row0 + r) * DH_ + k0 + ac);
            As[ac + 0][r] = v.x; As[ac + 1][r] = v.y;
            As[ac + 2][r] = v.z; As[ac + 3][r] = v.w;
            float4 w = *(const float4*)(Bk + (size_t)(col0 + r) * DH_ + k0 + ac);
            Bs[ac + 0][r] = w.x; Bs[ac + 1][r] = w.y;
            Bs[ac + 2][r] = w.z; Bs[ac + 3][r] = w.w;
        }
        __syncthreads();
        #pragma unroll
        for (int k = 0; k < 16; ++k) {
            float a[8], b[8];
            *(float4*)(a)     = *(const float4*)&As[k][ty * 8];
            *(float4*)(a + 4) = *(const float4*)&As[k][ty * 8 + 4];
            *(float4*)(b)     = *(const float4*)&Bs[k][tx * 8];
            *(float4*)(b + 4) = *(const float4*)&Bs[k][tx * 8 + 4];
            #pragma unroll
            for (int i = 0; i < 8; ++i)
                #pragma unroll
                for (int j = 0; j < 8; ++j)
                    acc[i][j] += a[i] * b[j];
        }
        __syncthreads();
    }

    const float scale = 0.125f;  // 1/sqrt(64)
    #pragma unroll
    for (int i = 0; i < 8; ++i) {
        size_t m = row0 + ty * 8 + i;
        #pragma unroll
        for (int j = 0; j < 8; ++j)
            out[m * S_ + col0 + tx * 8 + j] = acc[i][j] * scale;
    }
}

// ---------------------------------------------------------------------------
// Row softmax in-place over rows of length 2048. One block per row.
// ---------------------------------------------------------------------------
__global__ void __launch_bounds__(256, 1) softmax_rows(float* __restrict__ Sc)
{
    float* p = Sc + (size_t)blockIdx.x * S_;
    const int tid = threadIdx.x;
    __shared__ float red[256];

    float vals[8];
    float mx = -1e30f;
    #pragma unroll
    for (int i = 0; i < 8; ++i) {
        vals[i] = p[tid + 256 * i];
        mx = fmaxf(mx, vals[i]);
    }
    red[tid] = mx; __syncthreads();
    #pragma unroll
    for (int s = 128; s > 0; s >>= 1) {
        if (tid < s) red[tid] = fmaxf(red[tid], red[tid + s]);
        __syncthreads();
    }
    mx = red[0];
    __syncthreads();

    float sum = 0.f;
    #pragma unroll
    for (int i = 0; i < 8; ++i) {
        vals[i] = __expf(vals[i] - mx);
        sum += vals[i];
    }
    red[tid] = sum; __syncthreads();
    #pragma unroll
    for (int s = 128; s > 0; s >>= 1) {
        if (tid < s) red[tid] += red[tid + s];
        __syncthreads();
    }
    float inv = 1.0f / red[0];
    #pragma unroll
    for (int i = 0; i < 8; ++i)
        p[tid + 256 * i] = vals[i] * inv;
}

// ---------------------------------------------------------------------------
// ctx = P @ V per (b,h):  [2048x2048] @ [2048x64] -> scatter into [B,S,H*d]
// BM=128, BN=64, BK=16; 256 threads, 8x4 micro-tile.
// ---------------------------------------------------------------------------
__global__ void __launch_bounds__(256, 1) pv_gemm(
    const float* __restrict__ P, const float* __restrict__ V,
    float* __restrict__ ctx)
{
    const int bh = blockIdx.z;
    const int b  = bh >> 5;   // /H_
    const int h  = bh & 31;
    const float* Pp = P + (size_t)bh * S_ * S_;
    const float* Vp = V + (size_t)bh * S_ * DH_;

    __shared__ float Ps[16][128];  // transposed P tile
    __shared__ float Vs[16][64];
    const int tid  = threadIdx.x;
    const int row0 = blockIdx.y * 128;
    const int ar = tid >> 2, ac = (tid & 3) << 2;
    const int vr = tid >> 4, vc = (tid & 15) << 2;
    const int ty = tid >> 4, tx = tid & 15;

    float acc[8][4] = {};

    for (int k0 = 0; k0 < S_; k0 += 16) {
        #pragma unroll
        for (int p = 0; p < 2; ++p) {
            int r = ar + p * 64;
            float4 v = *(const float4*)(Pp + (size_t)(row0 + r) * S_ + k0 + ac);
            Ps[ac + 0][r] = v.x; Ps[ac + 1][r] = v.y;
            Ps[ac + 2][r] = v.z; Ps[ac + 3][r] = v.w;
        }
        *(float4*)&Vs[vr][vc] = *(const float4*)(Vp + (size_t)(k0 + vr) * DH_ + vc);
        __syncthreads();
        #pragma unroll
        for (int k = 0; k < 16; ++k) {
            float a[8], bb[4];
            *(float4*)(a)     = *(const float4*)&Ps[k][ty * 8];
            *(float4*)(a + 4) = *(const float4*)&Ps[k][ty * 8 + 4];
            *(float4*)(bb)    = *(const float4*)&Vs[k][tx * 4];
            #pragma unroll
            for (int i = 0; i < 8; ++i)
                #pragma unroll
                for (int j = 0; j < 4; ++j)
                    acc[i][j] += a[i] * bb[j];
        }
        __syncthreads();
    }

    #pragma unroll
    for (int i = 0; i < 8; ++i) {
        size_t m = row0 + ty * 8 + i;
        #pragma unroll
        for (int j = 0; j < 4; ++j)
            ctx[((size_t)(b * S_) + m) * D_ + h * DH_ + tx * 4 + j] = acc[i][j];
    }
}

// ---------------------------------------------------------------------------
extern "C" void kernel_launch(void* const* d_in, const int* in_sizes, int n_in,
                              void* d_out, int out_size)
{
    const float* X  = (const float*)d_in[0];
    const float* Wq = (const float*)d_in[1];
    const float* bq = (const float*)d_in[2];
    const float* Wk = (const float*)d_in[3];
    const float* bk = (const float*)d_in[4];
    const float* Wv = (const float*)d_in[5];
    const float* bv = (const float*)d_in[6];
    const float* Wo = (const float*)d_in[7];
    const float* bo = (const float*)d_in[8];
    float* out = (float*)d_out;

    float *q, *k, *v, *ctx, *sc;
    cudaGetSymbolAddress((void**)&q,   g_q);
    cudaGetSymbolAddress((void**)&k,   g_k);
    cudaGetSymbolAddress((void**)&v,   g_v);
    cudaGetSymbolAddress((void**)&ctx, g_ctx);
    cudaGetSymbolAddress((void**)&sc,  g_sc);

    dim3 blk(256);
    dim3 grid_proj(D_ / 128, M_ / 128);        // (16, 32)
    // QKV projections (split-head output layout)
    gemm128<<<grid_proj, blk>>>(X, Wq, bq, q, 1);
    gemm128<<<grid_proj, blk>>>(X, Wk, bk, k, 1);
    gemm128<<<grid_proj, blk>>>(X, Wv, bv, v, 1);

    // Scores
    dim3 grid_qk(S_ / 128, S_ / 128, BH_);     // (16, 16, 64)
    qk_gemm<<<grid_qk, blk>>>(q, k, sc);

    // Softmax
    softmax_rows<<<(unsigned)((size_t)BH_ * S_), blk>>>(sc);

    // ctx = P @ V
    dim3 grid_pv(1, S_ / 128, BH_);            // (1, 16, 64)
    pv_gemm<<<grid_pv, blk>>>(sc, v, ctx);

    // Output projection (row-major into d_out)
    gemm128<<<grid_proj, blk>>>(ctx, Wo, bo, out, 0);
}

// round 3
// speedup vs baseline: 2.8709x; 2.8709x over previous
#include <cuda_runtime.h>
#include <cuda_bf16.h>
#include <cstdint>

#define B_   2
#define S_   2048
#define D_   2048
#define H_   32
#define DH_  64
#define M_   (B_*S_)    // 4096
#define BH_  (B_*H_)    // 64

// ---------------------------------------------------------------------------
// Scratch (static __device__ arrays: allocation-guard safe)
// ---------------------------------------------------------------------------
__device__ float         g_sc[(size_t)BH_*S_*S_];     // fp32 scores, 1 GB
__device__ __nv_bfloat16 g_ph[(size_t)BH_*S_*S_];     // probs hi
__device__ __nv_bfloat16 g_pl[(size_t)BH_*S_*S_];     // probs lo
__device__ __nv_bfloat16 g_xh[(size_t)M_*D_];         // X hi (later ctx hi)
__device__ __nv_bfloat16 g_xl[(size_t)M_*D_];         // X lo (later ctx lo)
__device__ __nv_bfloat16 g_wh[(size_t)4*D_*D_];       // Wt hi (4 mats, [N][K])
__device__ __nv_bfloat16 g_wl[(size_t)4*D_*D_];
__device__ __nv_bfloat16 g_qh[(size_t)M_*D_];         // Q hi [BH][S][64]
__device__ __nv_bfloat16 g_ql[(size_t)M_*D_];
__device__ __nv_bfloat16 g_kh[(size_t)M_*D_];         // K hi [BH][S][64]
__device__ __nv_bfloat16 g_kl[(size_t)M_*D_];
__device__ __nv_bfloat16 g_vth[(size_t)M_*D_];        // V^T hi [BH][64][S]
__device__ __nv_bfloat16 g_vtl[(size_t)M_*D_];

// ---------------------------------------------------------------------------
// Baseline-PTX primitives (sm_80-level: work on plain sm_103 target)
// ---------------------------------------------------------------------------
__device__ __forceinline__ uint32_t smem_u32(const void* p) {
    uint32_t a;
    asm("{ .reg .u64 t; cvta.to.shared.u64 t, %1; cvt.u32.u64 %0, t; }" : "=r"(a) : "l"(p));
    return a;
}
__device__ __forceinline__ void ldsm4(uint32_t* r, uint32_t a) {
    asm volatile("ldmatrix.sync.aligned.m8n8.x4.shared.b16 {%0,%1,%2,%3}, [%4];"
                 : "=r"(r[0]), "=r"(r[1]), "=r"(r[2]), "=r"(r[3]) : "r"(a));
}
__device__ __forceinline__ void mma_bf16(float* d, const uint32_t* a,
                                         uint32_t b0, uint32_t b1) {
    asm volatile("mma.sync.aligned.m16n8k16.row.col.f32.bf16.bf16.f32 "
                 "{%0,%1,%2,%3}, {%4,%5,%6,%7}, {%8,%9}, {%0,%1,%2,%3};"
                 : "+f"(d[0]), "+f"(d[1]), "+f"(d[2]), "+f"(d[3])
                 : "r"(a[0]), "r"(a[1]), "r"(a[2]), "r"(a[3]), "r"(b0), "r"(b1));
}
__device__ __forceinline__ void cp_async16(uint32_t dst, const void* src) {
    asm volatile("cp.async.cg.shared.global [%0], [%1], 16;" :: "r"(dst), "l"(src));
}
#define CP_COMMIT() asm volatile("cp.async.commit_group;" ::: "memory")
#define CP_WAIT1()  asm volatile("cp.async.wait_group 1;"  ::: "memory")
#define CP_WAIT0()  asm volatile("cp.async.wait_group 0;"  ::: "memory")

// pack two floats -> bf16x2 word; split2 -> hi word + lo (residual) word
__device__ __forceinline__ uint32_t pack2(float x, float y) {
    __nv_bfloat162 t(__float2bfloat16(x), __float2bfloat16(y));
    return *reinterpret_cast<uint32_t*>(&t);
}
__device__ __forceinline__ void split2(float x, float y, uint32_t& hi, uint32_t& lo) {
    __nv_bfloat16 hx = __float2bfloat16(x), hy = __float2bfloat16(y);
    __nv_bfloat162 hh(hx, hy);
    __nv_bfloat162 ll(__float2bfloat16(x - __bfloat162float(hx)),
                      __float2bfloat16(y - __bfloat162float(hy)));
    hi = *reinterpret_cast<uint32_t*>(&hh);
    lo = *reinterpret_cast<uint32_t*>(&ll);
}

// ---------------------------------------------------------------------------
// hi/lo split of fp32 activations
// ---------------------------------------------------------------------------
__global__ void conv_hilo(const float* __restrict__ X,
                          __nv_bfloat16* __restrict__ Hi,
                          __nv_bfloat16* __restrict__ Lo)
{
    size_t i = (size_t)blockIdx.x * blockDim.x + threadIdx.x;
    float4 v = ((const float4*)X)[i];
    uint32_t h0, l0, h1, l1;
    split2(v.x, v.y, h0, l0);
    split2(v.z, v.w, h1, l1);
    ((uint2*)Hi)[i] = make_uint2(h0, h1);
    ((uint2*)Lo)[i] = make_uint2(l0, l1);
}

// ---------------------------------------------------------------------------
// Transposed hi/lo weight split: Wt[n][k] = W[k][n]
// ---------------------------------------------------------------------------
__global__ void conv_wT(const float* __restrict__ W,
                        __nv_bfloat16* __restrict__ Th,
                        __nv_bfloat16* __restrict__ Tl)
{
    __shared__ float tile[32][33];
    int nx0 = blockIdx.x * 32;
    int ky0 = blockIdx.y * 32;
    #pragma unroll
    for (int i = 0; i < 4; ++i) {
        int kl = threadIdx.y + i * 8;
        tile[kl][threadIdx.x] = W[(size_t)(ky0 + kl) * D_ + nx0 + threadIdx.x];
    }
    __syncthreads();
    #pragma unroll
    for (int i = 0; i < 4; ++i) {
        int nl = threadIdx.y + i * 8;
        float v = tile[threadIdx.x][nl];
        __nv_bfloat16 h = __float2bfloat16(v);
        size_t o = (size_t)(nx0 + nl) * D_ + ky0 + threadIdx.x;
        Th[o] = h;
        Tl[o] = __float2bfloat16(v - __bfloat162float(h));
    }
}

// ---------------------------------------------------------------------------
// Projection GEMM: C[M,N] = (Ah+Al)[M,K] @ (Bh+Bl)[N,K]^T + bias  (bf16x3)
// CTA tile 128x128, K-chunk 64, 2-stage cp.async pipeline, 8 warps.
// Warp tile 64x32: warp grid 2(m) x 4(n).
// mode 0: fp32 dense out0[M][2048]
// mode 1: bf16 hi/lo split-head  out0/out1 = [BH][S][64]
// mode 2: bf16 hi/lo transposed  out0/out1 = [BH][64][S]
// ---------------------------------------------------------------------------
#define PROJ_SMEM 131072

__global__ void __launch_bounds__(256, 1) proj_gemm(
    const __nv_bfloat16* __restrict__ Ah_g, const __nv_bfloat16* __restrict__ Al_g,
    const __nv_bfloat16* __restrict__ Bh_g, const __nv_bfloat16* __restrict__ Bl_g,
    const float* __restrict__ bias, void* out0, void* out1, int mode)
{
    extern __shared__ char dyn[];
    uint32_t raw = smem_u32(dyn);
    uint32_t st  = (raw + 127u) & ~127u;
    char* stp    = dyn + (st - raw);

    const int tid = threadIdx.x, wid = tid >> 5, lane = tid & 31;
    const int n0 = blockIdx.x * 128, m0 = blockIdx.y * 128;
    const int wm = wid & 1, wn = wid >> 1;
    const int lr = lane & 15;

    uint32_t swk[4];
    #pragma unroll
    for (int kk = 0; kk < 4; ++kk)
        swk[kk] = (uint32_t)((((kk * 2 + (lane >> 4)) ^ (lane & 7)) << 4));

    auto load_chunk = [&](int c, int s) {
        uint32_t sb = st + (uint32_t)s * 65536u;
        int k0 = c * 64;
        #pragma unroll
        for (int t = 0; t < 2; ++t) {
            const __nv_bfloat16* src = t ? Al_g : Ah_g;
            uint32_t tb = sb + (uint32_t)t * 16384u;
            #pragma unroll
            for (int j = 0; j < 4; ++j) {
                int q = tid + 256 * j, row = q >> 3, ch = q & 7;
                cp_async16(tb + row * 128 + ((ch ^ (row & 7)) << 4),
                           src + (size_t)(m0 + row) * D_ + k0 + ch * 8);
            }
        }
        #pragma unroll
        for (int t = 0; t < 2; ++t) {
            const __nv_bfloat16* src = t ? Bl_g : Bh_g;
            uint32_t tb = sb + 32768u + (uint32_t)t * 16384u;
            #pragma unroll
            for (int j = 0; j < 4; ++j) {
                int q = tid + 256 * j, row = q >> 3, ch = q & 7;
                cp_async16(tb + row * 128 + ((ch ^ (row & 7)) << 4),
                           src + (size_t)(n0 + row) * D_ + k0 + ch * 8);
            }
        }
        CP_COMMIT();
    };

    float acc[4][4][4] = {};
    load_chunk(0, 0);
    load_chunk(1, 1);

    for (int c = 0; c < 32; ++c) {
        CP_WAIT1();
        __syncthreads();
        uint32_t sb = st + (uint32_t)(c & 1) * 65536u;
        uint32_t tAh = sb, tAl = sb + 16384u, tBh = sb + 32768u, tBl = sb + 49152u;
        #pragma unroll
        for (int kk = 0; kk < 4; ++kk) {
            uint32_t ah[4][4], al[4][4];
            #pragma unroll
            for (int mi = 0; mi < 4; ++mi) {
                uint32_t ro = (uint32_t)((wm * 64 + mi * 16 + lr) * 128);
                ldsm4(ah[mi], tAh + ro + swk[kk]);
                ldsm4(al[mi], tAl + ro + swk[kk]);
            }
            uint32_t bh[4][2], bl[4][2];
            #pragma unroll
            for (int nj = 0; nj < 2; ++nj) {
                uint32_t ro = (uint32_t)((wn * 32 + nj * 16 + lr) * 128);
                uint32_t r4[4];
                ldsm4(r4, tBh + ro + swk[kk]);
                bh[nj*2][0] = r4[0]; bh[nj*2][1] = r4[2];
                bh[nj*2+1][0] = r4[1]; bh[nj*2+1][1] = r4[3];
                ldsm4(r4, tBl + ro + swk[kk]);
                bl[nj*2][0] = r4[0]; bl[nj*2][1] = r4[2];
                bl[nj*2+1][0] = r4[1]; bl[nj*2+1][1] = r4[3];
            }
            #pragma unroll
            for (int mi = 0; mi < 4; ++mi)
                #pragma unroll
                for (int nb = 0; nb < 4; ++nb) {
                    mma_bf16(acc[mi][nb], ah[mi], bh[nb][0], bh[nb][1]);
                    mma_bf16(acc[mi][nb], ah[mi], bl[nb][0], bl[nb][1]);
                    mma_bf16(acc[mi][nb], al[mi], bh[nb][0], bh[nb][1]);
                }
        }
        __syncthreads();
        if (c + 2 < 32) load_chunk(c + 2, c & 1);
        else            CP_COMMIT();
    }

    // epilogue via smem tile (reuses stage memory)
    CP_WAIT0();
    float* ftile = (float*)stp;   // 128 x 132
    #pragma unroll
    for (int mi = 0; mi < 4; ++mi)
        #pragma unroll
        for (int nb = 0; nb < 4; ++nb) {
            int r  = wm * 64 + mi * 16 + (lane >> 2);
            int cc = wn * 32 + nb * 8 + (lane & 3) * 2;
            ftile[r * 132 + cc]           = acc[mi][nb][0];
            ftile[r * 132 + cc + 1]       = acc[mi][nb][1];
            ftile[(r + 8) * 132 + cc]     = acc[mi][nb][2];
            ftile[(r + 8) * 132 + cc + 1] = acc[mi][nb][3];
        }
    __syncthreads();

    if (mode == 2) {
        // V transposed: out[bh][64][S]
        const int lane4 = lane * 4;
        int bb = m0 >> 11;
        int s0 = (m0 & (S_ - 1)) + lane4;
        __nv_bfloat16* O0 = (__nv_bfloat16*)out0;
        __nv_bfloat16* O1 = (__nv_bfloat16*)out1;
        #pragma unroll
        for (int ii = 0; ii < 16; ++ii) {
            int nl = wid * 16 + ii;
            int n  = n0 + nl;
            float bvs = bias[n];
            int h = n >> 6, jj = n & 63;
            float v0 = ftile[(lane4 + 0) * 132 + nl] + bvs;
            float v1 = ftile[(lane4 + 1) * 132 + nl] + bvs;
            float v2 = ftile[(lane4 + 2) * 132 + nl] + bvs;
            float v3 = ftile[(lane4 + 3) * 132 + nl] + bvs;
            uint32_t h0, l0, h1, l1;
            split2(v0, v1, h0, l0);
            split2(v2, v3, h1, l1);
            size_t base = ((size_t)(bb * H_ + h) * DH_ + jj) * S_ + s0;
            *(uint2*)&O0[base] = make_uint2(h0, h1);
            *(uint2*)&O1[base] = make_uint2(l0, l1);
        }
    } else {
        const int c4 = (tid & 31) * 4;
        float4 bv = *(const float4*)&bias[n0 + c4];
        #pragma unroll
        for (int i = 0; i < 16; ++i) {
            int r = (tid >> 5) + i * 8;
            float4 v = *(float4*)&ftile[r * 132 + c4];
            v.x += bv.x; v.y += bv.y; v.z += bv.z; v.w += bv.w;
            int m = m0 + r;
            if (mode == 0) {
                *(float4*)&((float*)out0)[(size_t)m * D_ + n0 + c4] = v;
            } else {
                int bidx = m >> 11, s = m & (S_ - 1);
                int n = n0 + c4, h = n >> 6, jj = n & 63;
                size_t base = (((size_t)(bidx * H_ + h) * S_) + s) * DH_ + jj;
                uint32_t h0, l0, h1, l1;
                split2(v.x, v.y, h0, l0);
                split2(v.z, v.w, h1, l1);
                *(uint2*)&((__nv_bfloat16*)out0)[base] = make_uint2(h0, h1);
                *(uint2*)&((__nv_bfloat16*)out1)[base] = make_uint2(l0, l1);
            }
        }
    }
}

// ---------------------------------------------------------------------------
// QK^T: Sc[bh][m][n] = 0.125 * (Qh+Ql)[m,:] . (Kh+Kl)[n,:]   (K dim = 64)
// CTA 128x128, single K tile, 8 warps, warp tile 64x32.
// ---------------------------------------------------------------------------
#define QK_SMEM 65536

__global__ void __launch_bounds__(256, 1) qk_mma(
    const __nv_bfloat16* __restrict__ Qh, const __nv_bfloat16* __restrict__ Ql,
    const __nv_bfloat16* __restrict__ Kh, const __nv_bfloat16* __restrict__ Kl,
    float* __restrict__ Sc)
{
    extern __shared__ char dyn[];
    uint32_t raw = smem_u32(dyn);
    uint32_t st  = (raw + 127u) & ~127u;

    const int tid = threadIdx.x, wid = tid >> 5, lane = tid & 31;
    const int bh = blockIdx.z;
    const int n0 = blockIdx.x * 128, m0 = blockIdx.y * 128;
    const int wm = wid & 1, wn = wid >> 1;
    const int lr = lane & 15;

    uint32_t swk[4];
    #pragma unroll
    for (int kk = 0; kk < 4; ++kk)
        swk[kk] = (uint32_t)((((kk * 2 + (lane >> 4)) ^ (lane & 7)) << 4));

    const __nv_bfloat16* mats[4] = { Qh, Ql, Kh, Kl };
    #pragma unroll
    for (int t = 0; t < 4; ++t) {
        int rowbase = (t < 2) ? m0 : n0;
        uint32_t tb = st + (uint32_t)t * 16384u;
        const __nv_bfloat16* src = mats[t];
        #pragma unroll
        for (int j = 0; j < 4; ++j) {
            int q = tid + 256 * j, row = q >> 3, ch = q & 7;
            cp_async16(tb + row * 128 + ((ch ^ (row & 7)) << 4),
                       src + ((size_t)bh * S_ + rowbase + row) * DH_ + ch * 8);
        }
    }
    CP_COMMIT();
    CP_WAIT0();
    __syncthreads();

    uint32_t tAh = st, tAl = st + 16384u, tBh = st + 32768u, tBl = st + 49152u;
    float acc[4][4][4] = {};
    #pragma unroll
    for (int kk = 0; kk < 4; ++kk) {
        uint32_t ah[4][4], al[4][4];
        #pragma unroll
        for (int mi = 0; mi < 4; ++mi) {
            uint32_t ro = (uint32_t)((wm * 64 + mi * 16 + lr) * 128);
            ldsm4(ah[mi], tAh + ro + swk[kk]);
            ldsm4(al[mi], tAl + ro + swk[kk]);
        }
        uint32_t bhf[4][2], blf[4][2];
        #pragma unroll
        for (int nj = 0; nj < 2; ++nj) {
            uint32_t ro = (uint32_t)((wn * 32 + nj * 16 + lr) * 128);
            uint32_t r4[4];
            ldsm4(r4, tBh + ro + swk[kk]);
            bhf[nj*2][0] = r4[0]; bhf[nj*2][1] = r4[2];
            bhf[nj*2+1][0] = r4[1]; bhf[nj*2+1][1] = r4[3];
            ldsm4(r4, tBl + ro + swk[kk]);
            blf[nj*2][0] = r4[0]; blf[nj*2][1] = r4[2];
            blf[nj*2+1][0] = r4[1]; blf[nj*2+1][1] = r4[3];
        }
        #pragma unroll
        for (int mi = 0; mi < 4; ++mi)
            #pragma unroll
            for (int nb = 0; nb < 4; ++nb) {
                mma_bf16(acc[mi][nb], ah[mi], bhf[nb][0], bhf[nb][1]);
                mma_bf16(acc[mi][nb], ah[mi], blf[nb][0], blf[nb][1]);
                mma_bf16(acc[mi][nb], al[mi], bhf[nb][0], bhf[nb][1]);
            }
    }

    float* out = Sc + (size_t)bh * S_ * S_;
    const float scale = 0.125f;
    #pragma unroll
    for (int mi = 0; mi < 4; ++mi)
        #pragma unroll
        for (int nb = 0; nb < 4; ++nb) {
            float* d = acc[mi][nb];
            int r  = m0 + wm * 64 + mi * 16 + (lane >> 2);
            int cl = n0 + wn * 32 + nb * 8 + (lane & 3) * 2;
            *(float2*)&out[(size_t)r * S_ + cl]       = make_float2(d[0]*scale, d[1]*scale);
            *(float2*)&out[(size_t)(r + 8) * S_ + cl] = make_float2(d[2]*scale, d[3]*scale);
        }
}

// ---------------------------------------------------------------------------
// Row softmax: fp32 scores in -> bf16 hi/lo probs out
// ---------------------------------------------------------------------------
__global__ void __launch_bounds__(256, 1) softmax_split(
    const float* __restrict__ Sc,
    __nv_bfloat16* __restrict__ Ph, __nv_bfloat16* __restrict__ Pl)
{
    const float* p = Sc + (size_t)blockIdx.x * S_;
    __nv_bfloat16* oh = Ph + (size_t)blockIdx.x * S_;
    __nv_bfloat16* ol = Pl + (size_t)blockIdx.x * S_;
    const int tid = threadIdx.x;
    __shared__ float red[256];

    float vals[8];
    float mx = -1e30f;
    #pragma unroll
    for (int i = 0; i < 8; ++i) {
        vals[i] = p[tid + 256 * i];
        mx = fmaxf(mx, vals[i]);
    }
    red[tid] = mx; __syncthreads();
    #pragma unroll
    for (int s = 128; s > 0; s >>= 1) {
        if (tid < s) red[tid] = fmaxf(red[tid], red[tid + s]);
        __syncthreads();
    }
    mx = red[0];
    __syncthreads();

    float sum = 0.f;
    #pragma unroll
    for (int i = 0; i < 8; ++i) {
        vals[i] = __expf(vals[i] - mx);
        sum += vals[i];
    }
    red[tid] = sum; __syncthreads();
    #pragma unroll
    for (int s = 128; s > 0; s >>= 1) {
        if (tid < s) red[tid] += red[tid + s];
        __syncthreads();
    }
    float inv = 1.0f / red[0];
    #pragma unroll
    for (int i = 0; i < 8; ++i) {
        float v = vals[i] * inv;
        __nv_bfloat16 h = __float2bfloat16(v);
        oh[tid + 256 * i] = h;
        ol[tid + 256 * i] = __float2bfloat16(v - __bfloat162float(h));
    }
}

// ---------------------------------------------------------------------------
// PV: ctx[m][h*64+n] = (Ph+Pl)[bh][m][:] @ (Vth+Vtl)[bh][n][:]^T  (bf16x3)
// CTA 128m x 64n, K-chunk 64, 2-stage pipeline. Warp tile 32x32 (4m x 2n grid).
// Output: ctx hi/lo bf16 into [M][2048].
// ---------------------------------------------------------------------------
#define PV_SMEM 98304

__global__ void __launch_bounds__(256, 1) pv_mma(
    const __nv_bfloat16* __restrict__ Ph, const __nv_bfloat16* __restrict__ Pl,
    const __nv_bfloat16* __restrict__ Vth, const __nv_bfloat16* __restrict__ Vtl,
    __nv_bfloat16* __restrict__ Ch, __nv_bfloat16* __restrict__ Cl)
{
    extern __shared__ char dyn[];
    uint32_t raw = smem_u32(dyn);
    uint32_t st  = (raw + 127u) & ~127u;

    const int tid = threadIdx.x, wid = tid >> 5, lane = tid & 31;
    const int bh = blockIdx.z;
    const int m0 = blockIdx.y * 128;
    const int wm = wid & 3, wn = wid >> 2;
    const int lr = lane & 15;

    uint32_t swk[4];
    #pragma unroll
    for (int kk = 0; kk < 4; ++kk)
        swk[kk] = (uint32_t)((((kk * 2 + (lane >> 4)) ^ (lane & 7)) << 4));

    const __nv_bfloat16* Pb_h = Ph + (size_t)bh * S_ * S_;
    const __nv_bfloat16* Pb_l = Pl + (size_t)bh * S_ * S_;
    const __nv_bfloat16* Vb_h = Vth + (size_t)bh * DH_ * S_;
    const __nv_bfloat16* Vb_l = Vtl + (size_t)bh * DH_ * S_;

    auto load_chunk = [&](int c, int s) {
        uint32_t sb = st + (uint32_t)s * 49152u;
        int k0 = c * 64;
        #pragma unroll
        for (int t = 0; t < 2; ++t) {
            const __nv_bfloat16* src = t ? Pb_l : Pb_h;
            uint32_t tb = sb + (uint32_t)t * 16384u;
            #pragma unroll
            for (int j = 0; j < 4; ++j) {
                int q = tid + 256 * j, row = q >> 3, ch = q & 7;
                cp_async16(tb + row * 128 + ((ch ^ (row & 7)) << 4),
                           src + (size_t)(m0 + row) * S_ + k0 + ch * 8);
            }
        }
        #pragma unroll
        for (int t = 0; t < 2; ++t) {
            const __nv_bfloat16* src = t ? Vb_l : Vb_h;
            uint32_t tb = sb + 32768u + (uint32_t)t * 8192u;
            #pragma unroll
            for (int j = 0; j < 2; ++j) {
                int q = tid + 256 * j, row = q >> 3, ch = q & 7;   // row 0..63
                cp_async16(tb + row * 128 + ((ch ^ (row & 7)) << 4),
                           src + (size_t)row * S_ + k0 + ch * 8);
            }
        }
        CP_COMMIT();
    };

    float acc[2][4][4] = {};
    load_chunk(0, 0);
    load_chunk(1, 1);

    for (int c = 0; c < 32; ++c) {
        CP_WAIT1();
        __syncthreads();
        uint32_t sb = st + (uint32_t)(c & 1) * 49152u;
        uint32_t tAh = sb, tAl = sb + 16384u, tBh = sb + 32768u, tBl = sb + 40960u;
        #pragma unroll
        for (int kk = 0; kk < 4; ++kk) {
            uint32_t ah[2][4], al[2][4];
            #pragma unroll
            for (int mi = 0; mi < 2; ++mi) {
                uint32_t ro = (uint32_t)((wm * 32 + mi * 16 + lr) * 128);
                ldsm4(ah[mi], tAh + ro + swk[kk]);
                ldsm4(al[mi], tAl + ro + swk[kk]);
            }
            uint32_t bhf[4][2], blf[4][2];
            #pragma unroll
            for (int nj = 0; nj < 2; ++nj) {
                uint32_t ro = (uint32_t)((wn * 32 + nj * 16 + lr) * 128);
                uint32_t r4[4];
                ldsm4(r4, tBh + ro + swk[kk]);
                bhf[nj*2][0] = r4[0]; bhf[nj*2][1] = r4[2];
                bhf[nj*2+1][0] = r4[1]; bhf[nj*2+1][1] = r4[3];
                ldsm4(r4, tBl + ro + swk[kk]);
                blf[nj*2][0] = r4[0]; blf[nj*2][1] = r4[2];
                blf[nj*2+1][0] = r4[1]; blf[nj*2+1][1] = r4[3];
            }
            #pragma unroll
            for (int mi = 0; mi < 2; ++mi)
                #pragma unroll
                for (int nb = 0; nb < 4; ++nb) {
                    mma_bf16(acc[mi][nb], ah[mi], bhf[nb][0], bhf[nb][1]);
                    mma_bf16(acc[mi][nb], ah[mi], blf[nb][0], blf[nb][1]);
                    mma_bf16(acc[mi][nb], al[mi], bhf[nb][0], bhf[nb][1]);
                }
        }
        __syncthreads();
        if (c + 2 < 32) load_chunk(c + 2, c & 1);
        else            CP_COMMIT();
    }

    // direct epilogue: split into ctx hi/lo at [b*2048+r][h*64+col]
    const int b = bh >> 5, h = bh & 31;
    #pragma unroll
    for (int mi = 0; mi < 2; ++mi)
        #pragma unroll
        for (int nb = 0; nb < 4; ++nb) {
            float* d = acc[mi][nb];
            int r  = m0 + wm * 32 + mi * 16 + (lane >> 2);
            int cl = wn * 32 + nb * 8 + (lane & 3) * 2;
            size_t idx = ((size_t)(b * S_) + r) * D_ + h * DH_ + cl;
            uint32_t hw, lw;
            split2(d[0], d[1], hw, lw);
            *(uint32_t*)&Ch[idx] = hw;
            *(uint32_t*)&Cl[idx] = lw;
            split2(d[2], d[3], hw, lw);
            *(uint32_t*)&Ch[idx + 8 * D_] = hw;
            *(uint32_t*)&Cl[idx + 8 * D_] = lw;
        }
}

// ---------------------------------------------------------------------------
extern "C" void kernel_launch(void* const* d_in, const int* in_sizes, int n_in,
                              void* d_out, int out_size)
{
    const float* X  = (const float*)d_in[0];
    const float* Wq = (const float*)d_in[1];
    const float* bq = (const float*)d_in[2];
    const float* Wk = (const float*)d_in[3];
    const float* bk = (const float*)d_in[4];
    const float* Wv = (const float*)d_in[5];
    const float* bv = (const float*)d_in[6];
    const float* Wo = (const float*)d_in[7];
    const float* bo = (const float*)d_in[8];
    float* out = (float*)d_out;

    float* sc;
    __nv_bfloat16 *ph, *pl, *xh, *xl, *wh, *wl, *qh, *ql, *kh, *kl, *vth, *vtl;
    cudaGetSymbolAddress((void**)&sc,  g_sc);
    cudaGetSymbolAddress((void**)&ph,  g_ph);
    cudaGetSymbolAddress((void**)&pl,  g_pl);
    cudaGetSymbolAddress((void**)&xh,  g_xh);
    cudaGetSymbolAddress((void**)&xl,  g_xl);
    cudaGetSymbolAddress((void**)&wh,  g_wh);
    cudaGetSymbolAddress((void**)&wl,  g_wl);
    cudaGetSymbolAddress((void**)&qh,  g_qh);
    cudaGetSymbolAddress((void**)&ql,  g_ql);
    cudaGetSymbolAddress((void**)&kh,  g_kh);
    cudaGetSymbolAddress((void**)&kl,  g_kl);
    cudaGetSymbolAddress((void**)&vth, g_vth);
    cudaGetSymbolAddress((void**)&vtl, g_vtl);

    static bool attr_done = false;
    if (!attr_done) {
        cudaFuncSetAttribute(proj_gemm, cudaFuncAttributeMaxDynamicSharedMemorySize, PROJ_SMEM);
        cudaFuncSetAttribute(qk_mma,    cudaFuncAttributeMaxDynamicSharedMemorySize, QK_SMEM);
        cudaFuncSetAttribute(pv_mma,    cudaFuncAttributeMaxDynamicSharedMemorySize, PV_SMEM);
        attr_done = true;
    }

    const size_t WSZ = (size_t)D_ * D_;

    // conversions
    conv_hilo<<<(M_ * (size_t)D_) / 1024, 256>>>(X, xh, xl);
    dim3 tblk(32, 8), tgrid(D_ / 32, D_ / 32);
    conv_wT<<<tgrid, tblk>>>(Wq, wh + 0 * WSZ, wl + 0 * WSZ);
    conv_wT<<<tgrid, tblk>>>(Wk, wh + 1 * WSZ, wl + 1 * WSZ);
    conv_wT<<<tgrid, tblk>>>(Wv, wh + 2 * WSZ, wl + 2 * WSZ);
    conv_wT<<<tgrid, tblk>>>(Wo, wh + 3 * WSZ, wl + 3 * WSZ);

    // projections
    dim3 pblk(256), pgrid(D_ / 128, M_ / 128);   // (16, 32)
    proj_gemm<<<pgrid, pblk, PROJ_SMEM>>>(xh, xl, wh + 0 * WSZ, wl + 0 * WSZ, bq, qh, ql, 1);
    proj_gemm<<<pgrid, pblk, PROJ_SMEM>>>(xh, xl, wh + 1 * WSZ, wl + 1 * WSZ, bk, kh, kl, 1);
    proj_gemm<<<pgrid, pblk, PROJ_SMEM>>>(xh, xl, wh + 2 * WSZ, wl + 2 * WSZ, bv, vth, vtl, 2);

    // attention
    dim3 qkgrid(S_ / 128, S_ / 128, BH_);        // (16, 16, 64)
    qk_mma<<<qkgrid, pblk, QK_SMEM>>>(qh, ql, kh, kl, sc);
    softmax_split<<<(unsigned)((size_t)BH_ * S_), pblk>>>(sc, ph, pl);
    dim3 pvgrid(1, S_ / 128, BH_);               // (1, 16, 64)
    pv_mma<<<pvgrid, pblk, PV_SMEM>>>(ph, pl, vth, vtl, xh, xl);   // ctx -> xh/xl

    // output projection
    proj_gemm<<<pgrid, pblk, PROJ_SMEM>>>(xh, xl, wh + 3 * WSZ, wl + 3 * WSZ, bo, out, nullptr, 0);
}

// round 4
// speedup vs baseline: 3.1477x; 1.0964x over previous
#include <cuda_runtime.h>
#include <cuda_fp16.h>
#include <cstdint>

#define B_   2
#define S_   2048
#define D_   2048
#define H_   32
#define DH_  64
#define M_   (B_*S_)    // 4096
#define BH_  (B_*H_)    // 64

// ---------------------------------------------------------------------------
// Scratch (static __device__ arrays: allocation-guard safe)
// ---------------------------------------------------------------------------
__device__ float  g_sc[(size_t)BH_*S_*S_];     // fp32 scores, 1 GB
__device__ __half g_ph[(size_t)BH_*S_*S_];     // probs hi (fp16)
__device__ __half g_pl[(size_t)BH_*S_*S_];     // probs lo
__device__ __half g_xh[(size_t)M_*D_];         // X hi (later ctx hi)
__device__ __half g_xl[(size_t)M_*D_];         // X lo (later ctx lo)
__device__ __half g_wh[(size_t)4*D_*D_];       // Wt fp16 [N][K] (4 mats)
__device__ __half g_wl[(size_t)D_*D_];         // Wo lo only (3-term hedge)
__device__ __half g_qh[(size_t)M_*D_];         // Q hi [BH][S][64]
__device__ __half g_ql[(size_t)M_*D_];         // Q lo
__device__ __half g_kh[(size_t)M_*D_];         // K fp16 single [BH][S][64]
__device__ __half g_vth[(size_t)M_*D_];        // V^T fp16 single [BH][64][S]

// ---------------------------------------------------------------------------
// Baseline-PTX primitives (sm_80-level; assemble for plain sm_103 target)
// ---------------------------------------------------------------------------
__device__ __forceinline__ uint32_t smem_u32(const void* p) {
    uint32_t a;
    asm("{ .reg .u64 t; cvta.to.shared.u64 t, %1; cvt.u32.u64 %0, t; }" : "=r"(a) : "l"(p));
    return a;
}
__device__ __forceinline__ void ldsm4(uint32_t* r, uint32_t a) {
    asm volatile("ldmatrix.sync.aligned.m8n8.x4.shared.b16 {%0,%1,%2,%3}, [%4];"
                 : "=r"(r[0]), "=r"(r[1]), "=r"(r[2]), "=r"(r[3]) : "r"(a));
}
__device__ __forceinline__ void mma_f16(float* d, const uint32_t* a,
                                        uint32_t b0, uint32_t b1) {
    asm volatile("mma.sync.aligned.m16n8k16.row.col.f32.f16.f16.f32 "
                 "{%0,%1,%2,%3}, {%4,%5,%6,%7}, {%8,%9}, {%0,%1,%2,%3};"
                 : "+f"(d[0]), "+f"(d[1]), "+f"(d[2]), "+f"(d[3])
                 : "r"(a[0]), "r"(a[1]), "r"(a[2]), "r"(a[3]), "r"(b0), "r"(b1));
}
__device__ __forceinline__ void cp_async16(uint32_t dst, const void* src) {
    asm volatile("cp.async.cg.shared.global [%0], [%1], 16;" :: "r"(dst), "l"(src));
}
#define CP_COMMIT() asm volatile("cp.async.commit_group;" ::: "memory")
#define CP_WAIT1()  asm volatile("cp.async.wait_group 1;"  ::: "memory")
#define CP_WAIT0()  asm volatile("cp.async.wait_group 0;"  ::: "memory")

__device__ __forceinline__ uint32_t hpack2(float x, float y) {
    __half2 t = __halves2half2(__float2half_rn(x), __float2half_rn(y));
    return *reinterpret_cast<uint32_t*>(&t);
}
__device__ __forceinline__ void hsplit2(float x, float y, uint32_t& hi, uint32_t& lo) {
    __half hx = __float2half_rn(x), hy = __float2half_rn(y);
    __half2 hh = __halves2half2(hx, hy);
    __half2 ll = __halves2half2(__float2half_rn(x - __half2float(hx)),
                                __float2half_rn(y - __half2float(hy)));
    hi = *reinterpret_cast<uint32_t*>(&hh);
    lo = *reinterpret_cast<uint32_t*>(&ll);
}

// ---------------------------------------------------------------------------
// fp16 hi/lo split of fp32 activations
// ---------------------------------------------------------------------------
__global__ void conv_hilo(const float* __restrict__ X,
                          __half* __restrict__ Hi, __half* __restrict__ Lo)
{
    size_t i = (size_t)blockIdx.x * blockDim.x + threadIdx.x;
    float4 v = ((const float4*)X)[i];
    uint32_t h0, l0, h1, l1;
    hsplit2(v.x, v.y, h0, l0);
    hsplit2(v.z, v.w, h1, l1);
    ((uint2*)Hi)[i] = make_uint2(h0, h1);
    ((uint2*)Lo)[i] = make_uint2(l0, l1);
}

// ---------------------------------------------------------------------------
// Transposed fp16 weight: Wt[n][k] = W[k][n]; optional lo residual
// ---------------------------------------------------------------------------
__global__ void conv_wT(const float* __restrict__ W,
                        __half* __restrict__ Th, __half* __restrict__ Tl,
                        int with_lo)
{
    __shared__ float tile[32][33];
    int nx0 = blockIdx.x * 32;
    int ky0 = blockIdx.y * 32;
    #pragma unroll
    for (int i = 0; i < 4; ++i) {
        int kl = threadIdx.y + i * 8;
        tile[kl][threadIdx.x] = W[(size_t)(ky0 + kl) * D_ + nx0 + threadIdx.x];
    }
    __syncthreads();
    #pragma unroll
    for (int i = 0; i < 4; ++i) {
        int nl = threadIdx.y + i * 8;
        float v = tile[threadIdx.x][nl];
        __half h = __float2half_rn(v);
        size_t o = (size_t)(nx0 + nl) * D_ + ky0 + threadIdx.x;
        Th[o] = h;
        if (with_lo) Tl[o] = __float2half_rn(v - __half2float(h));
    }
}

// ---------------------------------------------------------------------------
// Projection GEMM: C[M,N] = (Ah+Al)[M,K] @ B[N,K]^T + bias
// A = fp16 hi/lo split; B = fp16 (optionally hi/lo when three=1 for 3-term).
// CTA 128x128, K-chunk 64, 2-stage cp.async, 8 warps (warp 64x32).
// mode 0: fp32 dense out0[M][2048]
// mode 1: fp16 hi/lo split-head  (Q)
// mode 2: fp16 single transposed (V^T [BH][64][S])
// mode 3: fp16 single split-head (K)
// ---------------------------------------------------------------------------
#define PROJ_SMEM 131072

__global__ void __launch_bounds__(256, 1) proj_gemm(
    const __half* __restrict__ Ah_g, const __half* __restrict__ Al_g,
    const __half* __restrict__ Bh_g, const __half* __restrict__ Bl_g,
    const float* __restrict__ bias, void* out0, void* out1, int mode, int three)
{
    extern __shared__ char dyn[];
    uint32_t raw = smem_u32(dyn);
    uint32_t st  = (raw + 127u) & ~127u;
    char* stp    = dyn + (st - raw);

    const int tid = threadIdx.x, wid = tid >> 5, lane = tid & 31;
    const int n0 = blockIdx.x * 128, m0 = blockIdx.y * 128;
    const int wm = wid & 1, wn = wid >> 1;
    const int lr = lane & 15;

    uint32_t swk[4];
    #pragma unroll
    for (int kk = 0; kk < 4; ++kk)
        swk[kk] = (uint32_t)((((kk * 2 + (lane >> 4)) ^ (lane & 7)) << 4));

    auto load_chunk = [&](int c, int s) {
        uint32_t sb = st + (uint32_t)s * 65536u;
        int k0 = c * 64;
        #pragma unroll
        for (int t = 0; t < 2; ++t) {
            const __half* src = t ? Al_g : Ah_g;
            uint32_t tb = sb + (uint32_t)t * 16384u;
            #pragma unroll
            for (int j = 0; j < 4; ++j) {
                int q = tid + 256 * j, row = q >> 3, ch = q & 7;
                cp_async16(tb + row * 128 + ((ch ^ (row & 7)) << 4),
                           src + (size_t)(m0 + row) * D_ + k0 + ch * 8);
            }
        }
        #pragma unroll
        for (int j = 0; j < 4; ++j) {
            int q = tid + 256 * j, row = q >> 3, ch = q & 7;
            cp_async16(sb + 32768u + row * 128 + ((ch ^ (row & 7)) << 4),
                       Bh_g + (size_t)(n0 + row) * D_ + k0 + ch * 8);
        }
        if (three) {
            #pragma unroll
            for (int j = 0; j < 4; ++j) {
                int q = tid + 256 * j, row = q >> 3, ch = q & 7;
                cp_async16(sb + 49152u + row * 128 + ((ch ^ (row & 7)) << 4),
                           Bl_g + (size_t)(n0 + row) * D_ + k0 + ch * 8);
            }
        }
        CP_COMMIT();
    };

    float acc[4][4][4] = {};
    load_chunk(0, 0);
    load_chunk(1, 1);

    for (int c = 0; c < 32; ++c) {
        CP_WAIT1();
        __syncthreads();
        uint32_t sb = st + (uint32_t)(c & 1) * 65536u;
        uint32_t tAh = sb, tAl = sb + 16384u, tBh = sb + 32768u, tBl = sb + 49152u;
        #pragma unroll
        for (int kk = 0; kk < 4; ++kk) {
            uint32_t ah[4][4], al[4][4];
            #pragma unroll
            for (int mi = 0; mi < 4; ++mi) {
                uint32_t ro = (uint32_t)((wm * 64 + mi * 16 + lr) * 128);
                ldsm4(ah[mi], tAh + ro + swk[kk]);
                ldsm4(al[mi], tAl + ro + swk[kk]);
            }
            uint32_t bh[4][2], bl[4][2];
            #pragma unroll
            for (int nj = 0; nj < 2; ++nj) {
                uint32_t ro = (uint32_t)((wn * 32 + nj * 16 + lr) * 128);
                uint32_t r4[4];
                ldsm4(r4, tBh + ro + swk[kk]);
                bh[nj*2][0] = r4[0]; bh[nj*2][1] = r4[2];
                bh[nj*2+1][0] = r4[1]; bh[nj*2+1][1] = r4[3];
                if (three) {
                    ldsm4(r4, tBl + ro + swk[kk]);
                    bl[nj*2][0] = r4[0]; bl[nj*2][1] = r4[2];
                    bl[nj*2+1][0] = r4[1]; bl[nj*2+1][1] = r4[3];
                }
            }
            #pragma unroll
            for (int mi = 0; mi < 4; ++mi)
                #pragma unroll
                for (int nb = 0; nb < 4; ++nb) {
                    mma_f16(acc[mi][nb], ah[mi], bh[nb][0], bh[nb][1]);
                    mma_f16(acc[mi][nb], al[mi], bh[nb][0], bh[nb][1]);
                    if (three)
                        mma_f16(acc[mi][nb], ah[mi], bl[nb][0], bl[nb][1]);
                }
        }
        __syncthreads();
        if (c + 2 < 32) load_chunk(c + 2, c & 1);
        else            CP_COMMIT();
    }

    // epilogue via smem fp32 tile (reuses stage memory)
    CP_WAIT0();
    float* ftile = (float*)stp;   // 128 x 132
    #pragma unroll
    for (int mi = 0; mi < 4; ++mi)
        #pragma unroll
        for (int nb = 0; nb < 4; ++nb) {
            int r  = wm * 64 + mi * 16 + (lane >> 2);
            int cc = wn * 32 + nb * 8 + (lane & 3) * 2;
            ftile[r * 132 + cc]           = acc[mi][nb][0];
            ftile[r * 132 + cc + 1]       = acc[mi][nb][1];
            ftile[(r + 8) * 132 + cc]     = acc[mi][nb][2];
            ftile[(r + 8) * 132 + cc + 1] = acc[mi][nb][3];
        }
    __syncthreads();

    if (mode == 2) {
        // V^T single fp16: out[bh][64][S]
        const int lane4 = lane * 4;
        int bb = m0 >> 11;
        int s0 = (m0 & (S_ - 1)) + lane4;
        __half* O0 = (__half*)out0;
        #pragma unroll
        for (int ii = 0; ii < 16; ++ii) {
            int nl = wid * 16 + ii;
            int n  = n0 + nl;
            float bvs = bias[n];
            int h = n >> 6, jj = n & 63;
            float v0 = ftile[(lane4 + 0) * 132 + nl] + bvs;
            float v1 = ftile[(lane4 + 1) * 132 + nl] + bvs;
            float v2 = ftile[(lane4 + 2) * 132 + nl] + bvs;
            float v3 = ftile[(lane4 + 3) * 132 + nl] + bvs;
            size_t base = ((size_t)(bb * H_ + h) * DH_ + jj) * S_ + s0;
            *(uint2*)&O0[base] = make_uint2(hpack2(v0, v1), hpack2(v2, v3));
        }
    } else {
        const int c4 = (tid & 31) * 4;
        float4 bv = *(const float4*)&bias[n0 + c4];
        #pragma unroll
        for (int i = 0; i < 16; ++i) {
            int r = (tid >> 5) + i * 8;
            float4 v = *(float4*)&ftile[r * 132 + c4];
            v.x += bv.x; v.y += bv.y; v.z += bv.z; v.w += bv.w;
            int m = m0 + r;
            if (mode == 0) {
                *(float4*)&((float*)out0)[(size_t)m * D_ + n0 + c4] = v;
            } else {
                int bidx = m >> 11, s = m & (S_ - 1);
                int n = n0 + c4, h = n >> 6, jj = n & 63;
                size_t base = (((size_t)(bidx * H_ + h) * S_) + s) * DH_ + jj;
                if (mode == 1) {
                    uint32_t h0, l0, h1, l1;
                    hsplit2(v.x, v.y, h0, l0);
                    hsplit2(v.z, v.w, h1, l1);
                    *(uint2*)&((__half*)out0)[base] = make_uint2(h0, h1);
                    *(uint2*)&((__half*)out1)[base] = make_uint2(l0, l1);
                } else { // mode 3: single fp16
                    *(uint2*)&((__half*)out0)[base] =
                        make_uint2(hpack2(v.x, v.y), hpack2(v.z, v.w));
                }
            }
        }
    }
}

// ---------------------------------------------------------------------------
// QK^T: Sc = 0.125 * (Qh+Ql) . K^T   (K quantized fp16; 2 MMAs per frag)
// ---------------------------------------------------------------------------
#define QK_SMEM 49152

__global__ void __launch_bounds__(256, 1) qk_mma(
    const __half* __restrict__ Qh, const __half* __restrict__ Ql,
    const __half* __restrict__ Kh, float* __restrict__ Sc)
{
    extern __shared__ char dyn[];
    uint32_t raw = smem_u32(dyn);
    uint32_t st  = (raw + 127u) & ~127u;

    const int tid = threadIdx.x, wid = tid >> 5, lane = tid & 31;
    const int bh = blockIdx.z;
    const int n0 = blockIdx.x * 128, m0 = blockIdx.y * 128;
    const int wm = wid & 1, wn = wid >> 1;
    const int lr = lane & 15;

    uint32_t swk[4];
    #pragma unroll
    for (int kk = 0; kk < 4; ++kk)
        swk[kk] = (uint32_t)((((kk * 2 + (lane >> 4)) ^ (lane & 7)) << 4));

    const __half* mats[3] = { Qh, Ql, Kh };
    #pragma unroll
    for (int t = 0; t < 3; ++t) {
        int rowbase = (t < 2) ? m0 : n0;
        uint32_t tb = st + (uint32_t)t * 16384u;
        const __half* src = mats[t];
        #pragma unroll
        for (int j = 0; j < 4; ++j) {
            int q = tid + 256 * j, row = q >> 3, ch = q & 7;
            cp_async16(tb + row * 128 + ((ch ^ (row & 7)) << 4),
                       src + ((size_t)bh * S_ + rowbase + row) * DH_ + ch * 8);
        }
    }
    CP_COMMIT();
    CP_WAIT0();
    __syncthreads();

    uint32_t tAh = st, tAl = st + 16384u, tB = st + 32768u;
    float acc[4][4][4] = {};
    #pragma unroll
    for (int kk = 0; kk < 4; ++kk) {
        uint32_t ah[4][4], al[4][4];
        #pragma unroll
        for (int mi = 0; mi < 4; ++mi) {
            uint32_t ro = (uint32_t)((wm * 64 + mi * 16 + lr) * 128);
            ldsm4(ah[mi], tAh + ro + swk[kk]);
            ldsm4(al[mi], tAl + ro + swk[kk]);
        }
        uint32_t bf[4][2];
        #pragma unroll
        for (int nj = 0; nj < 2; ++nj) {
            uint32_t ro = (uint32_t)((wn * 32 + nj * 16 + lr) * 128);
            uint32_t r4[4];
            ldsm4(r4, tB + ro + swk[kk]);
            bf[nj*2][0] = r4[0]; bf[nj*2][1] = r4[2];
            bf[nj*2+1][0] = r4[1]; bf[nj*2+1][1] = r4[3];
        }
        #pragma unroll
        for (int mi = 0; mi < 4; ++mi)
            #pragma unroll
            for (int nb = 0; nb < 4; ++nb) {
                mma_f16(acc[mi][nb], ah[mi], bf[nb][0], bf[nb][1]);
                mma_f16(acc[mi][nb], al[mi], bf[nb][0], bf[nb][1]);
            }
    }

    float* out = Sc + (size_t)bh * S_ * S_;
    const float scale = 0.125f;
    #pragma unroll
    for (int mi = 0; mi < 4; ++mi)
        #pragma unroll
        for (int nb = 0; nb < 4; ++nb) {
            float* d = acc[mi][nb];
            int r  = m0 + wm * 64 + mi * 16 + (lane >> 2);
            int cl = n0 + wn * 32 + nb * 8 + (lane & 3) * 2;
            *(float2*)&out[(size_t)r * S_ + cl]       = make_float2(d[0]*scale, d[1]*scale);
            *(float2*)&out[(size_t)(r + 8) * S_ + cl] = make_float2(d[2]*scale, d[3]*scale);
        }
}

// ---------------------------------------------------------------------------
// Row softmax: fp32 scores -> fp16 hi/lo probs
// ---------------------------------------------------------------------------
__global__ void __launch_bounds__(256, 1) softmax_split(
    const float* __restrict__ Sc,
    __half* __restrict__ Ph, __half* __restrict__ Pl)
{
    const float* p = Sc + (size_t)blockIdx.x * S_;
    __half* oh = Ph + (size_t)blockIdx.x * S_;
    __half* ol = Pl + (size_t)blockIdx.x * S_;
    const int tid = threadIdx.x;
    __shared__ float red[256];

    float vals[8];
    float mx = -1e30f;
    #pragma unroll
    for (int i = 0; i < 8; ++i) {
        vals[i] = p[tid + 256 * i];
        mx = fmaxf(mx, vals[i]);
    }
    red[tid] = mx; __syncthreads();
    #pragma unroll
    for (int s = 128; s > 0; s >>= 1) {
        if (tid < s) red[tid] = fmaxf(red[tid], red[tid + s]);
        __syncthreads();
    }
    mx = red[0];
    __syncthreads();

    float sum = 0.f;
    #pragma unroll
    for (int i = 0; i < 8; ++i) {
        vals[i] = __expf(vals[i] - mx);
        sum += vals[i];
    }
    red[tid] = sum; __syncthreads();
    #pragma unroll
    for (int s = 128; s > 0; s >>= 1) {
        if (tid < s) red[tid] += red[tid + s];
        __syncthreads();
    }
    float inv = 1.0f / red[0];
    #pragma unroll
    for (int i = 0; i < 8; ++i) {
        float v = vals[i] * inv;
        __half h = __float2half_rn(v);
        oh[tid + 256 * i] = h;
        ol[tid + 256 * i] = __float2half_rn(v - __half2float(h));
    }
}

// ---------------------------------------------------------------------------
// PV: ctx = (Ph+Pl) @ V   (V quantized fp16; 2 MMAs). CTA 128m x 64n.
// Output: ctx fp16 hi/lo into [M][2048].
// ---------------------------------------------------------------------------
#define PV_SMEM 81920

__global__ void __launch_bounds__(256, 1) pv_mma(
    const __half* __restrict__ Ph, const __half* __restrict__ Pl,
    const __half* __restrict__ Vt,
    __half* __restrict__ Ch, __half* __restrict__ Cl)
{
    extern __shared__ char dyn[];
    uint32_t raw = smem_u32(dyn);
    uint32_t st  = (raw + 127u) & ~127u;

    const int tid = threadIdx.x, wid = tid >> 5, lane = tid & 31;
    const int bh = blockIdx.z;
    const int m0 = blockIdx.y * 128;
    const int wm = wid & 3, wn = wid >> 2;
    const int lr = lane & 15;

    uint32_t swk[4];
    #pragma unroll
    for (int kk = 0; kk < 4; ++kk)
        swk[kk] = (uint32_t)((((kk * 2 + (lane >> 4)) ^ (lane & 7)) << 4));

    const __half* Pb_h = Ph + (size_t)bh * S_ * S_;
    const __half* Pb_l = Pl + (size_t)bh * S_ * S_;
    const __half* Vb   = Vt + (size_t)bh * DH_ * S_;

    auto load_chunk = [&](int c, int s) {
        uint32_t sb = st + (uint32_t)s * 40960u;
        int k0 = c * 64;
        #pragma unroll
        for (int t = 0; t < 2; ++t) {
            const __half* src = t ? Pb_l : Pb_h;
            uint32_t tb = sb + (uint32_t)t * 16384u;
            #pragma unroll
            for (int j = 0; j < 4; ++j) {
                int q = tid + 256 * j, row = q >> 3, ch = q & 7;
                cp_async16(tb + row * 128 + ((ch ^ (row & 7)) << 4),
                           src + (size_t)(m0 + row) * S_ + k0 + ch * 8);
            }
        }
        #pragma unroll
        for (int j = 0; j < 2; ++j) {
            int q = tid + 256 * j, row = q >> 3, ch = q & 7;   // row 0..63
            cp_async16(sb + 32768u + row * 128 + ((ch ^ (row & 7)) << 4),
                       Vb + (size_t)row * S_ + k0 + ch * 8);
        }
        CP_COMMIT();
    };

    float acc[2][4][4] = {};
    load_chunk(0, 0);
    load_chunk(1, 1);

    for (int c = 0; c < 32; ++c) {
        CP_WAIT1();
        __syncthreads();
        uint32_t sb = st + (uint32_t)(c & 1) * 40960u;
        uint32_t tAh = sb, tAl = sb + 16384u, tB = sb + 32768u;
        #pragma unroll
        for (int kk = 0; kk < 4; ++kk) {
            uint32_t ah[2][4], al[2][4];
            #pragma unroll
            for (int mi = 0; mi < 2; ++mi) {
                uint32_t ro = (uint32_t)((wm * 32 + mi * 16 + lr) * 128);
                ldsm4(ah[mi], tAh + ro + swk[kk]);
                ldsm4(al[mi], tAl + ro + swk[kk]);
            }
            uint32_t bf[4][2];
            #pragma unroll
            for (int nj = 0; nj < 2; ++nj) {
                uint32_t ro = (uint32_t)((wn * 32 + nj * 16 + lr) * 128);
                uint32_t r4[4];
                ldsm4(r4, tB + ro + swk[kk]);
                bf[nj*2][0] = r4[0]; bf[nj*2][1] = r4[2];
                bf[nj*2+1][0] = r4[1]; bf[nj*2+1][1] = r4[3];
            }
            #pragma unroll
            for (int mi = 0; mi < 2; ++mi)
                #pragma unroll
                for (int nb = 0; nb < 4; ++nb) {
                    mma_f16(acc[mi][nb], ah[mi], bf[nb][0], bf[nb][1]);
                    mma_f16(acc[mi][nb], al[mi], bf[nb][0], bf[nb][1]);
                }
        }
        __syncthreads();
        if (c + 2 < 32) load_chunk(c + 2, c & 1);
        else            CP_COMMIT();
    }

    // direct epilogue: ctx hi/lo fp16 at [b*2048+r][h*64+col]
    const int b = bh >> 5, h = bh & 31;
    #pragma unroll
    for (int mi = 0; mi < 2; ++mi)
        #pragma unroll
        for (int nb = 0; nb < 4; ++nb) {
            float* d = acc[mi][nb];
            int r  = m0 + wm * 32 + mi * 16 + (lane >> 2);
            int cl = wn * 32 + nb * 8 + (lane & 3) * 2;
            size_t idx = ((size_t)(b * S_) + r) * D_ + h * DH_ + cl;
            uint32_t hw, lw;
            hsplit2(d[0], d[1], hw, lw);
            *(uint32_t*)&Ch[idx] = hw;
            *(uint32_t*)&Cl[idx] = lw;
            hsplit2(d[2], d[3], hw, lw);
            *(uint32_t*)&Ch[idx + 8 * D_] = hw;
            *(uint32_t*)&Cl[idx + 8 * D_] = lw;
        }
}

// ---------------------------------------------------------------------------
extern "C" void kernel_launch(void* const* d_in, const int* in_sizes, int n_in,
                              void* d_out, int out_size)
{
    const float* X  = (const float*)d_in[0];
    const float* Wq = (const float*)d_in[1];
    const float* bq = (const float*)d_in[2];
    const float* Wk = (const float*)d_in[3];
    const float* bk = (const float*)d_in[4];
    const float* Wv = (const float*)d_in[5];
    const float* bv = (const float*)d_in[6];
    const float* Wo = (const float*)d_in[7];
    const float* bo = (const float*)d_in[8];
    float* out = (float*)d_out;

    float* sc;
    __half *ph, *pl, *xh, *xl, *wh, *wl, *qh, *ql, *kh, *vth;
    cudaGetSymbolAddress((void**)&sc,  g_sc);
    cudaGetSymbolAddress((void**)&ph,  g_ph);
    cudaGetSymbolAddress((void**)&pl,  g_pl);
    cudaGetSymbolAddress((void**)&xh,  g_xh);
    cudaGetSymbolAddress((void**)&xl,  g_xl);
    cudaGetSymbolAddress((void**)&wh,  g_wh);
    cudaGetSymbolAddress((void**)&wl,  g_wl);
    cudaGetSymbolAddress((void**)&qh,  g_qh);
    cudaGetSymbolAddress((void**)&ql,  g_ql);
    cudaGetSymbolAddress((void**)&kh,  g_kh);
    cudaGetSymbolAddress((void**)&vth, g_vth);

    static bool attr_done = false;
    if (!attr_done) {
        cudaFuncSetAttribute(proj_gemm, cudaFuncAttributeMaxDynamicSharedMemorySize, PROJ_SMEM);
        cudaFuncSetAttribute(qk_mma,    cudaFuncAttributeMaxDynamicSharedMemorySize, QK_SMEM);
        cudaFuncSetAttribute(pv_mma,    cudaFuncAttributeMaxDynamicSharedMemorySize, PV_SMEM);
        attr_done = true;
    }

    const size_t WSZ = (size_t)D_ * D_;

    // conversions
    conv_hilo<<<(M_ * (size_t)D_) / 1024, 256>>>(X, xh, xl);
    dim3 tblk(32, 8), tgrid(D_ / 32, D_ / 32);
    conv_wT<<<tgrid, tblk>>>(Wq, wh + 0 * WSZ, nullptr, 0);
    conv_wT<<<tgrid, tblk>>>(Wk, wh + 1 * WSZ, nullptr, 0);
    conv_wT<<<tgrid, tblk>>>(Wv, wh + 2 * WSZ, nullptr, 0);
    conv_wT<<<tgrid, tblk>>>(Wo, wh + 3 * WSZ, wl, 1);      // hi/lo for out-proj

    // projections (2-term fp16)
    dim3 pblk(256), pgrid(D_ / 128, M_ / 128);   // (16, 32)
    proj_gemm<<<pgrid, pblk, PROJ_SMEM>>>(xh, xl, wh + 0 * WSZ, nullptr, bq, qh, ql, 1, 0);
    proj_gemm<<<pgrid, pblk, PROJ_SMEM>>>(xh, xl, wh + 1 * WSZ, nullptr, bk, kh, nullptr, 3, 0);
    proj_gemm<<<pgrid, pblk, PROJ_SMEM>>>(xh, xl, wh + 2 * WSZ, nullptr, bv, vth, nullptr, 2, 0);

    // attention
    dim3 qkgrid(S_ / 128, S_ / 128, BH_);        // (16, 16, 64)
    qk_mma<<<qkgrid, pblk, QK_SMEM>>>(qh, ql, kh, sc);
    softmax_split<<<(unsigned)((size_t)BH_ * S_), pblk>>>(sc, ph, pl);
    dim3 pvgrid(1, S_ / 128, BH_);               // (1, 16, 64)
    pv_mma<<<pvgrid, pblk, PV_SMEM>>>(ph, pl, vth, xh, xl);   // ctx -> xh/xl

    // output projection (3-term hedge)
    proj_gemm<<<pgrid, pblk, PROJ_SMEM>>>(xh, xl, wh + 3 * WSZ, wl, bo, out, nullptr, 0, 1);
}

// round 5
// speedup vs baseline: 4.2626x; 1.3542x over previous
#include <cuda_runtime.h>
#include <cuda_fp16.h>
#include <cstdint>

#define B_   2
#define S_   2048
#define D_   2048
#define H_   32
#define DH_  64
#define M_   (B_*S_)    // 4096
#define BH_  (B_*H_)    // 64

// ---------------------------------------------------------------------------
// Scratch (static __device__ arrays: allocation-guard safe)
// ---------------------------------------------------------------------------
__device__ __half g_xh[(size_t)M_*D_];         // X hi (later ctx hi)
__device__ __half g_xl[(size_t)M_*D_];         // X lo (later ctx lo)
__device__ __half g_wh[(size_t)4*D_*D_];       // Wt fp16 [N][K] (4 mats)
__device__ __half g_wl[(size_t)D_*D_];         // Wo lo only (3-term hedge)
__device__ __half g_qh[(size_t)M_*D_];         // Q hi [BH][S][64] (pre-scaled 1/8)
__device__ __half g_ql[(size_t)M_*D_];         // Q lo
__device__ __half g_kh[(size_t)M_*D_];         // K fp16 single [BH][S][64]
__device__ __half g_vth[(size_t)M_*D_];        // V^T fp16 single [BH][64][S]

// ---------------------------------------------------------------------------
// Baseline-PTX primitives (sm_80-level; assemble for plain sm_103 target)
// ---------------------------------------------------------------------------
__device__ __forceinline__ uint32_t smem_u32(const void* p) {
    uint32_t a;
    asm("{ .reg .u64 t; cvta.to.shared.u64 t, %1; cvt.u32.u64 %0, t; }" : "=r"(a) : "l"(p));
    return a;
}
__device__ __forceinline__ void ldsm4(uint32_t* r, uint32_t a) {
    asm volatile("ldmatrix.sync.aligned.m8n8.x4.shared.b16 {%0,%1,%2,%3}, [%4];"
                 : "=r"(r[0]), "=r"(r[1]), "=r"(r[2]), "=r"(r[3]) : "r"(a));
}
__device__ __forceinline__ void mma_f16(float* d, const uint32_t* a,
                                        uint32_t b0, uint32_t b1) {
    asm volatile("mma.sync.aligned.m16n8k16.row.col.f32.f16.f16.f32 "
                 "{%0,%1,%2,%3}, {%4,%5,%6,%7}, {%8,%9}, {%0,%1,%2,%3};"
                 : "+f"(d[0]), "+f"(d[1]), "+f"(d[2]), "+f"(d[3])
                 : "r"(a[0]), "r"(a[1]), "r"(a[2]), "r"(a[3]), "r"(b0), "r"(b1));
}
__device__ __forceinline__ void cp_async16(uint32_t dst, const void* src) {
    asm volatile("cp.async.cg.shared.global [%0], [%1], 16;" :: "r"(dst), "l"(src));
}
#define CP_COMMIT() asm volatile("cp.async.commit_group;" ::: "memory")
#define CP_WAIT1()  asm volatile("cp.async.wait_group 1;"  ::: "memory")
#define CP_WAIT2()  asm volatile("cp.async.wait_group 2;"  ::: "memory")
#define CP_WAIT0()  asm volatile("cp.async.wait_group 0;"  ::: "memory")

__device__ __forceinline__ uint32_t hpack2(float x, float y) {
    __half2 t = __halves2half2(__float2half_rn(x), __float2half_rn(y));
    return *reinterpret_cast<uint32_t*>(&t);
}
__device__ __forceinline__ void hsplit2(float x, float y, uint32_t& hi, uint32_t& lo) {
    __half hx = __float2half_rn(x), hy = __float2half_rn(y);
    __half2 hh = __halves2half2(hx, hy);
    __half2 ll = __halves2half2(__float2half_rn(x - __half2float(hx)),
                                __float2half_rn(y - __half2float(hy)));
    hi = *reinterpret_cast<uint32_t*>(&hh);
    lo = *reinterpret_cast<uint32_t*>(&ll);
}

// ---------------------------------------------------------------------------
// fp16 hi/lo split of fp32 activations
// ---------------------------------------------------------------------------
__global__ void conv_hilo(const float* __restrict__ X,
                          __half* __restrict__ Hi, __half* __restrict__ Lo)
{
    size_t i = (size_t)blockIdx.x * blockDim.x + threadIdx.x;
    float4 v = ((const float4*)X)[i];
    uint32_t h0, l0, h1, l1;
    hsplit2(v.x, v.y, h0, l0);
    hsplit2(v.z, v.w, h1, l1);
    ((uint2*)Hi)[i] = make_uint2(h0, h1);
    ((uint2*)Lo)[i] = make_uint2(l0, l1);
}

// ---------------------------------------------------------------------------
// Transposed fp16 weight: Wt[n][k] = W[k][n]; optional lo residual
// ---------------------------------------------------------------------------
__global__ void conv_wT(const float* __restrict__ W,
                        __half* __restrict__ Th, __half* __restrict__ Tl,
                        int with_lo)
{
    __shared__ float tile[32][33];
    int nx0 = blockIdx.x * 32;
    int ky0 = blockIdx.y * 32;
    #pragma unroll
    for (int i = 0; i < 4; ++i) {
        int kl = threadIdx.y + i * 8;
        tile[kl][threadIdx.x] = W[(size_t)(ky0 + kl) * D_ + nx0 + threadIdx.x];
    }
    __syncthreads();
    #pragma unroll
    for (int i = 0; i < 4; ++i) {
        int nl = threadIdx.y + i * 8;
        float v = tile[threadIdx.x][nl];
        __half h = __float2half_rn(v);
        size_t o = (size_t)(nx0 + nl) * D_ + ky0 + threadIdx.x;
        Th[o] = h;
        if (with_lo) Tl[o] = __float2half_rn(v - __half2float(h));
    }
}

// ---------------------------------------------------------------------------
// Projection GEMM: C[M,N] = (Ah+Al)[M,K] @ B[N,K]^T + bias
// mode 0: fp32 dense out0[M][2048]
// mode 1: fp16 hi/lo split-head, PRE-SCALED by 0.125 (Q)
// mode 2: fp16 single transposed (V^T [BH][64][S])
// mode 3: fp16 single split-head (K)
// ---------------------------------------------------------------------------
#define PROJ_SMEM 131072

__global__ void __launch_bounds__(256, 1) proj_gemm(
    const __half* __restrict__ Ah_g, const __half* __restrict__ Al_g,
    const __half* __restrict__ Bh_g, const __half* __restrict__ Bl_g,
    const float* __restrict__ bias, void* out0, void* out1, int mode, int three)
{
    extern __shared__ char dyn[];
    uint32_t raw = smem_u32(dyn);
    uint32_t st  = (raw + 127u) & ~127u;
    char* stp    = dyn + (st - raw);

    const int tid = threadIdx.x, wid = tid >> 5, lane = tid & 31;
    const int n0 = blockIdx.x * 128, m0 = blockIdx.y * 128;
    const int wm = wid & 1, wn = wid >> 1;
    const int lr = lane & 15;

    uint32_t swk[4];
    #pragma unroll
    for (int kk = 0; kk < 4; ++kk)
        swk[kk] = (uint32_t)((((kk * 2 + (lane >> 4)) ^ (lane & 7)) << 4));

    auto load_chunk = [&](int c, int s) {
        uint32_t sb = st + (uint32_t)s * 65536u;
        int k0 = c * 64;
        #pragma unroll
        for (int t = 0; t < 2; ++t) {
            const __half* src = t ? Al_g : Ah_g;
            uint32_t tb = sb + (uint32_t)t * 16384u;
            #pragma unroll
            for (int j = 0; j < 4; ++j) {
                int q = tid + 256 * j, row = q >> 3, ch = q & 7;
                cp_async16(tb + row * 128 + ((ch ^ (row & 7)) << 4),
                           src + (size_t)(m0 + row) * D_ + k0 + ch * 8);
            }
        }
        #pragma unroll
        for (int j = 0; j < 4; ++j) {
            int q = tid + 256 * j, row = q >> 3, ch = q & 7;
            cp_async16(sb + 32768u + row * 128 + ((ch ^ (row & 7)) << 4),
                       Bh_g + (size_t)(n0 + row) * D_ + k0 + ch * 8);
        }
        if (three) {
            #pragma unroll
            for (int j = 0; j < 4; ++j) {
                int q = tid + 256 * j, row = q >> 3, ch = q & 7;
                cp_async16(sb + 49152u + row * 128 + ((ch ^ (row & 7)) << 4),
                           Bl_g + (size_t)(n0 + row) * D_ + k0 + ch * 8);
            }
        }
        CP_COMMIT();
    };

    float acc[4][4][4] = {};
    load_chunk(0, 0);
    load_chunk(1, 1);

    for (int c = 0; c < 32; ++c) {
        CP_WAIT1();
        __syncthreads();
        uint32_t sb = st + (uint32_t)(c & 1) * 65536u;
        uint32_t tAh = sb, tAl = sb + 16384u, tBh = sb + 32768u, tBl = sb + 49152u;
        #pragma unroll
        for (int kk = 0; kk < 4; ++kk) {
            uint32_t ah[4][4], al[4][4];
            #pragma unroll
            for (int mi = 0; mi < 4; ++mi) {
                uint32_t ro = (uint32_t)((wm * 64 + mi * 16 + lr) * 128);
                ldsm4(ah[mi], tAh + ro + swk[kk]);
                ldsm4(al[mi], tAl + ro + swk[kk]);
            }
            uint32_t bh[4][2], bl[4][2];
            #pragma unroll
            for (int nj = 0; nj < 2; ++nj) {
                uint32_t ro = (uint32_t)((wn * 32 + nj * 16 + lr) * 128);
                uint32_t r4[4];
                ldsm4(r4, tBh + ro + swk[kk]);
                bh[nj*2][0] = r4[0]; bh[nj*2][1] = r4[2];
                bh[nj*2+1][0] = r4[1]; bh[nj*2+1][1] = r4[3];
                if (three) {
                    ldsm4(r4, tBl + ro + swk[kk]);
                    bl[nj*2][0] = r4[0]; bl[nj*2][1] = r4[2];
                    bl[nj*2+1][0] = r4[1]; bl[nj*2+1][1] = r4[3];
                }
            }
            #pragma unroll
            for (int mi = 0; mi < 4; ++mi)
                #pragma unroll
                for (int nb = 0; nb < 4; ++nb) {
                    mma_f16(acc[mi][nb], ah[mi], bh[nb][0], bh[nb][1]);
                    mma_f16(acc[mi][nb], al[mi], bh[nb][0], bh[nb][1]);
                    if (three)
                        mma_f16(acc[mi][nb], ah[mi], bl[nb][0], bl[nb][1]);
                }
        }
        __syncthreads();
        if (c + 2 < 32) load_chunk(c + 2, c & 1);
        else            CP_COMMIT();
    }

    // epilogue via smem fp32 tile (reuses stage memory)
    CP_WAIT0();
    float* ftile = (float*)stp;   // 128 x 132
    #pragma unroll
    for (int mi = 0; mi < 4; ++mi)
        #pragma unroll
        for (int nb = 0; nb < 4; ++nb) {
            int r  = wm * 64 + mi * 16 + (lane >> 2);
            int cc = wn * 32 + nb * 8 + (lane & 3) * 2;
            ftile[r * 132 + cc]           = acc[mi][nb][0];
            ftile[r * 132 + cc + 1]       = acc[mi][nb][1];
            ftile[(r + 8) * 132 + cc]     = acc[mi][nb][2];
            ftile[(r + 8) * 132 + cc + 1] = acc[mi][nb][3];
        }
    __syncthreads();

    if (mode == 2) {
        // V^T single fp16: out[bh][64][S]
        const int lane4 = lane * 4;
        int bb = m0 >> 11;
        int s0 = (m0 & (S_ - 1)) + lane4;
        __half* O0 = (__half*)out0;
        #pragma unroll
        for (int ii = 0; ii < 16; ++ii) {
            int nl = wid * 16 + ii;
            int n  = n0 + nl;
            float bvs = bias[n];
            int h = n >> 6, jj = n & 63;
            float v0 = ftile[(lane4 + 0) * 132 + nl] + bvs;
            float v1 = ftile[(lane4 + 1) * 132 + nl] + bvs;
            float v2 = ftile[(lane4 + 2) * 132 + nl] + bvs;
            float v3 = ftile[(lane4 + 3) * 132 + nl] + bvs;
            size_t base = ((size_t)(bb * H_ + h) * DH_ + jj) * S_ + s0;
            *(uint2*)&O0[base] = make_uint2(hpack2(v0, v1), hpack2(v2, v3));
        }
    } else {
        const int c4 = (tid & 31) * 4;
        float4 bv = *(const float4*)&bias[n0 + c4];
        #pragma unroll
        for (int i = 0; i < 16; ++i) {
            int r = (tid >> 5) + i * 8;
            float4 v = *(float4*)&ftile[r * 132 + c4];
            v.x += bv.x; v.y += bv.y; v.z += bv.z; v.w += bv.w;
            int m = m0 + r;
            if (mode == 0) {
                *(float4*)&((float*)out0)[(size_t)m * D_ + n0 + c4] = v;
            } else {
                int bidx = m >> 11, s = m & (S_ - 1);
                int n = n0 + c4, h = n >> 6, jj = n & 63;
                size_t base = (((size_t)(bidx * H_ + h) * S_) + s) * DH_ + jj;
                if (mode == 1) {
                    // Q: fold in softmax scale 1/sqrt(64) = 0.125 (exact)
                    v.x *= 0.125f; v.y *= 0.125f; v.z *= 0.125f; v.w *= 0.125f;
                    uint32_t h0, l0, h1, l1;
                    hsplit2(v.x, v.y, h0, l0);
                    hsplit2(v.z, v.w, h1, l1);
                    *(uint2*)&((__half*)out0)[base] = make_uint2(h0, h1);
                    *(uint2*)&((__half*)out1)[base] = make_uint2(l0, l1);
                } else { // mode 3: single fp16
                    *(uint2*)&((__half*)out0)[base] =
                        make_uint2(hpack2(v.x, v.y), hpack2(v.z, v.w));
                }
            }
        }
    }
}

// ---------------------------------------------------------------------------
// Fused attention: per CTA = 128 query rows of one (b,h).
// Online softmax, P kept in registers (C-frag -> A-frag identity), PV fused.
// 8 warps: warp w owns query rows m0 + w*16 .. +15.
// ---------------------------------------------------------------------------
#define ATTN_SMEM 98304   // Q hi/lo 32KB + 2 stages x (K 16KB + V^T 16KB)

__global__ void __launch_bounds__(256, 1) attn_fused(
    const __half* __restrict__ Qh, const __half* __restrict__ Ql,
    const __half* __restrict__ Kh, const __half* __restrict__ Vt,
    __half* __restrict__ Ch, __half* __restrict__ Cl)
{
    extern __shared__ char dyn[];
    uint32_t raw = smem_u32(dyn);
    uint32_t st  = (raw + 127u) & ~127u;

    const int tid = threadIdx.x, wid = tid >> 5, lane = tid & 31;
    const int lr  = lane & 15;
    const int bh  = blockIdx.y;
    const int m0  = blockIdx.x * 128;

    uint32_t swk[4];
    #pragma unroll
    for (int kk = 0; kk < 4; ++kk)
        swk[kk] = (uint32_t)((((kk * 2 + (lane >> 4)) ^ (lane & 7)) << 4));

    const __half* Qh_b = Qh + ((size_t)bh * S_ + m0) * DH_;
    const __half* Ql_b = Ql + ((size_t)bh * S_ + m0) * DH_;
    const __half* Kh_b = Kh + (size_t)bh * S_ * DH_;
    const __half* Vt_b = Vt + (size_t)bh * DH_ * S_;

    const uint32_t QH = st, QL = st + 16384u;
    const uint32_t ST0 = st + 32768u;

    // --- load Q tile (own cp.async group) ---
    #pragma unroll
    for (int t = 0; t < 2; ++t) {
        const __half* src = t ? Ql_b : Qh_b;
        uint32_t base = t ? QL : QH;
        #pragma unroll
        for (int j = 0; j < 4; ++j) {
            int q = tid + 256 * j, row = q >> 3, ch = q & 7;
            cp_async16(base + row * 128 + ((ch ^ (row & 7)) << 4),
                       src + (size_t)row * DH_ + ch * 8);
        }
    }
    CP_COMMIT();

    auto load_kv = [&](int i, int s) {
        uint32_t kb = ST0 + (uint32_t)s * 32768u;
        uint32_t vb = kb + 16384u;
        #pragma unroll
        for (int j = 0; j < 4; ++j) {
            int q = tid + 256 * j, row = q >> 3, ch = q & 7;
            cp_async16(kb + row * 128 + ((ch ^ (row & 7)) << 4),
                       Kh_b + (size_t)(i * 128 + row) * DH_ + ch * 8);
        }
        #pragma unroll
        for (int sub = 0; sub < 2; ++sub)
            #pragma unroll
            for (int j = 0; j < 2; ++j) {
                int q = tid + 256 * j, row = q >> 3, ch = q & 7;  // row 0..63
                cp_async16(vb + sub * 8192 + row * 128 + ((ch ^ (row & 7)) << 4),
                           Vt_b + (size_t)row * S_ + i * 128 + sub * 64 + ch * 8);
            }
        CP_COMMIT();
    };
    load_kv(0, 0);
    load_kv(1, 1);

    // wait for Q, then load Q fragments once
    CP_WAIT2();
    __syncthreads();
    uint32_t qah[4][4], qal[4][4];
    #pragma unroll
    for (int kk = 0; kk < 4; ++kk) {
        uint32_t ro = (uint32_t)((wid * 16 + lr) * 128);
        ldsm4(qah[kk], QH + ro + swk[kk]);
        ldsm4(qal[kk], QL + ro + swk[kk]);
    }

    float cAcc[8][4] = {};
    float mA = -1e30f, mB = -1e30f, lA = 0.f, lB = 0.f;

    for (int i = 0; i < 16; ++i) {
        CP_WAIT1();
        __syncthreads();
        uint32_t kb = ST0 + (uint32_t)(i & 1) * 32768u;
        uint32_t vb = kb + 16384u;

        // --- QK^T: scores 16x128 per warp ---
        float sAcc[16][4] = {};
        #pragma unroll
        for (int kk = 0; kk < 4; ++kk) {
            uint32_t bK[16][2];
            #pragma unroll
            for (int g = 0; g < 8; ++g) {
                uint32_t r4[4];
                ldsm4(r4, kb + (uint32_t)((g * 16 + lr) * 128) + swk[kk]);
                bK[2*g][0]   = r4[0]; bK[2*g][1]   = r4[2];
                bK[2*g+1][0] = r4[1]; bK[2*g+1][1] = r4[3];
            }
            #pragma unroll
            for (int nt = 0; nt < 16; ++nt) {
                mma_f16(sAcc[nt], qah[kk], bK[nt][0], bK[nt][1]);
                mma_f16(sAcc[nt], qal[kk], bK[nt][0], bK[nt][1]);
            }
        }

        // --- online softmax (rows A = lane>>2, B = +8) ---
        float rA = -1e30f, rB = -1e30f;
        #pragma unroll
        for (int nt = 0; nt < 16; ++nt) {
            rA = fmaxf(rA, fmaxf(sAcc[nt][0], sAcc[nt][1]));
            rB = fmaxf(rB, fmaxf(sAcc[nt][2], sAcc[nt][3]));
        }
        rA = fmaxf(rA, __shfl_xor_sync(0xffffffffu, rA, 1));
        rA = fmaxf(rA, __shfl_xor_sync(0xffffffffu, rA, 2));
        rB = fmaxf(rB, __shfl_xor_sync(0xffffffffu, rB, 1));
        rB = fmaxf(rB, __shfl_xor_sync(0xffffffffu, rB, 2));
        float mnA = fmaxf(mA, rA), mnB = fmaxf(mB, rB);
        float esA = __expf(mA - mnA), esB = __expf(mB - mnB);
        mA = mnA; mB = mnB;

        float suA = 0.f, suB = 0.f;
        #pragma unroll
        for (int nt = 0; nt < 16; ++nt) {
            sAcc[nt][0] = __expf(sAcc[nt][0] - mA);
            sAcc[nt][1] = __expf(sAcc[nt][1] - mA);
            sAcc[nt][2] = __expf(sAcc[nt][2] - mB);
            sAcc[nt][3] = __expf(sAcc[nt][3] - mB);
            suA += sAcc[nt][0] + sAcc[nt][1];
            suB += sAcc[nt][2] + sAcc[nt][3];
        }
        suA += __shfl_xor_sync(0xffffffffu, suA, 1);
        suA += __shfl_xor_sync(0xffffffffu, suA, 2);
        suB += __shfl_xor_sync(0xffffffffu, suB, 1);
        suB += __shfl_xor_sync(0xffffffffu, suB, 2);
        lA = lA * esA + suA;
        lB = lB * esB + suB;
        #pragma unroll
        for (int nb = 0; nb < 8; ++nb) {
            cAcc[nb][0] *= esA; cAcc[nb][1] *= esA;
            cAcc[nb][2] *= esB; cAcc[nb][3] *= esB;
        }

        // --- PV: C-frag -> A-frag identity, B from V^T smem ---
        #pragma unroll
        for (int kt = 0; kt < 8; ++kt) {
            uint32_t pa[4];
            pa[0] = hpack2(sAcc[2*kt][0],   sAcc[2*kt][1]);
            pa[1] = hpack2(sAcc[2*kt][2],   sAcc[2*kt][3]);
            pa[2] = hpack2(sAcc[2*kt+1][0], sAcc[2*kt+1][1]);
            pa[3] = hpack2(sAcc[2*kt+1][2], sAcc[2*kt+1][3]);
            uint32_t vsb = vb + (uint32_t)(kt >> 2) * 8192u;
            int kkv = kt & 3;
            uint32_t bV[8][2];
            #pragma unroll
            for (int g = 0; g < 4; ++g) {
                uint32_t r4[4];
                ldsm4(r4, vsb + (uint32_t)((g * 16 + lr) * 128) + swk[kkv]);
                bV[2*g][0]   = r4[0]; bV[2*g][1]   = r4[2];
                bV[2*g+1][0] = r4[1]; bV[2*g+1][1] = r4[3];
            }
            #pragma unroll
            for (int nb = 0; nb < 8; ++nb)
                mma_f16(cAcc[nb], pa, bV[nb][0], bV[nb][1]);
        }

        __syncthreads();
        if (i + 2 < 16) load_kv(i + 2, i & 1);
        else            CP_COMMIT();
    }

    // --- epilogue: normalize, split hi/lo, scatter into ctx [M][2048] ---
    const int b = bh >> 5, h = bh & 31;
    float iA = 1.0f / lA, iB = 1.0f / lB;
    int rA_ = m0 + wid * 16 + (lane >> 2);
    int rB_ = rA_ + 8;
    #pragma unroll
    for (int nb = 0; nb < 8; ++nb) {
        int c = nb * 8 + (lane & 3) * 2;
        size_t ia = ((size_t)(b * S_) + rA_) * D_ + h * DH_ + c;
        size_t ib = ((size_t)(b * S_) + rB_) * D_ + h * DH_ + c;
        uint32_t hw, lw;
        hsplit2(cAcc[nb][0] * iA, cAcc[nb][1] * iA, hw, lw);
        *(uint32_t*)&Ch[ia] = hw; *(uint32_t*)&Cl[ia] = lw;
        hsplit2(cAcc[nb][2] * iB, cAcc[nb][3] * iB, hw, lw);
        *(uint32_t*)&Ch[ib] = hw; *(uint32_t*)&Cl[ib] = lw;
    }
}

// ---------------------------------------------------------------------------
extern "C" void kernel_launch(void* const* d_in, const int* in_sizes, int n_in,
                              void* d_out, int out_size)
{
    const float* X  = (const float*)d_in[0];
    const float* Wq = (const float*)d_in[1];
    const float* bq = (const float*)d_in[2];
    const float* Wk = (const float*)d_in[3];
    const float* bk = (const float*)d_in[4];
    const float* Wv = (const float*)d_in[5];
    const float* bv = (const float*)d_in[6];
    const float* Wo = (const float*)d_in[7];
    const float* bo = (const float*)d_in[8];
    float* out = (float*)d_out;

    __half *xh, *xl, *wh, *wl, *qh, *ql, *kh, *vth;
    cudaGetSymbolAddress((void**)&xh,  g_xh);
    cudaGetSymbolAddress((void**)&xl,  g_xl);
    cudaGetSymbolAddress((void**)&wh,  g_wh);
    cudaGetSymbolAddress((void**)&wl,  g_wl);
    cudaGetSymbolAddress((void**)&qh,  g_qh);
    cudaGetSymbolAddress((void**)&ql,  g_ql);
    cudaGetSymbolAddress((void**)&kh,  g_kh);
    cudaGetSymbolAddress((void**)&vth, g_vth);

    static bool attr_done = false;
    if (!attr_done) {
        cudaFuncSetAttribute(proj_gemm,  cudaFuncAttributeMaxDynamicSharedMemorySize, PROJ_SMEM);
        cudaFuncSetAttribute(attn_fused, cudaFuncAttributeMaxDynamicSharedMemorySize, ATTN_SMEM);
        attr_done = true;
    }

    const size_t WSZ = (size_t)D_ * D_;

    // conversions
    conv_hilo<<<(M_ * (size_t)D_) / 1024, 256>>>(X, xh, xl);
    dim3 tblk(32, 8), tgrid(D_ / 32, D_ / 32);
    conv_wT<<<tgrid, tblk>>>(Wq, wh + 0 * WSZ, nullptr, 0);
    conv_wT<<<tgrid, tblk>>>(Wk, wh + 1 * WSZ, nullptr, 0);
    conv_wT<<<tgrid, tblk>>>(Wv, wh + 2 * WSZ, nullptr, 0);
    conv_wT<<<tgrid, tblk>>>(Wo, wh + 3 * WSZ, wl, 1);      // hi/lo for out-proj

    // projections (2-term fp16)
    dim3 pblk(256), pgrid(D_ / 128, M_ / 128);   // (16, 32)
    proj_gemm<<<pgrid, pblk, PROJ_SMEM>>>(xh, xl, wh + 0 * WSZ, nullptr, bq, qh, ql, 1, 0);
    proj_gemm<<<pgrid, pblk, PROJ_SMEM>>>(xh, xl, wh + 1 * WSZ, nullptr, bk, kh, nullptr, 3, 0);
    proj_gemm<<<pgrid, pblk, PROJ_SMEM>>>(xh, xl, wh + 2 * WSZ, nullptr, bv, vth, nullptr, 2, 0);

    // fused attention: ctx (hi/lo) -> xh/xl
    dim3 agrid(S_ / 128, BH_);                   // (16, 64)
    attn_fused<<<agrid, pblk, ATTN_SMEM>>>(qh, ql, kh, vth, xh, xl);

    // output projection (3-term hedge)
    proj_gemm<<<pgrid, pblk, PROJ_SMEM>>>(xh, xl, wh + 3 * WSZ, wl, bo, out, nullptr, 0, 1);
}

// round 6
// speedup vs baseline: 5.4806x; 1.2857x over previous
#include <cuda_runtime.h>
#include <cuda_fp16.h>
#include <cstdint>

#define B_   2
#define S_   2048
#define D_   2048
#define H_   32
#define DH_  64
#define M_   (B_*S_)    // 4096
#define BH_  (B_*H_)    // 64

// ---------------------------------------------------------------------------
// Scratch (static __device__ arrays: allocation-guard safe)
// ---------------------------------------------------------------------------
__device__ __half g_xh[(size_t)M_*D_];         // X hi (later ctx hi)
__device__ __half g_xl[(size_t)M_*D_];         // X lo (later ctx lo)
__device__ __half g_wh[(size_t)4*D_*D_];       // Wt fp16 [N][K] (4 mats)
__device__ __half g_qh[(size_t)M_*D_];         // Q hi [BH][S][64] (pre-scaled 1/8)
__device__ __half g_ql[(size_t)M_*D_];         // Q lo
__device__ __half g_kh[(size_t)M_*D_];         // K fp16 single [BH][S][64]
__device__ __half g_vth[(size_t)M_*D_];        // V^T fp16 single [BH][64][S]

// ---------------------------------------------------------------------------
// Baseline-PTX primitives (sm_80-level; assemble for plain sm_103 target)
// ---------------------------------------------------------------------------
__device__ __forceinline__ uint32_t smem_u32(const void* p) {
    uint32_t a;
    asm("{ .reg .u64 t; cvta.to.shared.u64 t, %1; cvt.u32.u64 %0, t; }" : "=r"(a) : "l"(p));
    return a;
}
__device__ __forceinline__ void ldsm4(uint32_t* r, uint32_t a) {
    asm volatile("ldmatrix.sync.aligned.m8n8.x4.shared.b16 {%0,%1,%2,%3}, [%4];"
                 : "=r"(r[0]), "=r"(r[1]), "=r"(r[2]), "=r"(r[3]) : "r"(a));
}
__device__ __forceinline__ void mma_f16(float* d, const uint32_t* a,
                                        uint32_t b0, uint32_t b1) {
    asm volatile("mma.sync.aligned.m16n8k16.row.col.f32.f16.f16.f32 "
                 "{%0,%1,%2,%3}, {%4,%5,%6,%7}, {%8,%9}, {%0,%1,%2,%3};"
                 : "+f"(d[0]), "+f"(d[1]), "+f"(d[2]), "+f"(d[3])
                 : "r"(a[0]), "r"(a[1]), "r"(a[2]), "r"(a[3]), "r"(b0), "r"(b1));
}
__device__ __forceinline__ void cp_async16(uint32_t dst, const void* src) {
    asm volatile("cp.async.cg.shared.global [%0], [%1], 16;" :: "r"(dst), "l"(src));
}
#define CP_COMMIT() asm volatile("cp.async.commit_group;" ::: "memory")
#define CP_WAIT1()  asm volatile("cp.async.wait_group 1;"  ::: "memory")
#define CP_WAIT2()  asm volatile("cp.async.wait_group 2;"  ::: "memory")
#define CP_WAIT0()  asm volatile("cp.async.wait_group 0;"  ::: "memory")

__device__ __forceinline__ uint32_t hpack2(float x, float y) {
    __half2 t = __halves2half2(__float2half_rn(x), __float2half_rn(y));
    return *reinterpret_cast<uint32_t*>(&t);
}
__device__ __forceinline__ void hsplit2(float x, float y, uint32_t& hi, uint32_t& lo) {
    __half hx = __float2half_rn(x), hy = __float2half_rn(y);
    __half2 hh = __halves2half2(hx, hy);
    __half2 ll = __halves2half2(__float2half_rn(x - __half2float(hx)),
                                __float2half_rn(y - __half2float(hy)));
    hi = *reinterpret_cast<uint32_t*>(&hh);
    lo = *reinterpret_cast<uint32_t*>(&ll);
}

// ---------------------------------------------------------------------------
// fp16 hi/lo split of fp32 activations
// ---------------------------------------------------------------------------
__global__ void conv_hilo(const float* __restrict__ X,
                          __half* __restrict__ Hi, __half* __restrict__ Lo)
{
    size_t i = (size_t)blockIdx.x * blockDim.x + threadIdx.x;
    float4 v = ((const float4*)X)[i];
    uint32_t h0, l0, h1, l1;
    hsplit2(v.x, v.y, h0, l0);
    hsplit2(v.z, v.w, h1, l1);
    ((uint2*)Hi)[i] = make_uint2(h0, h1);
    ((uint2*)Lo)[i] = make_uint2(l0, l1);
}

// ---------------------------------------------------------------------------
// Transposed fp16 weight: Wt[n][k] = W[k][n]
// ---------------------------------------------------------------------------
__global__ void conv_wT(const float* __restrict__ W, __half* __restrict__ Th)
{
    __shared__ float tile[32][33];
    int nx0 = blockIdx.x * 32;
    int ky0 = blockIdx.y * 32;
    #pragma unroll
    for (int i = 0; i < 4; ++i) {
        int kl = threadIdx.y + i * 8;
        tile[kl][threadIdx.x] = W[(size_t)(ky0 + kl) * D_ + nx0 + threadIdx.x];
    }
    __syncthreads();
    #pragma unroll
    for (int i = 0; i < 4; ++i) {
        int nl = threadIdx.y + i * 8;
        Th[(size_t)(nx0 + nl) * D_ + ky0 + threadIdx.x] =
            __float2half_rn(tile[threadIdx.x][nl]);
    }
}

// ---------------------------------------------------------------------------
// Projection GEMM: C[M,N] = A[M,K] @ B[N,K]^T + bias
// A = fp16 hi (+ optional lo when na2=1, 2 MMA terms). B = single fp16.
// CTA 128x128, K-chunk 64, 2-stage cp.async, 8 warps (warp 64x32).
// mode 0: fp32 dense out0[M][2048]
// mode 1: fp16 hi/lo split-head, PRE-SCALED by 0.125 (Q)
// mode 2: fp16 single transposed (V^T [BH][64][S])
// mode 3: fp16 single split-head (K)
// ---------------------------------------------------------------------------
#define STAGE_STRIDE 49152u
#define PROJ_SMEM (2 * 49152 + 128)

__global__ void __launch_bounds__(256, 1) proj_gemm(
    const __half* __restrict__ Ah_g, const __half* __restrict__ Al_g,
    const __half* __restrict__ Bh_g,
    const float* __restrict__ bias, void* out0, void* out1, int mode, int na2)
{
    extern __shared__ char dyn[];
    uint32_t raw = smem_u32(dyn);
    uint32_t st  = (raw + 127u) & ~127u;
    char* stp    = dyn + (st - raw);

    const int tid = threadIdx.x, wid = tid >> 5, lane = tid & 31;
    const int n0 = blockIdx.x * 128, m0 = blockIdx.y * 128;
    const int wm = wid & 1, wn = wid >> 1;
    const int lr = lane & 15;

    uint32_t swk[4];
    #pragma unroll
    for (int kk = 0; kk < 4; ++kk)
        swk[kk] = (uint32_t)((((kk * 2 + (lane >> 4)) ^ (lane & 7)) << 4));

    auto load_chunk = [&](int c, int s) {
        uint32_t sb = st + (uint32_t)s * STAGE_STRIDE;
        int k0 = c * 64;
        #pragma unroll
        for (int j = 0; j < 4; ++j) {
            int q = tid + 256 * j, row = q >> 3, ch = q & 7;
            cp_async16(sb + row * 128 + ((ch ^ (row & 7)) << 4),
                       Ah_g + (size_t)(m0 + row) * D_ + k0 + ch * 8);
        }
        if (na2) {
            #pragma unroll
            for (int j = 0; j < 4; ++j) {
                int q = tid + 256 * j, row = q >> 3, ch = q & 7;
                cp_async16(sb + 16384u + row * 128 + ((ch ^ (row & 7)) << 4),
                           Al_g + (size_t)(m0 + row) * D_ + k0 + ch * 8);
            }
        }
        #pragma unroll
        for (int j = 0; j < 4; ++j) {
            int q = tid + 256 * j, row = q >> 3, ch = q & 7;
            cp_async16(sb + 32768u + row * 128 + ((ch ^ (row & 7)) << 4),
                       Bh_g + (size_t)(n0 + row) * D_ + k0 + ch * 8);
        }
        CP_COMMIT();
    };

    float acc[4][4][4] = {};
    load_chunk(0, 0);
    load_chunk(1, 1);

    for (int c = 0; c < 32; ++c) {
        CP_WAIT1();
        __syncthreads();
        uint32_t sb = st + (uint32_t)(c & 1) * STAGE_STRIDE;
        uint32_t tAh = sb, tAl = sb + 16384u, tBh = sb + 32768u;
        #pragma unroll
        for (int kk = 0; kk < 4; ++kk) {
            uint32_t ah[4][4], al[4][4];
            #pragma unroll
            for (int mi = 0; mi < 4; ++mi) {
                uint32_t ro = (uint32_t)((wm * 64 + mi * 16 + lr) * 128);
                ldsm4(ah[mi], tAh + ro + swk[kk]);
                if (na2) ldsm4(al[mi], tAl + ro + swk[kk]);
            }
            uint32_t bh[4][2];
            #pragma unroll
            for (int nj = 0; nj < 2; ++nj) {
                uint32_t ro = (uint32_t)((wn * 32 + nj * 16 + lr) * 128);
                uint32_t r4[4];
                ldsm4(r4, tBh + ro + swk[kk]);
                bh[nj*2][0] = r4[0]; bh[nj*2][1] = r4[2];
                bh[nj*2+1][0] = r4[1]; bh[nj*2+1][1] = r4[3];
            }
            #pragma unroll
            for (int mi = 0; mi < 4; ++mi)
                #pragma unroll
                for (int nb = 0; nb < 4; ++nb) {
                    mma_f16(acc[mi][nb], ah[mi], bh[nb][0], bh[nb][1]);
                    if (na2)
                        mma_f16(acc[mi][nb], al[mi], bh[nb][0], bh[nb][1]);
                }
        }
        __syncthreads();
        if (c + 2 < 32) load_chunk(c + 2, c & 1);
        else            CP_COMMIT();
    }

    // epilogue via smem fp32 tile (reuses stage memory)
    CP_WAIT0();
    float* ftile = (float*)stp;   // 128 x 132
    #pragma unroll
    for (int mi = 0; mi < 4; ++mi)
        #pragma unroll
        for (int nb = 0; nb < 4; ++nb) {
            int r  = wm * 64 + mi * 16 + (lane >> 2);
            int cc = wn * 32 + nb * 8 + (lane & 3) * 2;
            ftile[r * 132 + cc]           = acc[mi][nb][0];
            ftile[r * 132 + cc + 1]       = acc[mi][nb][1];
            ftile[(r + 8) * 132 + cc]     = acc[mi][nb][2];
            ftile[(r + 8) * 132 + cc + 1] = acc[mi][nb][3];
        }
    __syncthreads();

    if (mode == 2) {
        // V^T single fp16: out[bh][64][S]
        const int lane4 = lane * 4;
        int bb = m0 >> 11;
        int s0 = (m0 & (S_ - 1)) + lane4;
        __half* O0 = (__half*)out0;
        #pragma unroll
        for (int ii = 0; ii < 16; ++ii) {
            int nl = wid * 16 + ii;
            int n  = n0 + nl;
            float bvs = bias[n];
            int h = n >> 6, jj = n & 63;
            float v0 = ftile[(lane4 + 0) * 132 + nl] + bvs;
            float v1 = ftile[(lane4 + 1) * 132 + nl] + bvs;
            float v2 = ftile[(lane4 + 2) * 132 + nl] + bvs;
            float v3 = ftile[(lane4 + 3) * 132 + nl] + bvs;
            size_t base = ((size_t)(bb * H_ + h) * DH_ + jj) * S_ + s0;
            *(uint2*)&O0[base] = make_uint2(hpack2(v0, v1), hpack2(v2, v3));
        }
    } else {
        const int c4 = (tid & 31) * 4;
        float4 bv = *(const float4*)&bias[n0 + c4];
        #pragma unroll
        for (int i = 0; i < 16; ++i) {
            int r = (tid >> 5) + i * 8;
            float4 v = *(float4*)&ftile[r * 132 + c4];
            v.x += bv.x; v.y += bv.y; v.z += bv.z; v.w += bv.w;
            int m = m0 + r;
            if (mode == 0) {
                *(float4*)&((float*)out0)[(size_t)m * D_ + n0 + c4] = v;
            } else {
                int bidx = m >> 11, s = m & (S_ - 1);
                int n = n0 + c4, h = n >> 6, jj = n & 63;
                size_t base = (((size_t)(bidx * H_ + h) * S_) + s) * DH_ + jj;
                if (mode == 1) {
                    // Q: fold in softmax scale 1/sqrt(64) = 0.125 (exact)
                    v.x *= 0.125f; v.y *= 0.125f; v.z *= 0.125f; v.w *= 0.125f;
                    uint32_t h0, l0, h1, l1;
                    hsplit2(v.x, v.y, h0, l0);
                    hsplit2(v.z, v.w, h1, l1);
                    *(uint2*)&((__half*)out0)[base] = make_uint2(h0, h1);
                    *(uint2*)&((__half*)out1)[base] = make_uint2(l0, l1);
                } else { // mode 3: single fp16
                    *(uint2*)&((__half*)out0)[base] =
                        make_uint2(hpack2(v.x, v.y), hpack2(v.z, v.w));
                }
            }
        }
    }
}

// ---------------------------------------------------------------------------
// Fused attention: per CTA = 128 query rows of one (b,h).
// Online softmax, P kept in registers (C-frag -> A-frag identity), PV fused.
// ---------------------------------------------------------------------------
#define ATTN_SMEM 98304   // Q hi/lo 32KB + 2 stages x (K 16KB + V^T 16KB)

__global__ void __launch_bounds__(256, 1) attn_fused(
    const __half* __restrict__ Qh, const __half* __restrict__ Ql,
    const __half* __restrict__ Kh, const __half* __restrict__ Vt,
    __half* __restrict__ Ch, __half* __restrict__ Cl)
{
    extern __shared__ char dyn[];
    uint32_t raw = smem_u32(dyn);
    uint32_t st  = (raw + 127u) & ~127u;

    const int tid = threadIdx.x, wid = tid >> 5, lane = tid & 31;
    const int lr  = lane & 15;
    const int bh  = blockIdx.y;
    const int m0  = blockIdx.x * 128;

    uint32_t swk[4];
    #pragma unroll
    for (int kk = 0; kk < 4; ++kk)
        swk[kk] = (uint32_t)((((kk * 2 + (lane >> 4)) ^ (lane & 7)) << 4));

    const __half* Qh_b = Qh + ((size_t)bh * S_ + m0) * DH_;
    const __half* Ql_b = Ql + ((size_t)bh * S_ + m0) * DH_;
    const __half* Kh_b = Kh + (size_t)bh * S_ * DH_;
    const __half* Vt_b = Vt + (size_t)bh * DH_ * S_;

    const uint32_t QH = st, QL = st + 16384u;
    const uint32_t ST0 = st + 32768u;

    #pragma unroll
    for (int t = 0; t < 2; ++t) {
        const __half* src = t ? Ql_b : Qh_b;
        uint32_t base = t ? QL : QH;
        #pragma unroll
        for (int j = 0; j < 4; ++j) {
            int q = tid + 256 * j, row = q >> 3, ch = q & 7;
            cp_async16(base + row * 128 + ((ch ^ (row & 7)) << 4),
                       src + (size_t)row * DH_ + ch * 8);
        }
    }
    CP_COMMIT();

    auto load_kv = [&](int i, int s) {
        uint32_t kb = ST0 + (uint32_t)s * 32768u;
        uint32_t vb = kb + 16384u;
        #pragma unroll
        for (int j = 0; j < 4; ++j) {
            int q = tid + 256 * j, row = q >> 3, ch = q & 7;
            cp_async16(kb + row * 128 + ((ch ^ (row & 7)) << 4),
                       Kh_b + (size_t)(i * 128 + row) * DH_ + ch * 8);
        }
        #pragma unroll
        for (int sub = 0; sub < 2; ++sub)
            #pragma unroll
            for (int j = 0; j < 2; ++j) {
                int q = tid + 256 * j, row = q >> 3, ch = q & 7;  // row 0..63
                cp_async16(vb + sub * 8192 + row * 128 + ((ch ^ (row & 7)) << 4),
                           Vt_b + (size_t)row * S_ + i * 128 + sub * 64 + ch * 8);
            }
        CP_COMMIT();
    };
    load_kv(0, 0);
    load_kv(1, 1);

    CP_WAIT2();
    __syncthreads();
    uint32_t qah[4][4], qal[4][4];
    #pragma unroll
    for (int kk = 0; kk < 4; ++kk) {
        uint32_t ro = (uint32_t)((wid * 16 + lr) * 128);
        ldsm4(qah[kk], QH + ro + swk[kk]);
        ldsm4(qal[kk], QL + ro + swk[kk]);
    }

    float cAcc[8][4] = {};
    float mA = -1e30f, mB = -1e30f, lA = 0.f, lB = 0.f;

    for (int i = 0; i < 16; ++i) {
        CP_WAIT1();
        __syncthreads();
        uint32_t kb = ST0 + (uint32_t)(i & 1) * 32768u;
        uint32_t vb = kb + 16384u;

        float sAcc[16][4] = {};
        #pragma unroll
        for (int kk = 0; kk < 4; ++kk) {
            uint32_t bK[16][2];
            #pragma unroll
            for (int g = 0; g < 8; ++g) {
                uint32_t r4[4];
                ldsm4(r4, kb + (uint32_t)((g * 16 + lr) * 128) + swk[kk]);
                bK[2*g][0]   = r4[0]; bK[2*g][1]   = r4[2];
                bK[2*g+1][0] = r4[1]; bK[2*g+1][1] = r4[3];
            }
            #pragma unroll
            for (int nt = 0; nt < 16; ++nt) {
                mma_f16(sAcc[nt], qah[kk], bK[nt][0], bK[nt][1]);
                mma_f16(sAcc[nt], qal[kk], bK[nt][0], bK[nt][1]);
            }
        }

        float rA = -1e30f, rB = -1e30f;
        #pragma unroll
        for (int nt = 0; nt < 16; ++nt) {
            rA = fmaxf(rA, fmaxf(sAcc[nt][0], sAcc[nt][1]));
            rB = fmaxf(rB, fmaxf(sAcc[nt][2], sAcc[nt][3]));
        }
        rA = fmaxf(rA, __shfl_xor_sync(0xffffffffu, rA, 1));
        rA = fmaxf(rA, __shfl_xor_sync(0xffffffffu, rA, 2));
        rB = fmaxf(rB, __shfl_xor_sync(0xffffffffu, rB, 1));
        rB = fmaxf(rB, __shfl_xor_sync(0xffffffffu, rB, 2));
        float mnA = fmaxf(mA, rA), mnB = fmaxf(mB, rB);
        float esA = __expf(mA - mnA), esB = __expf(mB - mnB);
        mA = mnA; mB = mnB;

        float suA = 0.f, suB = 0.f;
        #pragma unroll
        for (int nt = 0; nt < 16; ++nt) {
            sAcc[nt][0] = __expf(sAcc[nt][0] - mA);
            sAcc[nt][1] = __expf(sAcc[nt][1] - mA);
            sAcc[nt][2] = __expf(sAcc[nt][2] - mB);
            sAcc[nt][3] = __expf(sAcc[nt][3] - mB);
            suA += sAcc[nt][0] + sAcc[nt][1];
            suB += sAcc[nt][2] + sAcc[nt][3];
        }
        suA += __shfl_xor_sync(0xffffffffu, suA, 1);
        suA += __shfl_xor_sync(0xffffffffu, suA, 2);
        suB += __shfl_xor_sync(0xffffffffu, suB, 1);
        suB += __shfl_xor_sync(0xffffffffu, suB, 2);
        lA = lA * esA + suA;
        lB = lB * esB + suB;
        #pragma unroll
        for (int nb = 0; nb < 8; ++nb) {
            cAcc[nb][0] *= esA; cAcc[nb][1] *= esA;
            cAcc[nb][2] *= esB; cAcc[nb][3] *= esB;
        }

        #pragma unroll
        for (int kt = 0; kt < 8; ++kt) {
            uint32_t pa[4];
            pa[0] = hpack2(sAcc[2*kt][0],   sAcc[2*kt][1]);
            pa[1] = hpack2(sAcc[2*kt][2],   sAcc[2*kt][3]);
            pa[2] = hpack2(sAcc[2*kt+1][0], sAcc[2*kt+1][1]);
            pa[3] = hpack2(sAcc[2*kt+1][2], sAcc[2*kt+1][3]);
            uint32_t vsb = vb + (uint32_t)(kt >> 2) * 8192u;
            int kkv = kt & 3;
            uint32_t bV[8][2];
            #pragma unroll
            for (int g = 0; g < 4; ++g) {
                uint32_t r4[4];
                ldsm4(r4, vsb + (uint32_t)((g * 16 + lr) * 128) + swk[kkv]);
                bV[2*g][0]   = r4[0]; bV[2*g][1]   = r4[2];
                bV[2*g+1][0] = r4[1]; bV[2*g+1][1] = r4[3];
            }
            #pragma unroll
            for (int nb = 0; nb < 8; ++nb)
                mma_f16(cAcc[nb], pa, bV[nb][0], bV[nb][1]);
        }

        __syncthreads();
        if (i + 2 < 16) load_kv(i + 2, i & 1);
        else            CP_COMMIT();
    }

    const int b = bh >> 5, h = bh & 31;
    float iA = 1.0f / lA, iB = 1.0f / lB;
    int rA_ = m0 + wid * 16 + (lane >> 2);
    int rB_ = rA_ + 8;
    #pragma unroll
    for (int nb = 0; nb < 8; ++nb) {
        int c = nb * 8 + (lane & 3) * 2;
        size_t ia = ((size_t)(b * S_) + rA_) * D_ + h * DH_ + c;
        size_t ib = ((size_t)(b * S_) + rB_) * D_ + h * DH_ + c;
        uint32_t hw, lw;
        hsplit2(cAcc[nb][0] * iA, cAcc[nb][1] * iA, hw, lw);
        *(uint32_t*)&Ch[ia] = hw; *(uint32_t*)&Cl[ia] = lw;
        hsplit2(cAcc[nb][2] * iB, cAcc[nb][3] * iB, hw, lw);
        *(uint32_t*)&Ch[ib] = hw; *(uint32_t*)&Cl[ib] = lw;
    }
}

// ---------------------------------------------------------------------------
extern "C" void kernel_launch(void* const* d_in, const int* in_sizes, int n_in,
                              void* d_out, int out_size)
{
    const float* X  = (const float*)d_in[0];
    const float* Wq = (const float*)d_in[1];
    const float* bq = (const float*)d_in[2];
    const float* Wk = (const float*)d_in[3];
    const float* bk = (const float*)d_in[4];
    const float* Wv = (const float*)d_in[5];
    const float* bv = (const float*)d_in[6];
    const float* Wo = (const float*)d_in[7];
    const float* bo = (const float*)d_in[8];
    float* out = (float*)d_out;

    __half *xh, *xl, *wh, *qh, *ql, *kh, *vth;
    cudaGetSymbolAddress((void**)&xh,  g_xh);
    cudaGetSymbolAddress((void**)&xl,  g_xl);
    cudaGetSymbolAddress((void**)&wh,  g_wh);
    cudaGetSymbolAddress((void**)&qh,  g_qh);
    cudaGetSymbolAddress((void**)&ql,  g_ql);
    cudaGetSymbolAddress((void**)&kh,  g_kh);
    cudaGetSymbolAddress((void**)&vth, g_vth);

    static bool attr_done = false;
    if (!attr_done) {
        cudaFuncSetAttribute(proj_gemm,  cudaFuncAttributeMaxDynamicSharedMemorySize, PROJ_SMEM);
        cudaFuncSetAttribute(attn_fused, cudaFuncAttributeMaxDynamicSharedMemorySize, ATTN_SMEM);
        attr_done = true;
    }

    const size_t WSZ = (size_t)D_ * D_;

    // conversions
    conv_hilo<<<(M_ * (size_t)D_) / 1024, 256>>>(X, xh, xl);
    dim3 tblk(32, 8), tgrid(D_ / 32, D_ / 32);
    conv_wT<<<tgrid, tblk>>>(Wq, wh + 0 * WSZ);
    conv_wT<<<tgrid, tblk>>>(Wk, wh + 1 * WSZ);
    conv_wT<<<tgrid, tblk>>>(Wv, wh + 2 * WSZ);
    conv_wT<<<tgrid, tblk>>>(Wo, wh + 3 * WSZ);

    // projections
    dim3 pblk(256), pgrid(D_ / 128, M_ / 128);   // (16, 32)
    // Q: 2-term A (feeds exp-amplified score path)
    proj_gemm<<<pgrid, pblk, PROJ_SMEM>>>(xh, xl, wh + 0 * WSZ, bq, qh, ql, 1, 1);
    // K, V: 1-term A (output storage quant dominates anyway)
    proj_gemm<<<pgrid, pblk, PROJ_SMEM>>>(xh, xl, wh + 1 * WSZ, bk, kh, nullptr, 3, 0);
    proj_gemm<<<pgrid, pblk, PROJ_SMEM>>>(xh, xl, wh + 2 * WSZ, bv, vth, nullptr, 2, 0);

    // fused attention: ctx (hi/lo) -> xh/xl
    dim3 agrid(S_ / 128, BH_);                   // (16, 64)
    attn_fused<<<agrid, pblk, ATTN_SMEM>>>(qh, ql, kh, vth, xh, xl);

    // output projection: 2-term A, single-fp16 Wo
    proj_gemm<<<pgrid, pblk, PROJ_SMEM>>>(xh, xl, wh + 3 * WSZ, bo, out, nullptr, 0, 1);
}

// round 7
// speedup vs baseline: 9.1682x; 1.6729x over previous
#include <cuda_runtime.h>
#include <cuda_fp16.h>
#include <cstdint>

#define B_   2
#define S_   2048
#define D_   2048
#define H_   32
#define DH_  64
#define M_   (B_*S_)    // 4096
#define BH_  (B_*H_)    // 64

// ---------------------------------------------------------------------------
// Scratch (static __device__ arrays: allocation-guard safe)
// ---------------------------------------------------------------------------
__device__ __half g_xh[(size_t)M_*D_];         // X fp16 (later ctx fp16)
__device__ __half g_wh[(size_t)4*D_*D_];       // Wt fp16 [N][K] (4 mats)
__device__ __half g_qh[(size_t)M_*D_];         // Q fp16 [BH][S][64] (pre-scaled 1/8)
__device__ __half g_kh[(size_t)M_*D_];         // K fp16 [BH][S][64]
__device__ __half g_vth[(size_t)M_*D_];        // V^T fp16 [BH][64][S]

// ---------------------------------------------------------------------------
// Baseline-PTX primitives (sm_80-level; assemble for plain sm_103 target)
// ---------------------------------------------------------------------------
__device__ __forceinline__ uint32_t smem_u32(const void* p) {
    uint32_t a;
    asm("{ .reg .u64 t; cvta.to.shared.u64 t, %1; cvt.u32.u64 %0, t; }" : "=r"(a) : "l"(p));
    return a;
}
__device__ __forceinline__ void ldsm4(uint32_t* r, uint32_t a) {
    asm volatile("ldmatrix.sync.aligned.m8n8.x4.shared.b16 {%0,%1,%2,%3}, [%4];"
                 : "=r"(r[0]), "=r"(r[1]), "=r"(r[2]), "=r"(r[3]) : "r"(a));
}
__device__ __forceinline__ void mma_f16(float* d, const uint32_t* a,
                                        uint32_t b0, uint32_t b1) {
    asm volatile("mma.sync.aligned.m16n8k16.row.col.f32.f16.f16.f32 "
                 "{%0,%1,%2,%3}, {%4,%5,%6,%7}, {%8,%9}, {%0,%1,%2,%3};"
                 : "+f"(d[0]), "+f"(d[1]), "+f"(d[2]), "+f"(d[3])
                 : "r"(a[0]), "r"(a[1]), "r"(a[2]), "r"(a[3]), "r"(b0), "r"(b1));
}
__device__ __forceinline__ void cp_async16(uint32_t dst, const void* src) {
    asm volatile("cp.async.cg.shared.global [%0], [%1], 16;" :: "r"(dst), "l"(src));
}
#define CP_COMMIT() asm volatile("cp.async.commit_group;" ::: "memory")
#define CP_WAIT1()  asm volatile("cp.async.wait_group 1;"  ::: "memory")
#define CP_WAIT2()  asm volatile("cp.async.wait_group 2;"  ::: "memory")
#define CP_WAIT0()  asm volatile("cp.async.wait_group 0;"  ::: "memory")

__device__ __forceinline__ uint32_t hpack2(float x, float y) {
    __half2 t = __halves2half2(__float2half_rn(x), __float2half_rn(y));
    return *reinterpret_cast<uint32_t*>(&t);
}

// ---------------------------------------------------------------------------
// fp32 -> fp16 convert (X)
// ---------------------------------------------------------------------------
__global__ void conv_x(const float* __restrict__ X, __half* __restrict__ Hi)
{
    size_t i = (size_t)blockIdx.x * blockDim.x + threadIdx.x;
    float4 v = ((const float4*)X)[i];
    ((uint2*)Hi)[i] = make_uint2(hpack2(v.x, v.y), hpack2(v.z, v.w));
}

// ---------------------------------------------------------------------------
// Transposed fp16 weight: Wt[n][k] = W[k][n]
// ---------------------------------------------------------------------------
__global__ void conv_wT(const float* __restrict__ W, __half* __restrict__ Th)
{
    __shared__ float tile[32][33];
    int nx0 = blockIdx.x * 32;
    int ky0 = blockIdx.y * 32;
    #pragma unroll
    for (int i = 0; i < 4; ++i) {
        int kl = threadIdx.y + i * 8;
        tile[kl][threadIdx.x] = W[(size_t)(ky0 + kl) * D_ + nx0 + threadIdx.x];
    }
    __syncthreads();
    #pragma unroll
    for (int i = 0; i < 4; ++i) {
        int nl = threadIdx.y + i * 8;
        Th[(size_t)(nx0 + nl) * D_ + ky0 + threadIdx.x] =
            __float2half_rn(tile[threadIdx.x][nl]);
    }
}

// ---------------------------------------------------------------------------
// Projection GEMM: C[M,N] = A[M,K] @ B[N,K]^T + bias   (single fp16 x fp16)
// CTA tile 128x128, K-chunk 64, 2-stage cp.async, 8 warps (warp 64x32).
// mode 0: fp32 dense out[M][2048]
// mode 1: fp16 split-head [BH][S][64], scaled by `scale`
// mode 2: fp16 transposed [BH][64][S]
// ---------------------------------------------------------------------------
#define STAGE_STRIDE 32768u
#define PROJ_SMEM 67712      // max(2 stages x 32KB, 128x132 fp32 epilogue tile)

__global__ void __launch_bounds__(256, 1) proj_gemm(
    const __half* __restrict__ A_g, const __half* __restrict__ B_g,
    const float* __restrict__ bias, void* out0, int mode, float scale)
{
    extern __shared__ char dyn[];
    uint32_t raw = smem_u32(dyn);
    uint32_t st  = (raw + 127u) & ~127u;
    char* stp    = dyn + (st - raw);

    const int tid = threadIdx.x, wid = tid >> 5, lane = tid & 31;
    const int n0 = blockIdx.x * 128, m0 = blockIdx.y * 128;
    const int wm = wid & 1, wn = wid >> 1;
    const int lr = lane & 15;

    uint32_t swk[4];
    #pragma unroll
    for (int kk = 0; kk < 4; ++kk)
        swk[kk] = (uint32_t)((((kk * 2 + (lane >> 4)) ^ (lane & 7)) << 4));

    auto load_chunk = [&](int c, int s) {
        uint32_t sb = st + (uint32_t)s * STAGE_STRIDE;
        int k0 = c * 64;
        #pragma unroll
        for (int j = 0; j < 4; ++j) {
            int q = tid + 256 * j, row = q >> 3, ch = q & 7;
            cp_async16(sb + row * 128 + ((ch ^ (row & 7)) << 4),
                       A_g + (size_t)(m0 + row) * D_ + k0 + ch * 8);
        }
        #pragma unroll
        for (int j = 0; j < 4; ++j) {
            int q = tid + 256 * j, row = q >> 3, ch = q & 7;
            cp_async16(sb + 16384u + row * 128 + ((ch ^ (row & 7)) << 4),
                       B_g + (size_t)(n0 + row) * D_ + k0 + ch * 8);
        }
        CP_COMMIT();
    };

    float acc[4][4][4] = {};
    load_chunk(0, 0);
    load_chunk(1, 1);

    for (int c = 0; c < 32; ++c) {
        CP_WAIT1();
        __syncthreads();
        uint32_t sb = st + (uint32_t)(c & 1) * STAGE_STRIDE;
        uint32_t tA = sb, tB = sb + 16384u;
        #pragma unroll
        for (int kk = 0; kk < 4; ++kk) {
            uint32_t a4[4][4];
            #pragma unroll
            for (int mi = 0; mi < 4; ++mi) {
                uint32_t ro = (uint32_t)((wm * 64 + mi * 16 + lr) * 128);
                ldsm4(a4[mi], tA + ro + swk[kk]);
            }
            uint32_t b4[4][2];
            #pragma unroll
            for (int nj = 0; nj < 2; ++nj) {
                uint32_t ro = (uint32_t)((wn * 32 + nj * 16 + lr) * 128);
                uint32_t r4[4];
                ldsm4(r4, tB + ro + swk[kk]);
                b4[nj*2][0] = r4[0]; b4[nj*2][1] = r4[2];
                b4[nj*2+1][0] = r4[1]; b4[nj*2+1][1] = r4[3];
            }
            #pragma unroll
            for (int mi = 0; mi < 4; ++mi)
                #pragma unroll
                for (int nb = 0; nb < 4; ++nb)
                    mma_f16(acc[mi][nb], a4[mi], b4[nb][0], b4[nb][1]);
        }
        __syncthreads();
        if (c + 2 < 32) load_chunk(c + 2, c & 1);
        else            CP_COMMIT();
    }

    // epilogue via smem fp32 tile (reuses stage memory)
    CP_WAIT0();
    float* ftile = (float*)stp;   // 128 x 132
    #pragma unroll
    for (int mi = 0; mi < 4; ++mi)
        #pragma unroll
        for (int nb = 0; nb < 4; ++nb) {
            int r  = wm * 64 + mi * 16 + (lane >> 2);
            int cc = wn * 32 + nb * 8 + (lane & 3) * 2;
            ftile[r * 132 + cc]           = acc[mi][nb][0];
            ftile[r * 132 + cc + 1]       = acc[mi][nb][1];
            ftile[(r + 8) * 132 + cc]     = acc[mi][nb][2];
            ftile[(r + 8) * 132 + cc + 1] = acc[mi][nb][3];
        }
    __syncthreads();

    if (mode == 2) {
        // V^T fp16: out[bh][64][S]
        const int lane4 = lane * 4;
        int bb = m0 >> 11;
        int s0 = (m0 & (S_ - 1)) + lane4;
        __half* O0 = (__half*)out0;
        #pragma unroll
        for (int ii = 0; ii < 16; ++ii) {
            int nl = wid * 16 + ii;
            int n  = n0 + nl;
            float bvs = bias[n];
            int h = n >> 6, jj = n & 63;
            float v0 = ftile[(lane4 + 0) * 132 + nl] + bvs;
            float v1 = ftile[(lane4 + 1) * 132 + nl] + bvs;
            float v2 = ftile[(lane4 + 2) * 132 + nl] + bvs;
            float v3 = ftile[(lane4 + 3) * 132 + nl] + bvs;
            size_t base = ((size_t)(bb * H_ + h) * DH_ + jj) * S_ + s0;
            *(uint2*)&O0[base] = make_uint2(hpack2(v0, v1), hpack2(v2, v3));
        }
    } else {
        const int c4 = (tid & 31) * 4;
        float4 bv = *(const float4*)&bias[n0 + c4];
        #pragma unroll
        for (int i = 0; i < 16; ++i) {
            int r = (tid >> 5) + i * 8;
            float4 v = *(float4*)&ftile[r * 132 + c4];
            v.x += bv.x; v.y += bv.y; v.z += bv.z; v.w += bv.w;
            int m = m0 + r;
            if (mode == 0) {
                *(float4*)&((float*)out0)[(size_t)m * D_ + n0 + c4] = v;
            } else {
                // split-head fp16 with scale
                v.x *= scale; v.y *= scale; v.z *= scale; v.w *= scale;
                int bidx = m >> 11, s = m & (S_ - 1);
                int n = n0 + c4, h = n >> 6, jj = n & 63;
                size_t base = (((size_t)(bidx * H_ + h) * S_) + s) * DH_ + jj;
                *(uint2*)&((__half*)out0)[base] =
                    make_uint2(hpack2(v.x, v.y), hpack2(v.z, v.w));
            }
        }
    }
}

// ---------------------------------------------------------------------------
// Fused attention: per CTA = 128 query rows of one (b,h). All fp16 single.
// Online softmax, P in registers (C-frag -> A-frag identity), PV fused.
// ---------------------------------------------------------------------------
#define ATTN_SMEM 82048   // Q 16KB + 2 stages x (K 16KB + V^T 16KB)

__global__ void __launch_bounds__(256, 1) attn_fused(
    const __half* __restrict__ Qh, const __half* __restrict__ Kh,
    const __half* __restrict__ Vt, __half* __restrict__ Ch)
{
    extern __shared__ char dyn[];
    uint32_t raw = smem_u32(dyn);
    uint32_t st  = (raw + 127u) & ~127u;

    const int tid = threadIdx.x, wid = tid >> 5, lane = tid & 31;
    const int lr  = lane & 15;
    const int bh  = blockIdx.y;
    const int m0  = blockIdx.x * 128;

    uint32_t swk[4];
    #pragma unroll
    for (int kk = 0; kk < 4; ++kk)
        swk[kk] = (uint32_t)((((kk * 2 + (lane >> 4)) ^ (lane & 7)) << 4));

    const __half* Qh_b = Qh + ((size_t)bh * S_ + m0) * DH_;
    const __half* Kh_b = Kh + (size_t)bh * S_ * DH_;
    const __half* Vt_b = Vt + (size_t)bh * DH_ * S_;

    const uint32_t QH  = st;
    const uint32_t ST0 = st + 16384u;

    #pragma unroll
    for (int j = 0; j < 4; ++j) {
        int q = tid + 256 * j, row = q >> 3, ch = q & 7;
        cp_async16(QH + row * 128 + ((ch ^ (row & 7)) << 4),
                   Qh_b + (size_t)row * DH_ + ch * 8);
    }
    CP_COMMIT();

    auto load_kv = [&](int i, int s) {
        uint32_t kb = ST0 + (uint32_t)s * 32768u;
        uint32_t vb = kb + 16384u;
        #pragma unroll
        for (int j = 0; j < 4; ++j) {
            int q = tid + 256 * j, row = q >> 3, ch = q & 7;
            cp_async16(kb + row * 128 + ((ch ^ (row & 7)) << 4),
                       Kh_b + (size_t)(i * 128 + row) * DH_ + ch * 8);
        }
        #pragma unroll
        for (int sub = 0; sub < 2; ++sub)
            #pragma unroll
            for (int j = 0; j < 2; ++j) {
                int q = tid + 256 * j, row = q >> 3, ch = q & 7;  // row 0..63
                cp_async16(vb + sub * 8192 + row * 128 + ((ch ^ (row & 7)) << 4),
                           Vt_b + (size_t)row * S_ + i * 128 + sub * 64 + ch * 8);
            }
        CP_COMMIT();
    };
    load_kv(0, 0);
    load_kv(1, 1);

    CP_WAIT2();
    __syncthreads();
    uint32_t qa[4][4];
    #pragma unroll
    for (int kk = 0; kk < 4; ++kk) {
        uint32_t ro = (uint32_t)((wid * 16 + lr) * 128);
        ldsm4(qa[kk], QH + ro + swk[kk]);
    }

    float cAcc[8][4] = {};
    float mA = -1e30f, mB = -1e30f, lA = 0.f, lB = 0.f;

    for (int i = 0; i < 16; ++i) {
        CP_WAIT1();
        __syncthreads();
        uint32_t kb = ST0 + (uint32_t)(i & 1) * 32768u;
        uint32_t vb = kb + 16384u;

        float sAcc[16][4] = {};
        #pragma unroll
        for (int kk = 0; kk < 4; ++kk) {
            uint32_t bK[16][2];
            #pragma unroll
            for (int g = 0; g < 8; ++g) {
                uint32_t r4[4];
                ldsm4(r4, kb + (uint32_t)((g * 16 + lr) * 128) + swk[kk]);
                bK[2*g][0]   = r4[0]; bK[2*g][1]   = r4[2];
                bK[2*g+1][0] = r4[1]; bK[2*g+1][1] = r4[3];
            }
            #pragma unroll
            for (int nt = 0; nt < 16; ++nt)
                mma_f16(sAcc[nt], qa[kk], bK[nt][0], bK[nt][1]);
        }

        float rA = -1e30f, rB = -1e30f;
        #pragma unroll
        for (int nt = 0; nt < 16; ++nt) {
            rA = fmaxf(rA, fmaxf(sAcc[nt][0], sAcc[nt][1]));
            rB = fmaxf(rB, fmaxf(sAcc[nt][2], sAcc[nt][3]));
        }
        rA = fmaxf(rA, __shfl_xor_sync(0xffffffffu, rA, 1));
        rA = fmaxf(rA, __shfl_xor_sync(0xffffffffu, rA, 2));
        rB = fmaxf(rB, __shfl_xor_sync(0xffffffffu, rB, 1));
        rB = fmaxf(rB, __shfl_xor_sync(0xffffffffu, rB, 2));
        float mnA = fmaxf(mA, rA), mnB = fmaxf(mB, rB);
        float esA = __expf(mA - mnA), esB = __expf(mB - mnB);
        mA = mnA; mB = mnB;

        float suA = 0.f, suB = 0.f;
        #pragma unroll
        for (int nt = 0; nt < 16; ++nt) {
            sAcc[nt][0] = __expf(sAcc[nt][0] - mA);
            sAcc[nt][1] = __expf(sAcc[nt][1] - mA);
            sAcc[nt][2] = __expf(sAcc[nt][2] - mB);
            sAcc[nt][3] = __expf(sAcc[nt][3] - mB);
            suA += sAcc[nt][0] + sAcc[nt][1];
            suB += sAcc[nt][2] + sAcc[nt][3];
        }
        suA += __shfl_xor_sync(0xffffffffu, suA, 1);
        suA += __shfl_xor_sync(0xffffffffu, suA, 2);
        suB += __shfl_xor_sync(0xffffffffu, suB, 1);
        suB += __shfl_xor_sync(0xffffffffu, suB, 2);
        lA = lA * esA + suA;
        lB = lB * esB + suB;
        #pragma unroll
        for (int nb = 0; nb < 8; ++nb) {
            cAcc[nb][0] *= esA; cAcc[nb][1] *= esA;
            cAcc[nb][2] *= esB; cAcc[nb][3] *= esB;
        }

        #pragma unroll
        for (int kt = 0; kt < 8; ++kt) {
            uint32_t pa[4];
            pa[0] = hpack2(sAcc[2*kt][0],   sAcc[2*kt][1]);
            pa[1] = hpack2(sAcc[2*kt][2],   sAcc[2*kt][3]);
            pa[2] = hpack2(sAcc[2*kt+1][0], sAcc[2*kt+1][1]);
            pa[3] = hpack2(sAcc[2*kt+1][2], sAcc[2*kt+1][3]);
            uint32_t vsb = vb + (uint32_t)(kt >> 2) * 8192u;
            int kkv = kt & 3;
            uint32_t bV[8][2];
            #pragma unroll
            for (int g = 0; g < 4; ++g) {
                uint32_t r4[4];
                ldsm4(r4, vsb + (uint32_t)((g * 16 + lr) * 128) + swk[kkv]);
                bV[2*g][0]   = r4[0]; bV[2*g][1]   = r4[2];
                bV[2*g+1][0] = r4[1]; bV[2*g+1][1] = r4[3];
            }
            #pragma unroll
            for (int nb = 0; nb < 8; ++nb)
                mma_f16(cAcc[nb], pa, bV[nb][0], bV[nb][1]);
        }

        __syncthreads();
        if (i + 2 < 16) load_kv(i + 2, i & 1);
        else            CP_COMMIT();
    }

    // epilogue: normalize, single fp16 ctx into [M][2048]
    const int b = bh >> 5, h = bh & 31;
    float iA = 1.0f / lA, iB = 1.0f / lB;
    int rA_ = m0 + wid * 16 + (lane >> 2);
    int rB_ = rA_ + 8;
    #pragma unroll
    for (int nb = 0; nb < 8; ++nb) {
        int c = nb * 8 + (lane & 3) * 2;
        size_t ia = ((size_t)(b * S_) + rA_) * D_ + h * DH_ + c;
        size_t ib = ((size_t)(b * S_) + rB_) * D_ + h * DH_ + c;
        *(uint32_t*)&Ch[ia] = hpack2(cAcc[nb][0] * iA, cAcc[nb][1] * iA);
        *(uint32_t*)&Ch[ib] = hpack2(cAcc[nb][2] * iB, cAcc[nb][3] * iB);
    }
}

// ---------------------------------------------------------------------------
extern "C" void kernel_launch(void* const* d_in, const int* in_sizes, int n_in,
                              void* d_out, int out_size)
{
    const float* X  = (const float*)d_in[0];
    const float* Wq = (const float*)d_in[1];
    const float* bq = (const float*)d_in[2];
    const float* Wk = (const float*)d_in[3];
    const float* bk = (const float*)d_in[4];
    const float* Wv = (const float*)d_in[5];
    const float* bv = (const float*)d_in[6];
    const float* Wo = (const float*)d_in[7];
    const float* bo = (const float*)d_in[8];
    float* out = (float*)d_out;

    __half *xh, *wh, *qh, *kh, *vth;
    cudaGetSymbolAddress((void**)&xh,  g_xh);
    cudaGetSymbolAddress((void**)&wh,  g_wh);
    cudaGetSymbolAddress((void**)&qh,  g_qh);
    cudaGetSymbolAddress((void**)&kh,  g_kh);
    cudaGetSymbolAddress((void**)&vth, g_vth);

    static bool attr_done = false;
    if (!attr_done) {
        cudaFuncSetAttribute(proj_gemm,  cudaFuncAttributeMaxDynamicSharedMemorySize, PROJ_SMEM);
        cudaFuncSetAttribute(attn_fused, cudaFuncAttributeMaxDynamicSharedMemorySize, ATTN_SMEM);
        attr_done = true;
    }

    const size_t WSZ = (size_t)D_ * D_;

    // conversions
    conv_x<<<(M_ * (size_t)D_) / 1024, 256>>>(X, xh);
    dim3 tblk(32, 8), tgrid(D_ / 32, D_ / 32);
    conv_wT<<<tgrid, tblk>>>(Wq, wh + 0 * WSZ);
    conv_wT<<<tgrid, tblk>>>(Wk, wh + 1 * WSZ);
    conv_wT<<<tgrid, tblk>>>(Wv, wh + 2 * WSZ);
    conv_wT<<<tgrid, tblk>>>(Wo, wh + 3 * WSZ);

    // projections (single fp16 everywhere)
    dim3 pblk(256), pgrid(D_ / 128, M_ / 128);   // (16, 32)
    proj_gemm<<<pgrid, pblk, PROJ_SMEM>>>(xh, wh + 0 * WSZ, bq, qh, 1, 0.125f); // Q (scale folded)
    proj_gemm<<<pgrid, pblk, PROJ_SMEM>>>(xh, wh + 1 * WSZ, bk, kh, 1, 1.0f);   // K
    proj_gemm<<<pgrid, pblk, PROJ_SMEM>>>(xh, wh + 2 * WSZ, bv, vth, 2, 1.0f);  // V^T

    // fused attention: ctx fp16 -> xh (X no longer needed)
    dim3 agrid(S_ / 128, BH_);                   // (16, 64)
    attn_fused<<<agrid, pblk, ATTN_SMEM>>>(qh, kh, vth, xh);

    // output projection
    proj_gemm<<<pgrid, pblk, PROJ_SMEM>>>(xh, wh + 3 * WSZ, bo, out, 0, 1.0f);
}

// round 8
// speedup vs baseline: 10.1070x; 1.1024x over previous
#include <cuda_runtime.h>
#include <cuda_fp16.h>
#include <cstdint>

#define B_   2
#define S_   2048
#define D_   2048
#define H_   32
#define DH_  64
#define M_   (B_*S_)    // 4096
#define BH_  (B_*H_)    // 64
#define WSZ_ ((size_t)D_*D_)

// Q pre-scale: (1/sqrt(64)) * log2(e)  -> scores land in log2 domain
#define QSCALE 0.18033688011112042f

// ---------------------------------------------------------------------------
// Scratch
// ---------------------------------------------------------------------------
__device__ __half g_xh[(size_t)M_*D_];         // X fp16 (later ctx fp16)
__device__ __half g_wh[(size_t)4*D_*D_];       // Wt fp16 [N][K] (4 mats)
__device__ __half g_qh[(size_t)M_*D_];         // Q fp16 [BH][S][64] (log2-scaled)
__device__ __half g_kh[(size_t)M_*D_];         // K fp16 [BH][S][64]
__device__ __half g_vth[(size_t)M_*D_];        // V^T fp16 [BH][64][S]

// ---------------------------------------------------------------------------
// Baseline-PTX primitives
// ---------------------------------------------------------------------------
__device__ __forceinline__ uint32_t smem_u32(const void* p) {
    uint32_t a;
    asm("{ .reg .u64 t; cvta.to.shared.u64 t, %1; cvt.u32.u64 %0, t; }" : "=r"(a) : "l"(p));
    return a;
}
__device__ __forceinline__ void ldsm4(uint32_t* r, uint32_t a) {
    asm volatile("ldmatrix.sync.aligned.m8n8.x4.shared.b16 {%0,%1,%2,%3}, [%4];"
                 : "=r"(r[0]), "=r"(r[1]), "=r"(r[2]), "=r"(r[3]) : "r"(a));
}
__device__ __forceinline__ void mma_f16(float* d, const uint32_t* a,
                                        uint32_t b0, uint32_t b1) {
    asm volatile("mma.sync.aligned.m16n8k16.row.col.f32.f16.f16.f32 "
                 "{%0,%1,%2,%3}, {%4,%5,%6,%7}, {%8,%9}, {%0,%1,%2,%3};"
                 : "+f"(d[0]), "+f"(d[1]), "+f"(d[2]), "+f"(d[3])
                 : "r"(a[0]), "r"(a[1]), "r"(a[2]), "r"(a[3]), "r"(b0), "r"(b1));
}
__device__ __forceinline__ void cp_async16(uint32_t dst, const void* src) {
    asm volatile("cp.async.cg.shared.global [%0], [%1], 16;" :: "r"(dst), "l"(src));
}
#define CP_COMMIT() asm volatile("cp.async.commit_group;" ::: "memory")
#define CP_WAIT1()  asm volatile("cp.async.wait_group 1;"  ::: "memory")
#define CP_WAIT2()  asm volatile("cp.async.wait_group 2;"  ::: "memory")
#define CP_WAIT0()  asm volatile("cp.async.wait_group 0;"  ::: "memory")

__device__ __forceinline__ uint32_t hpack2(float x, float y) {
    __half2 t = __halves2half2(__float2half_rn(x), __float2half_rn(y));
    return *reinterpret_cast<uint32_t*>(&t);
}
__device__ __forceinline__ uint32_t ex2_f16x2(uint32_t x) {
    uint32_t r;
    asm("ex2.approx.f16x2 %0, %1;" : "=r"(r) : "r"(x));
    return r;
}

// ---------------------------------------------------------------------------
// fp32 -> fp16 convert (X)
// ---------------------------------------------------------------------------
__global__ void conv_x(const float* __restrict__ X, __half* __restrict__ Hi)
{
    size_t i = (size_t)blockIdx.x * blockDim.x + threadIdx.x;
    float4 v = ((const float4*)X)[i];
    ((uint2*)Hi)[i] = make_uint2(hpack2(v.x, v.y), hpack2(v.z, v.w));
}

// ---------------------------------------------------------------------------
// Transposed fp16 weights, all four mats in one launch (z selects)
// ---------------------------------------------------------------------------
__global__ void conv_wT4(const float* __restrict__ W0, const float* __restrict__ W1,
                         const float* __restrict__ W2, const float* __restrict__ W3,
                         __half* __restrict__ Th)
{
    const float* W = blockIdx.z == 0 ? W0 : blockIdx.z == 1 ? W1
                   : blockIdx.z == 2 ? W2 : W3;
    __half* T = Th + (size_t)blockIdx.z * WSZ_;
    __shared__ float tile[32][33];
    int nx0 = blockIdx.x * 32;
    int ky0 = blockIdx.y * 32;
    #pragma unroll
    for (int i = 0; i < 4; ++i) {
        int kl = threadIdx.y + i * 8;
        tile[kl][threadIdx.x] = W[(size_t)(ky0 + kl) * D_ + nx0 + threadIdx.x];
    }
    __syncthreads();
    #pragma unroll
    for (int i = 0; i < 4; ++i) {
        int nl = threadIdx.y + i * 8;
        T[(size_t)(nx0 + nl) * D_ + ky0 + threadIdx.x] =
            __float2half_rn(tile[threadIdx.x][nl]);
    }
}

// ---------------------------------------------------------------------------
// Shared GEMM mainloop pieces (128x128 tile, K-chunk 64, 8 warps)
// ---------------------------------------------------------------------------
#define STAGE_STRIDE 32768u
#define PROJ_SMEM 67712

#define GEMM_PROLOGUE()                                                         \
    extern __shared__ char dyn[];                                               \
    uint32_t raw = smem_u32(dyn);                                               \
    uint32_t st  = (raw + 127u) & ~127u;                                        \
    char* stp    = dyn + (st - raw);                                            \
    const int tid = threadIdx.x, wid = tid >> 5, lane = tid & 31;               \
    const int n0 = blockIdx.x * 128, m0 = blockIdx.y * 128;                     \
    const int wm = wid & 1, wn = wid >> 1;                                      \
    const int lr = lane & 15;                                                   \
    uint32_t swk[4];                                                            \
    _Pragma("unroll")                                                           \
    for (int kk = 0; kk < 4; ++kk)                                              \
        swk[kk] = (uint32_t)((((kk * 2 + (lane >> 4)) ^ (lane & 7)) << 4));

#define GEMM_MAINLOOP(A_g, B_g)                                                 \
    auto load_chunk = [&](int c, int s) {                                       \
        uint32_t sb = st + (uint32_t)s * STAGE_STRIDE;                          \
        int k0 = c * 64;                                                        \
        _Pragma("unroll")                                                       \
        for (int j = 0; j < 4; ++j) {                                           \
            int q = tid + 256 * j, row = q >> 3, ch = q & 7;                    \
            cp_async16(sb + row * 128 + ((ch ^ (row & 7)) << 4),                \
                       (A_g) + (size_t)(m0 + row) * D_ + k0 + ch * 8);          \
        }                                                                       \
        _Pragma("unroll")                                                       \
        for (int j = 0; j < 4; ++j) {                                           \
            int q = tid + 256 * j, row = q >> 3, ch = q & 7;                    \
            cp_async16(sb + 16384u + row * 128 + ((ch ^ (row & 7)) << 4),       \
                       (B_g) + (size_t)(n0 + row) * D_ + k0 + ch * 8);          \
        }                                                                       \
        CP_COMMIT();                                                            \
    };                                                                          \
    float acc[4][4][4] = {};                                                    \
    load_chunk(0, 0);                                                           \
    load_chunk(1, 1);                                                           \
    for (int c = 0; c < 32; ++c) {                                              \
        CP_WAIT1();                                                             \
        __syncthreads();                                                        \
        uint32_t sb = st + (uint32_t)(c & 1) * STAGE_STRIDE;                    \
        uint32_t tA = sb, tB = sb + 16384u;                                     \
        _Pragma("unroll")                                                       \
        for (int kk = 0; kk < 4; ++kk) {                                        \
            uint32_t a4[4][4];                                                  \
            _Pragma("unroll")                                                   \
            for (int mi = 0; mi < 4; ++mi) {                                    \
                uint32_t ro = (uint32_t)((wm * 64 + mi * 16 + lr) * 128);       \
                ldsm4(a4[mi], tA + ro + swk[kk]);                               \
            }                                                                   \
            uint32_t b4[4][2];                                                  \
            _Pragma("unroll")                                                   \
            for (int nj = 0; nj < 2; ++nj) {                                    \
                uint32_t ro = (uint32_t)((wn * 32 + nj * 16 + lr) * 128);       \
                uint32_t r4[4];                                                 \
                ldsm4(r4, tB + ro + swk[kk]);                                   \
                b4[nj*2][0] = r4[0]; b4[nj*2][1] = r4[2];                       \
                b4[nj*2+1][0] = r4[1]; b4[nj*2+1][1] = r4[3];                   \
            }                                                                   \
            _Pragma("unroll")                                                   \
            for (int mi = 0; mi < 4; ++mi)                                      \
                _Pragma("unroll")                                               \
                for (int nb = 0; nb < 4; ++nb)                                  \
                    mma_f16(acc[mi][nb], a4[mi], b4[nb][0], b4[nb][1]);         \
        }                                                                       \
        __syncthreads();                                                        \
        if (c + 2 < 32) load_chunk(c + 2, c & 1);                               \
        else            CP_COMMIT();                                            \
    }                                                                           \
    CP_WAIT0();                                                                 \
    float* ftile = (float*)stp;                                                 \
    _Pragma("unroll")                                                           \
    for (int mi = 0; mi < 4; ++mi)                                              \
        _Pragma("unroll")                                                       \
        for (int nb = 0; nb < 4; ++nb) {                                        \
            int r  = wm * 64 + mi * 16 + (lane >> 2);                           \
            int cc = wn * 32 + nb * 8 + (lane & 3) * 2;                         \
            ftile[r * 132 + cc]           = acc[mi][nb][0];                     \
            ftile[r * 132 + cc + 1]       = acc[mi][nb][1];                     \
            ftile[(r + 8) * 132 + cc]     = acc[mi][nb][2];                     \
            ftile[(r + 8) * 132 + cc + 1] = acc[mi][nb][3];                     \
        }                                                                       \
    __syncthreads();

// ---------------------------------------------------------------------------
// Fused QKV projection: z=0 Q (split-head, QSCALE), z=1 K (split-head),
// z=2 V (transposed [BH][64][S])
// ---------------------------------------------------------------------------
__global__ void __launch_bounds__(256, 1) qkv_gemm(
    const __half* __restrict__ A_g, const __half* __restrict__ Wbase,
    const float* __restrict__ bq, const float* __restrict__ bk,
    const float* __restrict__ bv,
    __half* __restrict__ Oq, __half* __restrict__ Ok, __half* __restrict__ Ov)
{
    const int z = blockIdx.z;
    const __half* B_g = Wbase + (size_t)z * WSZ_;
    const float* bias = z == 0 ? bq : z == 1 ? bk : bv;

    GEMM_PROLOGUE();
    GEMM_MAINLOOP(A_g, B_g);

    if (z == 2) {
        // V^T fp16: out[bh][64][S]
        const int lane4 = lane * 4;
        int bb = m0 >> 11;
        int s0 = (m0 & (S_ - 1)) + lane4;
        #pragma unroll
        for (int ii = 0; ii < 16; ++ii) {
            int nl = wid * 16 + ii;
            int n  = n0 + nl;
            float bvs = bias[n];
            int h = n >> 6, jj = n & 63;
            float v0 = ftile[(lane4 + 0) * 132 + nl] + bvs;
            float v1 = ftile[(lane4 + 1) * 132 + nl] + bvs;
            float v2 = ftile[(lane4 + 2) * 132 + nl] + bvs;
            float v3 = ftile[(lane4 + 3) * 132 + nl] + bvs;
            size_t base = ((size_t)(bb * H_ + h) * DH_ + jj) * S_ + s0;
            *(uint2*)&Ov[base] = make_uint2(hpack2(v0, v1), hpack2(v2, v3));
        }
    } else {
        const float scale = (z == 0) ? QSCALE : 1.0f;
        __half* O0 = (z == 0) ? Oq : Ok;
        const int c4 = (tid & 31) * 4;
        float4 bvv = *(const float4*)&bias[n0 + c4];
        #pragma unroll
        for (int i = 0; i < 16; ++i) {
            int r = (tid >> 5) + i * 8;
            float4 v = *(float4*)&ftile[r * 132 + c4];
            v.x = (v.x + bvv.x) * scale; v.y = (v.y + bvv.y) * scale;
            v.z = (v.z + bvv.z) * scale; v.w = (v.w + bvv.w) * scale;
            int m = m0 + r;
            int bidx = m >> 11, s = m & (S_ - 1);
            int n = n0 + c4, h = n >> 6, jj = n & 63;
            size_t base = (((size_t)(bidx * H_ + h) * S_) + s) * DH_ + jj;
            *(uint2*)&O0[base] = make_uint2(hpack2(v.x, v.y), hpack2(v.z, v.w));
        }
    }
}

// ---------------------------------------------------------------------------
// Output projection: fp32 dense out[M][2048]
// ---------------------------------------------------------------------------
__global__ void __launch_bounds__(256, 1) o_gemm(
    const __half* __restrict__ A_g, const __half* __restrict__ B_g,
    const float* __restrict__ bias, float* __restrict__ out)
{
    GEMM_PROLOGUE();
    GEMM_MAINLOOP(A_g, B_g);

    const int c4 = (tid & 31) * 4;
    float4 bv = *(const float4*)&bias[n0 + c4];
    #pragma unroll
    for (int i = 0; i < 16; ++i) {
        int r = (tid >> 5) + i * 8;
        float4 v = *(float4*)&ftile[r * 132 + c4];
        v.x += bv.x; v.y += bv.y; v.z += bv.z; v.w += bv.w;
        *(float4*)&out[(size_t)(m0 + r) * D_ + n0 + c4] = v;
    }
}

// ---------------------------------------------------------------------------
// Fused attention, log2-domain softmax in f16x2, MMA-based row sums.
// ---------------------------------------------------------------------------
#define ATTN_SMEM 82048   // Q 16KB + 2 stages x (K 16KB + V^T 16KB)
#define ONES_F16X2 0x3C003C00u

__global__ void __launch_bounds__(256, 1) attn_fused(
    const __half* __restrict__ Qh, const __half* __restrict__ Kh,
    const __half* __restrict__ Vt, __half* __restrict__ Ch)
{
    extern __shared__ char dyn[];
    uint32_t raw = smem_u32(dyn);
    uint32_t st  = (raw + 127u) & ~127u;

    const int tid = threadIdx.x, wid = tid >> 5, lane = tid & 31;
    const int lr  = lane & 15;
    const int bh  = blockIdx.y;
    const int m0  = blockIdx.x * 128;

    uint32_t swk[4];
    #pragma unroll
    for (int kk = 0; kk < 4; ++kk)
        swk[kk] = (uint32_t)((((kk * 2 + (lane >> 4)) ^ (lane & 7)) << 4));

    const __half* Qh_b = Qh + ((size_t)bh * S_ + m0) * DH_;
    const __half* Kh_b = Kh + (size_t)bh * S_ * DH_;
    const __half* Vt_b = Vt + (size_t)bh * DH_ * S_;

    const uint32_t QH  = st;
    const uint32_t ST0 = st + 16384u;

    #pragma unroll
    for (int j = 0; j < 4; ++j) {
        int q = tid + 256 * j, row = q >> 3, ch = q & 7;
        cp_async16(QH + row * 128 + ((ch ^ (row & 7)) << 4),
                   Qh_b + (size_t)row * DH_ + ch * 8);
    }
    CP_COMMIT();

    auto load_kv = [&](int i, int s) {
        uint32_t kb = ST0 + (uint32_t)s * 32768u;
        uint32_t vb = kb + 16384u;
        #pragma unroll
        for (int j = 0; j < 4; ++j) {
            int q = tid + 256 * j, row = q >> 3, ch = q & 7;
            cp_async16(kb + row * 128 + ((ch ^ (row & 7)) << 4),
                       Kh_b + (size_t)(i * 128 + row) * DH_ + ch * 8);
        }
        #pragma unroll
        for (int sub = 0; sub < 2; ++sub)
            #pragma unroll
            for (int j = 0; j < 2; ++j) {
                int q = tid + 256 * j, row = q >> 3, ch = q & 7;  // row 0..63
                cp_async16(vb + sub * 8192 + row * 128 + ((ch ^ (row & 7)) << 4),
                           Vt_b + (size_t)row * S_ + i * 128 + sub * 64 + ch * 8);
            }
        CP_COMMIT();
    };
    load_kv(0, 0);
    load_kv(1, 1);

    CP_WAIT2();
    __syncthreads();
    uint32_t qa[4][4];
    #pragma unroll
    for (int kk = 0; kk < 4; ++kk) {
        uint32_t ro = (uint32_t)((wid * 16 + lr) * 128);
        ldsm4(qa[kk], QH + ro + swk[kk]);
    }

    float cAcc[8][4] = {};
    float sumA[4] = {};                 // MMA row sums (exact fp32 accumulation)
    float mA = -1e30f, mB = -1e30f;     // running maxes (fp16-rounded values)

    for (int i = 0; i < 16; ++i) {
        CP_WAIT1();
        __syncthreads();
        uint32_t kb = ST0 + (uint32_t)(i & 1) * 32768u;
        uint32_t vb = kb + 16384u;

        // --- QK^T (log2-domain scores) ---
        float sAcc[16][4] = {};
        #pragma unroll
        for (int kk = 0; kk < 4; ++kk) {
            uint32_t bK[16][2];
            #pragma unroll
            for (int g = 0; g < 8; ++g) {
                uint32_t r4[4];
                ldsm4(r4, kb + (uint32_t)((g * 16 + lr) * 128) + swk[kk]);
                bK[2*g][0]   = r4[0]; bK[2*g][1]   = r4[2];
                bK[2*g+1][0] = r4[1]; bK[2*g+1][1] = r4[3];
            }
            #pragma unroll
            for (int nt = 0; nt < 16; ++nt)
                mma_f16(sAcc[nt], qa[kk], bK[nt][0], bK[nt][1]);
        }

        // --- row max (fp32), rounded to fp16 for consistent subtraction ---
        float rA = -1e30f, rB = -1e30f;
        #pragma unroll
        for (int nt = 0; nt < 16; ++nt) {
            rA = fmaxf(rA, fmaxf(sAcc[nt][0], sAcc[nt][1]));
            rB = fmaxf(rB, fmaxf(sAcc[nt][2], sAcc[nt][3]));
        }
        rA = fmaxf(rA, __shfl_xor_sync(0xffffffffu, rA, 1));
        rA = fmaxf(rA, __shfl_xor_sync(0xffffffffu, rA, 2));
        rB = fmaxf(rB, __shfl_xor_sync(0xffffffffu, rB, 1));
        rB = fmaxf(rB, __shfl_xor_sync(0xffffffffu, rB, 2));
        __half mhA = __float2half_rn(fmaxf(mA, rA));
        __half mhB = __float2half_rn(fmaxf(mB, rB));
        float mnA = __half2float(mhA), mnB = __half2float(mhB);
        float esA = exp2f(mA - mnA), esB = exp2f(mB - mnB);
        mA = mnA; mB = mnB;
        __half2 mA2 = __halves2half2(mhA, mhA);
        __half2 mB2 = __halves2half2(mhB, mhB);

        // --- probs: f16x2 ex2 directly into PV A-fragments ---
        uint32_t pw0[16], pw1[16];
        #pragma unroll
        for (int nt = 0; nt < 16; ++nt) {
            __half2 a = __floats2half2_rn(sAcc[nt][0], sAcc[nt][1]);
            __half2 b = __floats2half2_rn(sAcc[nt][2], sAcc[nt][3]);
            a = __hsub2(a, mA2);
            b = __hsub2(b, mB2);
            pw0[nt] = ex2_f16x2(*reinterpret_cast<uint32_t*>(&a));
            pw1[nt] = ex2_f16x2(*reinterpret_cast<uint32_t*>(&b));
        }

        // --- rescale accumulators ---
        #pragma unroll
        for (int nb = 0; nb < 8; ++nb) {
            cAcc[nb][0] *= esA; cAcc[nb][1] *= esA;
            cAcc[nb][2] *= esB; cAcc[nb][3] *= esB;
        }
        sumA[0] *= esA; sumA[1] *= esA; sumA[2] *= esB; sumA[3] *= esB;

        // --- PV + ones-column row sums ---
        #pragma unroll
        for (int kt = 0; kt < 8; ++kt) {
            uint32_t pa[4];
            pa[0] = pw0[2*kt];   pa[1] = pw1[2*kt];
            pa[2] = pw0[2*kt+1]; pa[3] = pw1[2*kt+1];
            uint32_t vsb = vb + (uint32_t)(kt >> 2) * 8192u;
            int kkv = kt & 3;
            uint32_t bV[8][2];
            #pragma unroll
            for (int g = 0; g < 4; ++g) {
                uint32_t r4[4];
                ldsm4(r4, vsb + (uint32_t)((g * 16 + lr) * 128) + swk[kkv]);
                bV[2*g][0]   = r4[0]; bV[2*g][1]   = r4[2];
                bV[2*g+1][0] = r4[1]; bV[2*g+1][1] = r4[3];
            }
            #pragma unroll
            for (int nb = 0; nb < 8; ++nb)
                mma_f16(cAcc[nb], pa, bV[nb][0], bV[nb][1]);
            mma_f16(sumA, pa, ONES_F16X2, ONES_F16X2);   // row sums
        }

        __syncthreads();
        if (i + 2 < 16) load_kv(i + 2, i & 1);
        else            CP_COMMIT();
    }

    // epilogue: normalize by MMA-computed sums, fp16 ctx into [M][2048]
    const int b = bh >> 5, h = bh & 31;
    float iA = 1.0f / sumA[0], iB = 1.0f / sumA[2];
    int rA_ = m0 + wid * 16 + (lane >> 2);
    int rB_ = rA_ + 8;
    #pragma unroll
    for (int nb = 0; nb < 8; ++nb) {
        int c = nb * 8 + (lane & 3) * 2;
        size_t ia = ((size_t)(b * S_) + rA_) * D_ + h * DH_ + c;
        size_t ib = ((size_t)(b * S_) + rB_) * D_ + h * DH_ + c;
        *(uint32_t*)&Ch[ia] = hpack2(cAcc[nb][0] * iA, cAcc[nb][1] * iA);
        *(uint32_t*)&Ch[ib] = hpack2(cAcc[nb][2] * iB, cAcc[nb][3] * iB);
    }
}

// ---------------------------------------------------------------------------
extern "C" void kernel_launch(void* const* d_in, const int* in_sizes, int n_in,
                              void* d_out, int out_size)
{
    const float* X  = (const float*)d_in[0];
    const float* Wq = (const float*)d_in[1];
    const float* bq = (const float*)d_in[2];
    const float* Wk = (const float*)d_in[3];
    const float* bk = (const float*)d_in[4];
    const float* Wv = (const float*)d_in[5];
    const float* bv = (const float*)d_in[6];
    const float* Wo = (const float*)d_in[7];
    const float* bo = (const float*)d_in[8];
    float* out = (float*)d_out;

    __half *xh, *wh, *qh, *kh, *vth;
    cudaGetSymbolAddress((void**)&xh,  g_xh);
    cudaGetSymbolAddress((void**)&wh,  g_wh);
    cudaGetSymbolAddress((void**)&qh,  g_qh);
    cudaGetSymbolAddress((void**)&kh,  g_kh);
    cudaGetSymbolAddress((void**)&vth, g_vth);

    static bool attr_done = false;
    if (!attr_done) {
        cudaFuncSetAttribute(qkv_gemm,   cudaFuncAttributeMaxDynamicSharedMemorySize, PROJ_SMEM);
        cudaFuncSetAttribute(o_gemm,     cudaFuncAttributeMaxDynamicSharedMemorySize, PROJ_SMEM);
        cudaFuncSetAttribute(attn_fused, cudaFuncAttributeMaxDynamicSharedMemorySize, ATTN_SMEM);
        attr_done = true;
    }

    // conversions
    conv_x<<<(M_ * (size_t)D_) / 1024, 256>>>(X, xh);
    dim3 tblk(32, 8), tgrid(D_ / 32, D_ / 32, 4);
    conv_wT4<<<tgrid, tblk>>>(Wq, Wk, Wv, Wo, wh);

    // fused QKV projections (one launch, 1536 CTAs)
    dim3 pblk(256), qgrid(D_ / 128, M_ / 128, 3);   // (16, 32, 3)
    qkv_gemm<<<qgrid, pblk, PROJ_SMEM>>>(xh, wh, bq, bk, bv, qh, kh, vth);

    // fused attention: ctx fp16 -> xh
    dim3 agrid(S_ / 128, BH_);                      // (16, 64)
    attn_fused<<<agrid, pblk, ATTN_SMEM>>>(qh, kh, vth, xh);

    // output projection
    dim3 ogrid(D_ / 128, M_ / 128);                 // (16, 32)
    o_gemm<<<ogrid, pblk, PROJ_SMEM>>>(xh, wh + 3 * WSZ_, bo, out);
}

// round 9
// speedup vs baseline: 10.3718x; 1.0262x over previous
#include <cuda_runtime.h>
#include <cuda_fp16.h>
#include <cstdint>

#define B_   2
#define S_   2048
#define D_   2048
#define H_   32
#define DH_  64
#define M_   (B_*S_)    // 4096
#define BH_  (B_*H_)    // 64
#define WSZ_ ((size_t)D_*D_)

// Q pre-scale: (1/sqrt(64)) * log2(e)  -> scores land in log2 domain
#define QSCALE 0.18033688011112042f

// ---------------------------------------------------------------------------
// Scratch
// ---------------------------------------------------------------------------
__device__ __half g_xh[(size_t)M_*D_];         // X fp16 (later ctx fp16)
__device__ __half g_wh[(size_t)4*D_*D_];       // Wt fp16 [N][K] (4 mats)
__device__ __half g_qh[(size_t)M_*D_];         // Q fp16 [BH][S][64] (log2-scaled)
__device__ __half g_kh[(size_t)M_*D_];         // K fp16 [BH][S][64]
__device__ __half g_vth[(size_t)M_*D_];        // V^T fp16 [BH][64][S]

// ---------------------------------------------------------------------------
// Baseline-PTX primitives
// ---------------------------------------------------------------------------
__device__ __forceinline__ uint32_t smem_u32(const void* p) {
    uint32_t a;
    asm("{ .reg .u64 t; cvta.to.shared.u64 t, %1; cvt.u32.u64 %0, t; }" : "=r"(a) : "l"(p));
    return a;
}
__device__ __forceinline__ void ldsm4(uint32_t* r, uint32_t a) {
    asm volatile("ldmatrix.sync.aligned.m8n8.x4.shared.b16 {%0,%1,%2,%3}, [%4];"
                 : "=r"(r[0]), "=r"(r[1]), "=r"(r[2]), "=r"(r[3]) : "r"(a));
}
__device__ __forceinline__ void mma_f16(float* d, const uint32_t* a,
                                        uint32_t b0, uint32_t b1) {
    asm volatile("mma.sync.aligned.m16n8k16.row.col.f32.f16.f16.f32 "
                 "{%0,%1,%2,%3}, {%4,%5,%6,%7}, {%8,%9}, {%0,%1,%2,%3};"
                 : "+f"(d[0]), "+f"(d[1]), "+f"(d[2]), "+f"(d[3])
                 : "r"(a[0]), "r"(a[1]), "r"(a[2]), "r"(a[3]), "r"(b0), "r"(b1));
}
__device__ __forceinline__ void cp_async16(uint32_t dst, const void* src) {
    asm volatile("cp.async.cg.shared.global [%0], [%1], 16;" :: "r"(dst), "l"(src));
}
#define CP_COMMIT() asm volatile("cp.async.commit_group;" ::: "memory")
#define CP_WAIT1()  asm volatile("cp.async.wait_group 1;"  ::: "memory")
#define CP_WAIT2()  asm volatile("cp.async.wait_group 2;"  ::: "memory")
#define CP_WAIT0()  asm volatile("cp.async.wait_group 0;"  ::: "memory")

__device__ __forceinline__ uint32_t hpack2(float x, float y) {
    __half2 t = __halves2half2(__float2half_rn(x), __float2half_rn(y));
    return *reinterpret_cast<uint32_t*>(&t);
}
__device__ __forceinline__ uint32_t ex2_f16x2(uint32_t x) {
    uint32_t r;
    asm("ex2.approx.f16x2 %0, %1;" : "=r"(r) : "r"(x));
    return r;
}

// ---------------------------------------------------------------------------
// fp32 -> fp16 convert (X)
// ---------------------------------------------------------------------------
__global__ void conv_x(const float* __restrict__ X, __half* __restrict__ Hi)
{
    size_t i = (size_t)blockIdx.x * blockDim.x + threadIdx.x;
    float4 v = ((const float4*)X)[i];
    ((uint2*)Hi)[i] = make_uint2(hpack2(v.x, v.y), hpack2(v.z, v.w));
}

// ---------------------------------------------------------------------------
// Transposed fp16 weights, coalesced __half2 stores (64k x 32n tiles, z = mat)
// ---------------------------------------------------------------------------
__global__ void conv_wT4(const float* __restrict__ W0, const float* __restrict__ W1,
                         const float* __restrict__ W2, const float* __restrict__ W3,
                         __half* __restrict__ Th)
{
    const float* W = blockIdx.z == 0 ? W0 : blockIdx.z == 1 ? W1
                   : blockIdx.z == 2 ? W2 : W3;
    __half* T = Th + (size_t)blockIdx.z * WSZ_;
    __shared__ float tile[64][33];
    const int tx = threadIdx.x, ty = threadIdx.y;     // 32 x 8
    int nx0 = blockIdx.x * 32;
    int ky0 = blockIdx.y * 64;
    #pragma unroll
    for (int i = 0; i < 8; ++i) {
        int kl = ty + i * 8;
        tile[kl][tx] = W[(size_t)(ky0 + kl) * D_ + nx0 + tx];
    }
    __syncthreads();
    #pragma unroll
    for (int i = 0; i < 4; ++i) {
        int nl = ty + i * 8;
        __half2 v = __floats2half2_rn(tile[tx * 2][nl], tile[tx * 2 + 1][nl]);
        *(__half2*)&T[(size_t)(nx0 + nl) * D_ + ky0 + tx * 2] = v;
    }
}

// ---------------------------------------------------------------------------
// Shared GEMM mainloop pieces (128x128 tile, K-chunk 64, 8 warps)
// ---------------------------------------------------------------------------
#define STAGE_STRIDE 32768u
#define PROJ_SMEM 67712

#define GEMM_PROLOGUE()                                                         \
    extern __shared__ char dyn[];                                               \
    uint32_t raw = smem_u32(dyn);                                               \
    uint32_t st  = (raw + 127u) & ~127u;                                        \
    char* stp    = dyn + (st - raw);                                            \
    const int tid = threadIdx.x, wid = tid >> 5, lane = tid & 31;               \
    const int n0 = blockIdx.x * 128, m0 = blockIdx.y * 128;                     \
    const int wm = wid & 1, wn = wid >> 1;                                      \
    const int lr = lane & 15;                                                   \
    uint32_t swk[4];                                                            \
    _Pragma("unroll")                                                           \
    for (int kk = 0; kk < 4; ++kk)                                              \
        swk[kk] = (uint32_t)((((kk * 2 + (lane >> 4)) ^ (lane & 7)) << 4));

#define GEMM_MAINLOOP(A_g, B_g)                                                 \
    auto load_chunk = [&](int c, int s) {                                       \
        uint32_t sb = st + (uint32_t)s * STAGE_STRIDE;                          \
        int k0 = c * 64;                                                        \
        _Pragma("unroll")                                                       \
        for (int j = 0; j < 4; ++j) {                                           \
            int q = tid + 256 * j, row = q >> 3, ch = q & 7;                    \
            cp_async16(sb + row * 128 + ((ch ^ (row & 7)) << 4),                \
                       (A_g) + (size_t)(m0 + row) * D_ + k0 + ch * 8);          \
        }                                                                       \
        _Pragma("unroll")                                                       \
        for (int j = 0; j < 4; ++j) {                                           \
            int q = tid + 256 * j, row = q >> 3, ch = q & 7;                    \
            cp_async16(sb + 16384u + row * 128 + ((ch ^ (row & 7)) << 4),       \
                       (B_g) + (size_t)(n0 + row) * D_ + k0 + ch * 8);          \
        }                                                                       \
        CP_COMMIT();                                                            \
    };                                                                          \
    float acc[4][4][4] = {};                                                    \
    load_chunk(0, 0);                                                           \
    load_chunk(1, 1);                                                           \
    for (int c = 0; c < 32; ++c) {                                              \
        CP_WAIT1();                                                             \
        __syncthreads();                                                        \
        uint32_t sb = st + (uint32_t)(c & 1) * STAGE_STRIDE;                    \
        uint32_t tA = sb, tB = sb + 16384u;                                     \
        _Pragma("unroll")                                                       \
        for (int kk = 0; kk < 4; ++kk) {                                        \
            uint32_t a4[4][4];                                                  \
            _Pragma("unroll")                                                   \
            for (int mi = 0; mi < 4; ++mi) {                                    \
                uint32_t ro = (uint32_t)((wm * 64 + mi * 16 + lr) * 128);       \
                ldsm4(a4[mi], tA + ro + swk[kk]);                               \
            }                                                                   \
            uint32_t b4[4][2];                                                  \
            _Pragma("unroll")                                                   \
            for (int nj = 0; nj < 2; ++nj) {                                    \
                uint32_t ro = (uint32_t)((wn * 32 + nj * 16 + lr) * 128);       \
                uint32_t r4[4];                                                 \
                ldsm4(r4, tB + ro + swk[kk]);                                   \
                b4[nj*2][0] = r4[0]; b4[nj*2][1] = r4[2];                       \
                b4[nj*2+1][0] = r4[1]; b4[nj*2+1][1] = r4[3];                   \
            }                                                                   \
            _Pragma("unroll")                                                   \
            for (int mi = 0; mi < 4; ++mi)                                      \
                _Pragma("unroll")                                               \
                for (int nb = 0; nb < 4; ++nb)                                  \
                    mma_f16(acc[mi][nb], a4[mi], b4[nb][0], b4[nb][1]);         \
        }                                                                       \
        __syncthreads();                                                        \
        if (c + 2 < 32) load_chunk(c + 2, c & 1);                               \
        else            CP_COMMIT();                                            \
    }                                                                           \
    CP_WAIT0();                                                                 \
    float* ftile = (float*)stp;                                                 \
    _Pragma("unroll")                                                           \
    for (int mi = 0; mi < 4; ++mi)                                              \
        _Pragma("unroll")                                                       \
        for (int nb = 0; nb < 4; ++nb) {                                        \
            int r  = wm * 64 + mi * 16 + (lane >> 2);                           \
            int cc = wn * 32 + nb * 8 + (lane & 3) * 2;                         \
            ftile[r * 132 + cc]           = acc[mi][nb][0];                     \
            ftile[r * 132 + cc + 1]       = acc[mi][nb][1];                     \
            ftile[(r + 8) * 132 + cc]     = acc[mi][nb][2];                     \
            ftile[(r + 8) * 132 + cc + 1] = acc[mi][nb][3];                     \
        }                                                                       \
    __syncthreads();

// ---------------------------------------------------------------------------
// Fused QKV projection: z=0 Q (split-head, QSCALE), z=1 K (split-head),
// z=2 V (transposed [BH][64][S])
// ---------------------------------------------------------------------------
__global__ void __launch_bounds__(256, 1) qkv_gemm(
    const __half* __restrict__ A_g, const __half* __restrict__ Wbase,
    const float* __restrict__ bq, const float* __restrict__ bk,
    const float* __restrict__ bv,
    __half* __restrict__ Oq, __half* __restrict__ Ok, __half* __restrict__ Ov)
{
    const int z = blockIdx.z;
    const __half* B_g = Wbase + (size_t)z * WSZ_;
    const float* bias = z == 0 ? bq : z == 1 ? bk : bv;

    GEMM_PROLOGUE();
    GEMM_MAINLOOP(A_g, B_g);

    if (z == 2) {
        const int lane4 = lane * 4;
        int bb = m0 >> 11;
        int s0 = (m0 & (S_ - 1)) + lane4;
        #pragma unroll
        for (int ii = 0; ii < 16; ++ii) {
            int nl = wid * 16 + ii;
            int n  = n0 + nl;
            float bvs = bias[n];
            int h = n >> 6, jj = n & 63;
            float v0 = ftile[(lane4 + 0) * 132 + nl] + bvs;
            float v1 = ftile[(lane4 + 1) * 132 + nl] + bvs;
            float v2 = ftile[(lane4 + 2) * 132 + nl] + bvs;
            float v3 = ftile[(lane4 + 3) * 132 + nl] + bvs;
            size_t base = ((size_t)(bb * H_ + h) * DH_ + jj) * S_ + s0;
            *(uint2*)&Ov[base] = make_uint2(hpack2(v0, v1), hpack2(v2, v3));
        }
    } else {
        const float scale = (z == 0) ? QSCALE : 1.0f;
        __half* O0 = (z == 0) ? Oq : Ok;
        const int c4 = (tid & 31) * 4;
        float4 bvv = *(const float4*)&bias[n0 + c4];
        #pragma unroll
        for (int i = 0; i < 16; ++i) {
            int r = (tid >> 5) + i * 8;
            float4 v = *(float4*)&ftile[r * 132 + c4];
            v.x = (v.x + bvv.x) * scale; v.y = (v.y + bvv.y) * scale;
            v.z = (v.z + bvv.z) * scale; v.w = (v.w + bvv.w) * scale;
            int m = m0 + r;
            int bidx = m >> 11, s = m & (S_ - 1);
            int n = n0 + c4, h = n >> 6, jj = n & 63;
            size_t base = (((size_t)(bidx * H_ + h) * S_) + s) * DH_ + jj;
            *(uint2*)&O0[base] = make_uint2(hpack2(v.x, v.y), hpack2(v.z, v.w));
        }
    }
}

// ---------------------------------------------------------------------------
// Output projection: fp32 dense out[M][2048]
// ---------------------------------------------------------------------------
__global__ void __launch_bounds__(256, 1) o_gemm(
    const __half* __restrict__ A_g, const __half* __restrict__ B_g,
    const float* __restrict__ bias, float* __restrict__ out)
{
    GEMM_PROLOGUE();
    GEMM_MAINLOOP(A_g, B_g);

    const int c4 = (tid & 31) * 4;
    float4 bv = *(const float4*)&bias[n0 + c4];
    #pragma unroll
    for (int i = 0; i < 16; ++i) {
        int r = (tid >> 5) + i * 8;
        float4 v = *(float4*)&ftile[r * 132 + c4];
        v.x += bv.x; v.y += bv.y; v.z += bv.z; v.w += bv.w;
        *(float4*)&out[(size_t)(m0 + r) * D_ + n0 + c4] = v;
    }
}

// ---------------------------------------------------------------------------
// Fused attention, 64-key half-tiles for 2 CTAs/SM occupancy.
// Log2-domain softmax in f16x2, MMA-based row sums, ex2 fused into PV loop.
// ---------------------------------------------------------------------------
#define ATTN_SMEM 82048   // Q 16KB + 2 stages x (K 16KB + V^T 16KB)
#define ONES_F16X2 0x3C003C00u

__global__ void __launch_bounds__(256, 2) attn_fused(
    const __half* __restrict__ Qh, const __half* __restrict__ Kh,
    const __half* __restrict__ Vt, __half* __restrict__ Ch)
{
    extern __shared__ char dyn[];
    uint32_t raw = smem_u32(dyn);
    uint32_t st  = (raw + 127u) & ~127u;

    const int tid = threadIdx.x, wid = tid >> 5, lane = tid & 31;
    const int lr  = lane & 15;
    const int bh  = blockIdx.y;
    const int m0  = blockIdx.x * 128;

    uint32_t swk[4];
    #pragma unroll
    for (int kk = 0; kk < 4; ++kk)
        swk[kk] = (uint32_t)((((kk * 2 + (lane >> 4)) ^ (lane & 7)) << 4));

    const __half* Qh_b = Qh + ((size_t)bh * S_ + m0) * DH_;
    const __half* Kh_b = Kh + (size_t)bh * S_ * DH_;
    const __half* Vt_b = Vt + (size_t)bh * DH_ * S_;

    const uint32_t QH  = st;
    const uint32_t ST0 = st + 16384u;

    #pragma unroll
    for (int j = 0; j < 4; ++j) {
        int q = tid + 256 * j, row = q >> 3, ch = q & 7;
        cp_async16(QH + row * 128 + ((ch ^ (row & 7)) << 4),
                   Qh_b + (size_t)row * DH_ + ch * 8);
    }
    CP_COMMIT();

    auto load_kv = [&](int i, int s) {
        uint32_t kb = ST0 + (uint32_t)s * 32768u;
        uint32_t vb = kb + 16384u;
        #pragma unroll
        for (int j = 0; j < 4; ++j) {
            int q = tid + 256 * j, row = q >> 3, ch = q & 7;
            cp_async16(kb + row * 128 + ((ch ^ (row & 7)) << 4),
                       Kh_b + (size_t)(i * 128 + row) * DH_ + ch * 8);
        }
        #pragma unroll
        for (int sub = 0; sub < 2; ++sub)
            #pragma unroll
            for (int j = 0; j < 2; ++j) {
                int q = tid + 256 * j, row = q >> 3, ch = q & 7;  // row 0..63
                cp_async16(vb + sub * 8192 + row * 128 + ((ch ^ (row & 7)) << 4),
                           Vt_b + (size_t)row * S_ + i * 128 + sub * 64 + ch * 8);
            }
        CP_COMMIT();
    };
    load_kv(0, 0);
    load_kv(1, 1);

    CP_WAIT2();
    __syncthreads();
    uint32_t qa[4][4];
    #pragma unroll
    for (int kk = 0; kk < 4; ++kk) {
        uint32_t ro = (uint32_t)((wid * 16 + lr) * 128);
        ldsm4(qa[kk], QH + ro + swk[kk]);
    }

    float cAcc[8][4] = {};
    float sumA[4] = {};
    float mA = -1e30f, mB = -1e30f;

    for (int i = 0; i < 16; ++i) {
        CP_WAIT1();
        __syncthreads();
        uint32_t kb = ST0 + (uint32_t)(i & 1) * 32768u;
        uint32_t vb = kb + 16384u;

        #pragma unroll
        for (int hf = 0; hf < 2; ++hf) {
            // --- QK^T over 64 keys ---
            float sAcc[8][4] = {};
            #pragma unroll
            for (int kk = 0; kk < 4; ++kk) {
                uint32_t bK[8][2];
                #pragma unroll
                for (int g = 0; g < 4; ++g) {
                    uint32_t r4[4];
                    ldsm4(r4, kb + (uint32_t)((hf * 64 + g * 16 + lr) * 128) + swk[kk]);
                    bK[2*g][0]   = r4[0]; bK[2*g][1]   = r4[2];
                    bK[2*g+1][0] = r4[1]; bK[2*g+1][1] = r4[3];
                }
                #pragma unroll
                for (int nt = 0; nt < 8; ++nt)
                    mma_f16(sAcc[nt], qa[kk], bK[nt][0], bK[nt][1]);
            }

            // --- running max (fp16-rounded) + rescale ---
            float rA = -1e30f, rB = -1e30f;
            #pragma unroll
            for (int nt = 0; nt < 8; ++nt) {
                rA = fmaxf(rA, fmaxf(sAcc[nt][0], sAcc[nt][1]));
                rB = fmaxf(rB, fmaxf(sAcc[nt][2], sAcc[nt][3]));
            }
            rA = fmaxf(rA, __shfl_xor_sync(0xffffffffu, rA, 1));
            rA = fmaxf(rA, __shfl_xor_sync(0xffffffffu, rA, 2));
            rB = fmaxf(rB, __shfl_xor_sync(0xffffffffu, rB, 1));
            rB = fmaxf(rB, __shfl_xor_sync(0xffffffffu, rB, 2));
            __half mhA = __float2half_rn(fmaxf(mA, rA));
            __half mhB = __float2half_rn(fmaxf(mB, rB));
            float mnA = __half2float(mhA), mnB = __half2float(mhB);
            float esA = exp2f(mA - mnA), esB = exp2f(mB - mnB);
            mA = mnA; mB = mnB;
            __half2 mA2 = __halves2half2(mhA, mhA);
            __half2 mB2 = __halves2half2(mhB, mhB);

            #pragma unroll
            for (int nb = 0; nb < 8; ++nb) {
                cAcc[nb][0] *= esA; cAcc[nb][1] *= esA;
                cAcc[nb][2] *= esB; cAcc[nb][3] *= esB;
            }
            sumA[0] *= esA; sumA[1] *= esA; sumA[2] *= esB; sumA[3] *= esB;

            // --- PV over this half: ex2 fused, ones-column row sums ---
            uint32_t vsb = vb + (uint32_t)hf * 8192u;
            #pragma unroll
            for (int kt = 0; kt < 4; ++kt) {
                uint32_t pa[4];
                {
                    __half2 a0 = __hsub2(__floats2half2_rn(sAcc[2*kt][0],   sAcc[2*kt][1]),   mA2);
                    __half2 b0 = __hsub2(__floats2half2_rn(sAcc[2*kt][2],   sAcc[2*kt][3]),   mB2);
                    __half2 a1 = __hsub2(__floats2half2_rn(sAcc[2*kt+1][0], sAcc[2*kt+1][1]), mA2);
                    __half2 b1 = __hsub2(__floats2half2_rn(sAcc[2*kt+1][2], sAcc[2*kt+1][3]), mB2);
                    pa[0] = ex2_f16x2(*reinterpret_cast<uint32_t*>(&a0));
                    pa[1] = ex2_f16x2(*reinterpret_cast<uint32_t*>(&b0));
                    pa[2] = ex2_f16x2(*reinterpret_cast<uint32_t*>(&a1));
                    pa[3] = ex2_f16x2(*reinterpret_cast<uint32_t*>(&b1));
                }
                uint32_t bV[8][2];
                #pragma unroll
                for (int g = 0; g < 4; ++g) {
                    uint32_t r4[4];
                    ldsm4(r4, vsb + (uint32_t)((g * 16 + lr) * 128) + swk[kt]);
                    bV[2*g][0]   = r4[0]; bV[2*g][1]   = r4[2];
                    bV[2*g+1][0] = r4[1]; bV[2*g+1][1] = r4[3];
                }
                #pragma unroll
                for (int nb = 0; nb < 8; ++nb)
                    mma_f16(cAcc[nb], pa, bV[nb][0], bV[nb][1]);
                mma_f16(sumA, pa, ONES_F16X2, ONES_F16X2);
            }
        }

        __syncthreads();
        if (i + 2 < 16) load_kv(i + 2, i & 1);
        else            CP_COMMIT();
    }

    // epilogue: normalize by MMA row sums, fp16 ctx into [M][2048]
    const int b = bh >> 5, h = bh & 31;
    float iA = 1.0f / sumA[0], iB = 1.0f / sumA[2];
    int rA_ = m0 + wid * 16 + (lane >> 2);
    int rB_ = rA_ + 8;
    #pragma unroll
    for (int nb = 0; nb < 8; ++nb) {
        int c = nb * 8 + (lane & 3) * 2;
        size_t ia = ((size_t)(b * S_) + rA_) * D_ + h * DH_ + c;
        size_t ib = ((size_t)(b * S_) + rB_) * D_ + h * DH_ + c;
        *(uint32_t*)&Ch[ia] = hpack2(cAcc[nb][0] * iA, cAcc[nb][1] * iA);
        *(uint32_t*)&Ch[ib] = hpack2(cAcc[nb][2] * iB, cAcc[nb][3] * iB);
    }
}

// ---------------------------------------------------------------------------
extern "C" void kernel_launch(void* const* d_in, const int* in_sizes, int n_in,
                              void* d_out, int out_size)
{
    const float* X  = (const float*)d_in[0];
    const float* Wq = (const float*)d_in[1];
    const float* bq = (const float*)d_in[2];
    const float* Wk = (const float*)d_in[3];
    const float* bk = (const float*)d_in[4];
    const float* Wv = (const float*)d_in[5];
    const float* bv = (const float*)d_in[6];
    const float* Wo = (const float*)d_in[7];
    const float* bo = (const float*)d_in[8];
    float* out = (float*)d_out;

    __half *xh, *wh, *qh, *kh, *vth;
    cudaGetSymbolAddress((void**)&xh,  g_xh);
    cudaGetSymbolAddress((void**)&wh,  g_wh);
    cudaGetSymbolAddress((void**)&qh,  g_qh);
    cudaGetSymbolAddress((void**)&kh,  g_kh);
    cudaGetSymbolAddress((void**)&vth, g_vth);

    static bool attr_done = false;
    if (!attr_done) {
        cudaFuncSetAttribute(qkv_gemm,   cudaFuncAttributeMaxDynamicSharedMemorySize, PROJ_SMEM);
        cudaFuncSetAttribute(o_gemm,     cudaFuncAttributeMaxDynamicSharedMemorySize, PROJ_SMEM);
        cudaFuncSetAttribute(attn_fused, cudaFuncAttributeMaxDynamicSharedMemorySize, ATTN_SMEM);
        attr_done = true;
    }

    // conversions
    conv_x<<<(M_ * (size_t)D_) / 1024, 256>>>(X, xh);
    dim3 tblk(32, 8), tgrid(D_ / 32, D_ / 64, 4);
    conv_wT4<<<tgrid, tblk>>>(Wq, Wk, Wv, Wo, wh);

    // fused QKV projections (one launch, 1536 CTAs)
    dim3 pblk(256), qgrid(D_ / 128, M_ / 128, 3);   // (16, 32, 3)
    qkv_gemm<<<qgrid, pblk, PROJ_SMEM>>>(xh, wh, bq, bk, bv, qh, kh, vth);

    // fused attention: ctx fp16 -> xh
    dim3 agrid(S_ / 128, BH_);                      // (16, 64)
    attn_fused<<<agrid, pblk, ATTN_SMEM>>>(qh, kh, vth, xh);

    // output projection
    dim3 ogrid(D_ / 128, M_ / 128);                 // (16, 32)
    o_gemm<<<ogrid, pblk, PROJ_SMEM>>>(xh, wh + 3 * WSZ_, bo, out);
}

// round 10
// speedup vs baseline: 10.3952x; 1.0023x over previous
#include <cuda_runtime.h>
#include <cuda_fp16.h>
#include <cstdint>

#define B_   2
#define S_   2048
#define D_   2048
#define H_   32
#define DH_  64
#define M_   (B_*S_)    // 4096
#define BH_  (B_*H_)    // 64
#define WSZ_ ((size_t)D_*D_)

// Q pre-scale: (1/sqrt(64)) * log2(e)  -> scores land in log2 domain
#define QSCALE 0.18033688011112042f

// ---------------------------------------------------------------------------
// Scratch
// ---------------------------------------------------------------------------
__device__ __half g_xh[(size_t)M_*D_];         // X fp16 (later ctx fp16)
__device__ __half g_wh[(size_t)4*D_*D_];       // Wt fp16 [N][K] (4 mats)
__device__ __half g_qh[(size_t)M_*D_];         // Q fp16 [BH][S][64] (log2-scaled)
__device__ __half g_kh[(size_t)M_*D_];         // K fp16 [BH][S][64]
__device__ __half g_vth[(size_t)M_*D_];        // V^T fp16 [BH][64][S]

// ---------------------------------------------------------------------------
// Baseline-PTX primitives
// ---------------------------------------------------------------------------
__device__ __forceinline__ uint32_t smem_u32(const void* p) {
    uint32_t a;
    asm("{ .reg .u64 t; cvta.to.shared.u64 t, %1; cvt.u32.u64 %0, t; }" : "=r"(a) : "l"(p));
    return a;
}
__device__ __forceinline__ void ldsm4(uint32_t* r, uint32_t a) {
    asm volatile("ldmatrix.sync.aligned.m8n8.x4.shared.b16 {%0,%1,%2,%3}, [%4];"
                 : "=r"(r[0]), "=r"(r[1]), "=r"(r[2]), "=r"(r[3]) : "r"(a));
}
__device__ __forceinline__ void mma_f16(float* d, const uint32_t* a,
                                        uint32_t b0, uint32_t b1) {
    asm volatile("mma.sync.aligned.m16n8k16.row.col.f32.f16.f16.f32 "
                 "{%0,%1,%2,%3}, {%4,%5,%6,%7}, {%8,%9}, {%0,%1,%2,%3};"
                 : "+f"(d[0]), "+f"(d[1]), "+f"(d[2]), "+f"(d[3])
                 : "r"(a[0]), "r"(a[1]), "r"(a[2]), "r"(a[3]), "r"(b0), "r"(b1));
}
__device__ __forceinline__ void cp_async16(uint32_t dst, const void* src) {
    asm volatile("cp.async.cg.shared.global [%0], [%1], 16;" :: "r"(dst), "l"(src));
}
#define CP_COMMIT() asm volatile("cp.async.commit_group;" ::: "memory")
#define CP_WAIT1()  asm volatile("cp.async.wait_group 1;"  ::: "memory")
#define CP_WAIT2()  asm volatile("cp.async.wait_group 2;"  ::: "memory")
#define CP_WAIT0()  asm volatile("cp.async.wait_group 0;"  ::: "memory")

__device__ __forceinline__ uint32_t hpack2(float x, float y) {
    __half2 t = __halves2half2(__float2half_rn(x), __float2half_rn(y));
    return *reinterpret_cast<uint32_t*>(&t);
}
__device__ __forceinline__ uint32_t ex2_f16x2(uint32_t x) {
    uint32_t r;
    asm("ex2.approx.f16x2 %0, %1;" : "=r"(r) : "r"(x));
    return r;
}

// ---------------------------------------------------------------------------
// fp32 -> fp16 convert (X)
// ---------------------------------------------------------------------------
__global__ void conv_x(const float* __restrict__ X, __half* __restrict__ Hi)
{
    size_t i = (size_t)blockIdx.x * blockDim.x + threadIdx.x;
    float4 v = ((const float4*)X)[i];
    ((uint2*)Hi)[i] = make_uint2(hpack2(v.x, v.y), hpack2(v.z, v.w));
}

// ---------------------------------------------------------------------------
// Transposed fp16 weights, coalesced __half2 stores (64k x 32n tiles, z = mat)
// ---------------------------------------------------------------------------
__global__ void conv_wT4(const float* __restrict__ W0, const float* __restrict__ W1,
                         const float* __restrict__ W2, const float* __restrict__ W3,
                         __half* __restrict__ Th)
{
    const float* W = blockIdx.z == 0 ? W0 : blockIdx.z == 1 ? W1
                   : blockIdx.z == 2 ? W2 : W3;
    __half* T = Th + (size_t)blockIdx.z * WSZ_;
    __shared__ float tile[64][33];
    const int tx = threadIdx.x, ty = threadIdx.y;     // 32 x 8
    int nx0 = blockIdx.x * 32;
    int ky0 = blockIdx.y * 64;
    #pragma unroll
    for (int i = 0; i < 8; ++i) {
        int kl = ty + i * 8;
        tile[kl][tx] = W[(size_t)(ky0 + kl) * D_ + nx0 + tx];
    }
    __syncthreads();
    #pragma unroll
    for (int i = 0; i < 4; ++i) {
        int nl = ty + i * 8;
        __half2 v = __floats2half2_rn(tile[tx * 2][nl], tile[tx * 2 + 1][nl]);
        *(__half2*)&T[(size_t)(nx0 + nl) * D_ + ky0 + tx * 2] = v;
    }
}

// ---------------------------------------------------------------------------
// Shared GEMM mainloop pieces (128x128 tile, K-chunk 64, 8 warps)
// ---------------------------------------------------------------------------
#define STAGE_STRIDE 32768u
#define PROJ_SMEM 67712

#define GEMM_PROLOGUE()                                                         \
    extern __shared__ char dyn[];                                               \
    uint32_t raw = smem_u32(dyn);                                               \
    uint32_t st  = (raw + 127u) & ~127u;                                        \
    char* stp    = dyn + (st - raw);                                            \
    const int tid = threadIdx.x, wid = tid >> 5, lane = tid & 31;               \
    const int n0 = blockIdx.x * 128, m0 = blockIdx.y * 128;                     \
    const int wm = wid & 1, wn = wid >> 1;                                      \
    const int lr = lane & 15;                                                   \
    uint32_t swk[4];                                                            \
    _Pragma("unroll")                                                           \
    for (int kk = 0; kk < 4; ++kk)                                              \
        swk[kk] = (uint32_t)((((kk * 2 + (lane >> 4)) ^ (lane & 7)) << 4));

#define GEMM_MAINLOOP(A_g, B_g)                                                 \
    auto load_chunk = [&](int c, int s) {                                       \
        uint32_t sb = st + (uint32_t)s * STAGE_STRIDE;                          \
        int k0 = c * 64;                                                        \
        _Pragma("unroll")                                                       \
        for (int j = 0; j < 4; ++j) {                                           \
            int q = tid + 256 * j, row = q >> 3, ch = q & 7;                    \
            cp_async16(sb + row * 128 + ((ch ^ (row & 7)) << 4),                \
                       (A_g) + (size_t)(m0 + row) * D_ + k0 + ch * 8);          \
        }                                                                       \
        _Pragma("unroll")                                                       \
        for (int j = 0; j < 4; ++j) {                                           \
            int q = tid + 256 * j, row = q >> 3, ch = q & 7;                    \
            cp_async16(sb + 16384u + row * 128 + ((ch ^ (row & 7)) << 4),       \
                       (B_g) + (size_t)(n0 + row) * D_ + k0 + ch * 8);          \
        }                                                                       \
        CP_COMMIT();                                                            \
    };                                                                          \
    float acc[4][4][4] = {};                                                    \
    load_chunk(0, 0);                                                           \
    load_chunk(1, 1);                                                           \
    for (int c = 0; c < 32; ++c) {                                              \
        CP_WAIT1();                                                             \
        __syncthreads();                                                        \
        uint32_t sb = st + (uint32_t)(c & 1) * STAGE_STRIDE;                    \
        uint32_t tA = sb, tB = sb + 16384u;                                     \
        _Pragma("unroll")                                                       \
        for (int kk = 0; kk < 4; ++kk) {                                        \
            uint32_t a4[4][4];                                                  \
            _Pragma("unroll")                                                   \
            for (int mi = 0; mi < 4; ++mi) {                                    \
                uint32_t ro = (uint32_t)((wm * 64 + mi * 16 + lr) * 128);       \
                ldsm4(a4[mi], tA + ro + swk[kk]);                               \
            }                                                                   \
            uint32_t b4[4][2];                                                  \
            _Pragma("unroll")                                                   \
            for (int nj = 0; nj < 2; ++nj) {                                    \
                uint32_t ro = (uint32_t)((wn * 32 + nj * 16 + lr) * 128);       \
                uint32_t r4[4];                                                 \
                ldsm4(r4, tB + ro + swk[kk]);                                   \
                b4[nj*2][0] = r4[0]; b4[nj*2][1] = r4[2];                       \
                b4[nj*2+1][0] = r4[1]; b4[nj*2+1][1] = r4[3];                   \
            }                                                                   \
            _Pragma("unroll")                                                   \
            for (int mi = 0; mi < 4; ++mi)                                      \
                _Pragma("unroll")                                               \
                for (int nb = 0; nb < 4; ++nb)                                  \
                    mma_f16(acc[mi][nb], a4[mi], b4[nb][0], b4[nb][1]);         \
        }                                                                       \
        __syncthreads();                                                        \
        if (c + 2 < 32) load_chunk(c + 2, c & 1);                               \
        else            CP_COMMIT();                                            \
    }                                                                           \
    CP_WAIT0();                                                                 \
    float* ftile = (float*)stp;                                                 \
    _Pragma("unroll")                                                           \
    for (int mi = 0; mi < 4; ++mi)                                              \
        _Pragma("unroll")                                                       \
        for (int nb = 0; nb < 4; ++nb) {                                        \
            int r  = wm * 64 + mi * 16 + (lane >> 2);                           \
            int cc = wn * 32 + nb * 8 + (lane & 3) * 2;                         \
            ftile[r * 132 + cc]           = acc[mi][nb][0];                     \
            ftile[r * 132 + cc + 1]       = acc[mi][nb][1];                     \
            ftile[(r + 8) * 132 + cc]     = acc[mi][nb][2];                     \
            ftile[(r + 8) * 132 + cc + 1] = acc[mi][nb][3];                     \
        }                                                                       \
    __syncthreads();

// ---------------------------------------------------------------------------
// Fused QKV projection: z=0 Q (split-head, QSCALE), z=1 K (split-head),
// z=2 V (transposed [BH][64][S]).  2 CTAs/SM (reg cap 128).
// ---------------------------------------------------------------------------
__global__ void __launch_bounds__(256, 2) qkv_gemm(
    const __half* __restrict__ A_g, const __half* __restrict__ Wbase,
    const float* __restrict__ bq, const float* __restrict__ bk,
    const float* __restrict__ bv,
    __half* __restrict__ Oq, __half* __restrict__ Ok, __half* __restrict__ Ov)
{
    const int z = blockIdx.z;
    const __half* B_g = Wbase + (size_t)z * WSZ_;
    const float* bias = z == 0 ? bq : z == 1 ? bk : bv;

    GEMM_PROLOGUE();
    GEMM_MAINLOOP(A_g, B_g);

    if (z == 2) {
        const int lane4 = lane * 4;
        int bb = m0 >> 11;
        int s0 = (m0 & (S_ - 1)) + lane4;
        #pragma unroll
        for (int ii = 0; ii < 16; ++ii) {
            int nl = wid * 16 + ii;
            int n  = n0 + nl;
            float bvs = bias[n];
            int h = n >> 6, jj = n & 63;
            float v0 = ftile[(lane4 + 0) * 132 + nl] + bvs;
            float v1 = ftile[(lane4 + 1) * 132 + nl] + bvs;
            float v2 = ftile[(lane4 + 2) * 132 + nl] + bvs;
            float v3 = ftile[(lane4 + 3) * 132 + nl] + bvs;
            size_t base = ((size_t)(bb * H_ + h) * DH_ + jj) * S_ + s0;
            *(uint2*)&Ov[base] = make_uint2(hpack2(v0, v1), hpack2(v2, v3));
        }
    } else {
        const float scale = (z == 0) ? QSCALE : 1.0f;
        __half* O0 = (z == 0) ? Oq : Ok;
        const int c4 = (tid & 31) * 4;
        float4 bvv = *(const float4*)&bias[n0 + c4];
        #pragma unroll
        for (int i = 0; i < 16; ++i) {
            int r = (tid >> 5) + i * 8;
            float4 v = *(float4*)&ftile[r * 132 + c4];
            v.x = (v.x + bvv.x) * scale; v.y = (v.y + bvv.y) * scale;
            v.z = (v.z + bvv.z) * scale; v.w = (v.w + bvv.w) * scale;
            int m = m0 + r;
            int bidx = m >> 11, s = m & (S_ - 1);
            int n = n0 + c4, h = n >> 6, jj = n & 63;
            size_t base = (((size_t)(bidx * H_ + h) * S_) + s) * DH_ + jj;
            *(uint2*)&O0[base] = make_uint2(hpack2(v.x, v.y), hpack2(v.z, v.w));
        }
    }
}

// ---------------------------------------------------------------------------
// Output projection: fp32 dense out[M][2048].  2 CTAs/SM (reg cap 128).
// ---------------------------------------------------------------------------
__global__ void __launch_bounds__(256, 2) o_gemm(
    const __half* __restrict__ A_g, const __half* __restrict__ B_g,
    const float* __restrict__ bias, float* __restrict__ out)
{
    GEMM_PROLOGUE();
    GEMM_MAINLOOP(A_g, B_g);

    const int c4 = (tid & 31) * 4;
    float4 bv = *(const float4*)&bias[n0 + c4];
    #pragma unroll
    for (int i = 0; i < 16; ++i) {
        int r = (tid >> 5) + i * 8;
        float4 v = *(float4*)&ftile[r * 132 + c4];
        v.x += bv.x; v.y += bv.y; v.z += bv.z; v.w += bv.w;
        *(float4*)&out[(size_t)(m0 + r) * D_ + n0 + c4] = v;
    }
}

// ---------------------------------------------------------------------------
// Fused attention, 64-key half-tiles, 2 CTAs/SM.
// Log2-domain softmax in f16x2, MMA-based row sums, ex2 fused into PV loop.
// ---------------------------------------------------------------------------
#define ATTN_SMEM 82048   // Q 16KB + 2 stages x (K 16KB + V^T 16KB)
#define ONES_F16X2 0x3C003C00u

__global__ void __launch_bounds__(256, 2) attn_fused(
    const __half* __restrict__ Qh, const __half* __restrict__ Kh,
    const __half* __restrict__ Vt, __half* __restrict__ Ch)
{
    extern __shared__ char dyn[];
    uint32_t raw = smem_u32(dyn);
    uint32_t st  = (raw + 127u) & ~127u;

    const int tid = threadIdx.x, wid = tid >> 5, lane = tid & 31;
    const int lr  = lane & 15;
    const int bh  = blockIdx.y;
    const int m0  = blockIdx.x * 128;

    uint32_t swk[4];
    #pragma unroll
    for (int kk = 0; kk < 4; ++kk)
        swk[kk] = (uint32_t)((((kk * 2 + (lane >> 4)) ^ (lane & 7)) << 4));

    const __half* Qh_b = Qh + ((size_t)bh * S_ + m0) * DH_;
    const __half* Kh_b = Kh + (size_t)bh * S_ * DH_;
    const __half* Vt_b = Vt + (size_t)bh * DH_ * S_;

    const uint32_t QH  = st;
    const uint32_t ST0 = st + 16384u;

    #pragma unroll
    for (int j = 0; j < 4; ++j) {
        int q = tid + 256 * j, row = q >> 3, ch = q & 7;
        cp_async16(QH + row * 128 + ((ch ^ (row & 7)) << 4),
                   Qh_b + (size_t)row * DH_ + ch * 8);
    }
    CP_COMMIT();

    auto load_kv = [&](int i, int s) {
        uint32_t kb = ST0 + (uint32_t)s * 32768u;
        uint32_t vb = kb + 16384u;
        #pragma unroll
        for (int j = 0; j < 4; ++j) {
            int q = tid + 256 * j, row = q >> 3, ch = q & 7;
            cp_async16(kb + row * 128 + ((ch ^ (row & 7)) << 4),
                       Kh_b + (size_t)(i * 128 + row) * DH_ + ch * 8);
        }
        #pragma unroll
        for (int sub = 0; sub < 2; ++sub)
            #pragma unroll
            for (int j = 0; j < 2; ++j) {
                int q = tid + 256 * j, row = q >> 3, ch = q & 7;  // row 0..63
                cp_async16(vb + sub * 8192 + row * 128 + ((ch ^ (row & 7)) << 4),
                           Vt_b + (size_t)row * S_ + i * 128 + sub * 64 + ch * 8);
            }
        CP_COMMIT();
    };
    load_kv(0, 0);
    load_kv(1, 1);

    CP_WAIT2();
    __syncthreads();
    uint32_t qa[4][4];
    #pragma unroll
    for (int kk = 0; kk < 4; ++kk) {
        uint32_t ro = (uint32_t)((wid * 16 + lr) * 128);
        ldsm4(qa[kk], QH + ro + swk[kk]);
    }

    float cAcc[8][4] = {};
    float sumA[4] = {};
    float mA = -1e30f, mB = -1e30f;

    for (int i = 0; i < 16; ++i) {
        CP_WAIT1();
        __syncthreads();
        uint32_t kb = ST0 + (uint32_t)(i & 1) * 32768u;
        uint32_t vb = kb + 16384u;

        #pragma unroll
        for (int hf = 0; hf < 2; ++hf) {
            float sAcc[8][4] = {};
            #pragma unroll
            for (int kk = 0; kk < 4; ++kk) {
                uint32_t bK[8][2];
                #pragma unroll
                for (int g = 0; g < 4; ++g) {
                    uint32_t r4[4];
                    ldsm4(r4, kb + (uint32_t)((hf * 64 + g * 16 + lr) * 128) + swk[kk]);
                    bK[2*g][0]   = r4[0]; bK[2*g][1]   = r4[2];
                    bK[2*g+1][0] = r4[1]; bK[2*g+1][1] = r4[3];
                }
                #pragma unroll
                for (int nt = 0; nt < 8; ++nt)
                    mma_f16(sAcc[nt], qa[kk], bK[nt][0], bK[nt][1]);
            }

            float rA = -1e30f, rB = -1e30f;
            #pragma unroll
            for (int nt = 0; nt < 8; ++nt) {
                rA = fmaxf(rA, fmaxf(sAcc[nt][0], sAcc[nt][1]));
                rB = fmaxf(rB, fmaxf(sAcc[nt][2], sAcc[nt][3]));
            }
            rA = fmaxf(rA, __shfl_xor_sync(0xffffffffu, rA, 1));
            rA = fmaxf(rA, __shfl_xor_sync(0xffffffffu, rA, 2));
            rB = fmaxf(rB, __shfl_xor_sync(0xffffffffu, rB, 1));
            rB = fmaxf(rB, __shfl_xor_sync(0xffffffffu, rB, 2));
            __half mhA = __float2half_rn(fmaxf(mA, rA));
            __half mhB = __float2half_rn(fmaxf(mB, rB));
            float mnA = __half2float(mhA), mnB = __half2float(mhB);
            float esA = exp2f(mA - mnA), esB = exp2f(mB - mnB);
            mA = mnA; mB = mnB;
            __half2 mA2 = __halves2half2(mhA, mhA);
            __half2 mB2 = __halves2half2(mhB, mhB);

            #pragma unroll
            for (int nb = 0; nb < 8; ++nb) {
                cAcc[nb][0] *= esA; cAcc[nb][1] *= esA;
                cAcc[nb][2] *= esB; cAcc[nb][3] *= esB;
            }
            sumA[0] *= esA; sumA[1] *= esA; sumA[2] *= esB; sumA[3] *= esB;

            uint32_t vsb = vb + (uint32_t)hf * 8192u;
            #pragma unroll
            for (int kt = 0; kt < 4; ++kt) {
                uint32_t pa[4];
                {
                    __half2 a0 = __hsub2(__floats2half2_rn(sAcc[2*kt][0],   sAcc[2*kt][1]),   mA2);
                    __half2 b0 = __hsub2(__floats2half2_rn(sAcc[2*kt][2],   sAcc[2*kt][3]),   mB2);
                    __half2 a1 = __hsub2(__floats2half2_rn(sAcc[2*kt+1][0], sAcc[2*kt+1][1]), mA2);
                    __half2 b1 = __hsub2(__floats2half2_rn(sAcc[2*kt+1][2], sAcc[2*kt+1][3]), mB2);
                    pa[0] = ex2_f16x2(*reinterpret_cast<uint32_t*>(&a0));
                    pa[1] = ex2_f16x2(*reinterpret_cast<uint32_t*>(&b0));
                    pa[2] = ex2_f16x2(*reinterpret_cast<uint32_t*>(&a1));
                    pa[3] = ex2_f16x2(*reinterpret_cast<uint32_t*>(&b1));
                }
                uint32_t bV[8][2];
                #pragma unroll
                for (int g = 0; g < 4; ++g) {
                    uint32_t r4[4];
                    ldsm4(r4, vsb + (uint32_t)((g * 16 + lr) * 128) + swk[kt]);
                    bV[2*g][0]   = r4[0]; bV[2*g][1]   = r4[2];
                    bV[2*g+1][0] = r4[1]; bV[2*g+1][1] = r4[3];
                }
                #pragma unroll
                for (int nb = 0; nb < 8; ++nb)
                    mma_f16(cAcc[nb], pa, bV[nb][0], bV[nb][1]);
                mma_f16(sumA, pa, ONES_F16X2, ONES_F16X2);
            }
        }

        __syncthreads();
        if (i + 2 < 16) load_kv(i + 2, i & 1);
        else            CP_COMMIT();
    }

    const int b = bh >> 5, h = bh & 31;
    float iA = 1.0f / sumA[0], iB = 1.0f / sumA[2];
    int rA_ = m0 + wid * 16 + (lane >> 2);
    int rB_ = rA_ + 8;
    #pragma unroll
    for (int nb = 0; nb < 8; ++nb) {
        int c = nb * 8 + (lane & 3) * 2;
        size_t ia = ((size_t)(b * S_) + rA_) * D_ + h * DH_ + c;
        size_t ib = ((size_t)(b * S_) + rB_) * D_ + h * DH_ + c;
        *(uint32_t*)&Ch[ia] = hpack2(cAcc[nb][0] * iA, cAcc[nb][1] * iA);
        *(uint32_t*)&Ch[ib] = hpack2(cAcc[nb][2] * iB, cAcc[nb][3] * iB);
    }
}

// ---------------------------------------------------------------------------
extern "C" void kernel_launch(void* const* d_in, const int* in_sizes, int n_in,
                              void* d_out, int out_size)
{
    const float* X  = (const float*)d_in[0];
    const float* Wq = (const float*)d_in[1];
    const float* bq = (const float*)d_in[2];
    const float* Wk = (const float*)d_in[3];
    const float* bk = (const float*)d_in[4];
    const float* Wv = (const float*)d_in[5];
    const float* bv = (const float*)d_in[6];
    const float* Wo = (const float*)d_in[7];
    const float* bo = (const float*)d_in[8];
    float* out = (float*)d_out;

    __half *xh, *wh, *qh, *kh, *vth;
    cudaGetSymbolAddress((void**)&xh,  g_xh);
    cudaGetSymbolAddress((void**)&wh,  g_wh);
    cudaGetSymbolAddress((void**)&qh,  g_qh);
    cudaGetSymbolAddress((void**)&kh,  g_kh);
    cudaGetSymbolAddress((void**)&vth, g_vth);

    static bool attr_done = false;
    if (!attr_done) {
        cudaFuncSetAttribute(qkv_gemm,   cudaFuncAttributeMaxDynamicSharedMemorySize, PROJ_SMEM);
        cudaFuncSetAttribute(o_gemm,     cudaFuncAttributeMaxDynamicSharedMemorySize, PROJ_SMEM);
        cudaFuncSetAttribute(attn_fused, cudaFuncAttributeMaxDynamicSharedMemorySize, ATTN_SMEM);
        attr_done = true;
    }

    // conversions
    conv_x<<<(M_ * (size_t)D_) / 1024, 256>>>(X, xh);
    dim3 tblk(32, 8), tgrid(D_ / 32, D_ / 64, 4);
    conv_wT4<<<tgrid, tblk>>>(Wq, Wk, Wv, Wo, wh);

    // fused QKV projections (one launch, 1536 CTAs, 2 CTAs/SM)
    dim3 pblk(256), qgrid(D_ / 128, M_ / 128, 3);   // (16, 32, 3)
    qkv_gemm<<<qgrid, pblk, PROJ_SMEM>>>(xh, wh, bq, bk, bv, qh, kh, vth);

    // fused attention: ctx fp16 -> xh
    dim3 agrid(S_ / 128, BH_);                      // (16, 64)
    attn_fused<<<agrid, pblk, ATTN_SMEM>>>(qh, kh, vth, xh);

    // output projection (2 CTAs/SM)
    dim3 ogrid(D_ / 128, M_ / 128);                 // (16, 32)
    o_gemm<<<ogrid, pblk, PROJ_SMEM>>>(xh, wh + 3 * WSZ_, bo, out);
}